// round 1
// baseline (speedup 1.0000x reference)
#include <cuda_runtime.h>
#include <math.h>

// Problem constants
#define BATCH 32
#define C 512
#define L 4096            // H*W = 64*64
#define GROUPS 32
#define CPG (C / GROUPS)  // 16
#define EPS 1e-5f

// Scratch (device globals: allocation-free rule)
__device__ float g_xn  [(size_t)BATCH * C * L];        // 256 MB
__device__ float g_qkv [(size_t)BATCH * 3 * C * L];    // 768 MB
__device__ float g_attn[(size_t)BATCH * C * C];        // 32 MB
__device__ float g_ret [(size_t)BATCH * C * L];        // 256 MB

// ---------------------------------------------------------------------------
// GroupNorm: one block per (batch, group). 16 channels x 4096 = 65536 floats.
// ---------------------------------------------------------------------------
__global__ __launch_bounds__(256) void groupnorm_kernel(
    const float* __restrict__ x, const float* __restrict__ gw,
    const float* __restrict__ gb, float* __restrict__ xn)
{
    const int bg = blockIdx.x;            // 0..BATCH*GROUPS-1
    const int b = bg / GROUPS;
    const int g = bg % GROUPS;
    const size_t base = ((size_t)b * C + (size_t)g * CPG) * L;
    const float4* px4 = (const float4*)(x + base);
    float4* pxn4 = (float4*)(xn + base);
    const int n4 = CPG * L / 4;           // 16384 float4

    const int tid = threadIdx.x;
    float s = 0.f, ss = 0.f;
    for (int i = tid; i < n4; i += 256) {
        float4 v = px4[i];
        s  += v.x + v.y + v.z + v.w;
        ss += v.x*v.x + v.y*v.y + v.z*v.z + v.w*v.w;
    }
    // block reduce
    __shared__ float sh_s[32], sh_ss[32];
    for (int o = 16; o > 0; o >>= 1) {
        s  += __shfl_down_sync(0xffffffff, s, o);
        ss += __shfl_down_sync(0xffffffff, ss, o);
    }
    if ((tid & 31) == 0) { sh_s[tid >> 5] = s; sh_ss[tid >> 5] = ss; }
    __syncthreads();
    if (tid < 32) {
        s  = (tid < 8) ? sh_s[tid]  : 0.f;
        ss = (tid < 8) ? sh_ss[tid] : 0.f;
        for (int o = 4; o > 0; o >>= 1) {
            s  += __shfl_down_sync(0xffffffff, s, o);
            ss += __shfl_down_sync(0xffffffff, ss, o);
        }
        if (tid == 0) { sh_s[0] = s; sh_ss[0] = ss; }
    }
    __syncthreads();
    const float inv_n = 1.f / (float)(CPG * L);
    const float mean  = sh_s[0] * inv_n;
    const float var   = sh_ss[0] * inv_n - mean * mean;
    const float rstd  = rsqrtf(var + EPS);

    for (int i = tid; i < n4; i += 256) {
        const int ch = g * CPG + (i >> 10);   // 1024 float4 per channel row
        const float w = gw[ch], bb = gb[ch];
        float4 v = px4[i];
        v.x = (v.x - mean) * rstd * w + bb;
        v.y = (v.y - mean) * rstd * w + bb;
        v.z = (v.z - mean) * rstd * w + bb;
        v.w = (v.w - mean) * rstd * w + bb;
        pxn4[i] = v;
    }
}

// ---------------------------------------------------------------------------
// Batched SGEMM, 128x128 tile, BK=8, 256 threads, 8x8 per thread.
// C[b] (MxN, row-major) = alpha * A[b] (MxK, rm) * op(B[b]) [+ bias[m]] [+ res[b]]
// TRANS_B=false: B is [K,N] rm (ldb=N). TRANS_B=true: B is [N,K] rm (ldb=K).
// All of M,N %128==0 and K%8==0 (guaranteed by problem shapes).
// ---------------------------------------------------------------------------
template<bool TRANS_B, bool ADD_BIAS, bool ADD_RES>
__global__ __launch_bounds__(256) void gemm128_kernel(
    const float* __restrict__ A, long long strideA,
    const float* __restrict__ B, long long strideB,
    float* __restrict__ Cc, long long strideC,
    int M, int N, int K,
    const float* __restrict__ bias,
    const float* __restrict__ res, long long strideRes,
    float alpha)
{
    const int bz = blockIdx.z;
    A  += (size_t)bz * strideA;
    B  += (size_t)bz * strideB;
    Cc += (size_t)bz * strideC;
    if (ADD_RES) res += (size_t)bz * strideRes;

    constexpr int BM = 128, BN = 128, BK = 8;
    __shared__ float As[BK][BM];
    __shared__ float Bs[BK][BN];

    const int tid = threadIdx.x;
    const int tx = tid & 15;        // 0..15 -> cols
    const int ty = tid >> 4;        // 0..15 -> rows
    const int bm = blockIdx.y * BM;
    const int bn = blockIdx.x * BN;

    // A tile load: BM x BK, float4 along K. 256 threads x 4 = 1024 floats.
    const int a_r = tid >> 1;               // 0..127
    const int a_c = (tid & 1) << 2;         // 0 or 4
    // B (NN) tile load: BK x BN, float4 along N.
    const int b_r = tid >> 5;               // 0..7
    const int b_c = (tid & 31) << 2;        // 0..124

    const int lda = K;
    const int ldb = TRANS_B ? K : N;

    float acc[8][8];
    #pragma unroll
    for (int i = 0; i < 8; i++)
        #pragma unroll
        for (int j = 0; j < 8; j++) acc[i][j] = 0.f;

    for (int k0 = 0; k0 < K; k0 += BK) {
        // load A (transposed store)
        {
            float4 v = *(const float4*)&A[(size_t)(bm + a_r) * lda + k0 + a_c];
            As[a_c + 0][a_r] = v.x;
            As[a_c + 1][a_r] = v.y;
            As[a_c + 2][a_r] = v.z;
            As[a_c + 3][a_r] = v.w;
        }
        if (TRANS_B) {
            float4 v = *(const float4*)&B[(size_t)(bn + a_r) * ldb + k0 + a_c];
            Bs[a_c + 0][a_r] = v.x;
            Bs[a_c + 1][a_r] = v.y;
            Bs[a_c + 2][a_r] = v.z;
            Bs[a_c + 3][a_r] = v.w;
        } else {
            float4 v = *(const float4*)&B[(size_t)(k0 + b_r) * ldb + bn + b_c];
            *(float4*)&Bs[b_r][b_c] = v;
        }
        __syncthreads();

        #pragma unroll
        for (int kk = 0; kk < BK; kk++) {
            float4 a0 = *(const float4*)&As[kk][ty * 8];
            float4 a1 = *(const float4*)&As[kk][ty * 8 + 4];
            float4 b0 = *(const float4*)&Bs[kk][tx * 8];
            float4 b1 = *(const float4*)&Bs[kk][tx * 8 + 4];
            float ar[8] = {a0.x,a0.y,a0.z,a0.w,a1.x,a1.y,a1.z,a1.w};
            float br[8] = {b0.x,b0.y,b0.z,b0.w,b1.x,b1.y,b1.z,b1.w};
            #pragma unroll
            for (int i = 0; i < 8; i++)
                #pragma unroll
                for (int j = 0; j < 8; j++)
                    acc[i][j] = fmaf(ar[i], br[j], acc[i][j]);
        }
        __syncthreads();
    }

    // epilogue
    #pragma unroll
    for (int i = 0; i < 8; i++) {
        const int row = bm + ty * 8 + i;
        const float bi = ADD_BIAS ? bias[row] : 0.f;
        #pragma unroll
        for (int j = 0; j < 8; j += 4) {
            const int col = bn + tx * 8 + j;
            float4 r;
            r.x = fmaf(acc[i][j + 0], alpha, bi);
            r.y = fmaf(acc[i][j + 1], alpha, bi);
            r.z = fmaf(acc[i][j + 2], alpha, bi);
            r.w = fmaf(acc[i][j + 3], alpha, bi);
            if (ADD_RES) {
                float4 rv = *(const float4*)&res[(size_t)row * N + col];
                r.x += rv.x; r.y += rv.y; r.z += rv.z; r.w += rv.w;
            }
            *(float4*)&Cc[(size_t)row * N + col] = r;
        }
    }
}

// ---------------------------------------------------------------------------
// Row softmax over 512 entries. One block (128 thr) per row; 4 floats/thread.
// ---------------------------------------------------------------------------
__global__ __launch_bounds__(128) void softmax512_kernel(float* __restrict__ attn)
{
    const size_t row = blockIdx.x;
    float4* p = (float4*)(attn + row * C);
    const int tid = threadIdx.x;

    float4 v = p[tid];
    float m = fmaxf(fmaxf(v.x, v.y), fmaxf(v.z, v.w));
    __shared__ float sh[4];
    for (int o = 16; o > 0; o >>= 1) m = fmaxf(m, __shfl_xor_sync(0xffffffff, m, o));
    if ((tid & 31) == 0) sh[tid >> 5] = m;
    __syncthreads();
    m = fmaxf(fmaxf(sh[0], sh[1]), fmaxf(sh[2], sh[3]));

    v.x = expf(v.x - m); v.y = expf(v.y - m);
    v.z = expf(v.z - m); v.w = expf(v.w - m);
    float s = v.x + v.y + v.z + v.w;
    for (int o = 16; o > 0; o >>= 1) s += __shfl_xor_sync(0xffffffff, s, o);
    __shared__ float shs[4];
    if ((tid & 31) == 0) shs[tid >> 5] = s;
    __syncthreads();
    s = shs[0] + shs[1] + shs[2] + shs[3];
    const float inv = 1.f / s;
    v.x *= inv; v.y *= inv; v.z *= inv; v.w *= inv;
    p[tid] = v;
}

// ---------------------------------------------------------------------------
extern "C" void kernel_launch(void* const* d_in, const int* in_sizes, int n_in,
                              void* d_out, int out_size)
{
    const float* x      = (const float*)d_in[0];
    const float* gn_w   = (const float*)d_in[1];
    const float* gn_b   = (const float*)d_in[2];
    const float* qkv_w  = (const float*)d_in[3];
    const float* qkv_b  = (const float*)d_in[4];
    const float* proj_w = (const float*)d_in[5];
    const float* proj_b = (const float*)d_in[6];
    float* out = (float*)d_out;

    float *xn, *qkv, *attn, *ret;
    cudaGetSymbolAddress((void**)&xn,   g_xn);
    cudaGetSymbolAddress((void**)&qkv,  g_qkv);
    cudaGetSymbolAddress((void**)&attn, g_attn);
    cudaGetSymbolAddress((void**)&ret,  g_ret);

    const long long sXN  = (long long)C * L;           // per-batch xn/ret/out stride
    const long long sQKV = (long long)3 * C * L;
    const long long sATT = (long long)C * C;

    // 1) GroupNorm
    groupnorm_kernel<<<BATCH * GROUPS, 256>>>(x, gn_w, gn_b, xn);

    // 2) QKV: [3C x C] @ [C x L]  (+bias)
    {
        dim3 grid(L / 128, (3 * C) / 128, BATCH);
        gemm128_kernel<false, true, false><<<grid, 256>>>(
            qkv_w, 0LL, xn, sXN, qkv, sQKV,
            3 * C, L, C, qkv_b, nullptr, 0LL, 1.0f);
    }

    // 3) logits = Q @ K^T / 64  (NT, K=L)
    {
        dim3 grid(C / 128, C / 128, BATCH);
        gemm128_kernel<true, false, false><<<grid, 256>>>(
            qkv, sQKV,                       // Q = qkv[b, 0:C, :]
            qkv + (size_t)C * L, sQKV,       // K = qkv[b, C:2C, :]
            attn, sATT,
            C, C, L, nullptr, nullptr, 0LL, 0.015625f /* 1/sqrt(4096) */);
    }

    // 4) softmax rows
    softmax512_kernel<<<BATCH * C, 128>>>(attn);

    // 5) ret = attn @ V
    {
        dim3 grid(L / 128, C / 128, BATCH);
        gemm128_kernel<false, false, false><<<grid, 256>>>(
            attn, sATT,
            qkv + (size_t)2 * C * L, sQKV,   // V
            ret, sXN,
            C, L, C, nullptr, nullptr, 0LL, 1.0f);
    }

    // 6) out = proj_w @ ret + proj_b + xn
    {
        dim3 grid(L / 128, C / 128, BATCH);
        gemm128_kernel<false, true, true><<<grid, 256>>>(
            proj_w, 0LL, ret, sXN, out, sXN,
            C, L, C, proj_b, xn, sXN, 1.0f);
    }
}

// round 3
// speedup vs baseline: 6.7758x; 6.7758x over previous
#include <cuda_runtime.h>
#include <cuda_fp16.h>
#include <cstdint>
#include <math.h>

#define BATCH 32
#define C 512
#define L 4096
#define GROUPS 32
#define CPG 16
#define EPS 1e-5f

// ---------------- scratch (device globals; allocation-free rule) -----------
__device__ __align__(256) float  g_xn    [(size_t)BATCH * C * L];      // fp32 residual
__device__ __align__(256) __half g_xnT   [(size_t)BATCH * L * C];      // [L,C] fp16
__device__ __align__(256) __half g_qk    [(size_t)BATCH * 1024 * L];   // q rows 0..511, k rows 512..1023
__device__ __align__(256) __half g_vT    [(size_t)BATCH * L * C];      // [L,C]
__device__ __align__(256) float  g_logits[(size_t)BATCH * C * C];
__device__ __align__(256) __half g_attn  [(size_t)BATCH * C * C];
__device__ __align__(256) __half g_retT  [(size_t)BATCH * L * C];
__device__ __align__(256) __half g_wh    [(size_t)4 * C * C];          // qkv_w (3C*C) + proj_w (C*C)

// ---------------- PTX helpers ----------------------------------------------
__device__ __forceinline__ uint32_t smem_u32(const void* p) {
    uint32_t a;
    asm("{ .reg .u64 t; cvta.to.shared.u64 t, %1; cvt.u32.u64 %0, t; }" : "=r"(a) : "l"(p));
    return a;
}
#define CP_ASYNC16(dst, src) \
    asm volatile("cp.async.cg.shared.global [%0], [%1], 16;" :: "r"(dst), "l"(src) : "memory")
#define CP_COMMIT() asm volatile("cp.async.commit_group;" ::: "memory")
#define CP_WAIT2()  asm volatile("cp.async.wait_group 2;" ::: "memory")

__device__ __forceinline__ void ldsm_x4(uint32_t (&r)[4], uint32_t addr) {
    asm volatile("ldmatrix.sync.aligned.m8n8.x4.shared.b16 {%0,%1,%2,%3}, [%4];"
        : "=r"(r[0]), "=r"(r[1]), "=r"(r[2]), "=r"(r[3]) : "r"(addr));
}
__device__ __forceinline__ void mma16816(float (&d)[4], const uint32_t (&a)[4],
                                         uint32_t b0, uint32_t b1) {
    asm volatile(
        "mma.sync.aligned.m16n8k16.row.col.f32.f16.f16.f32 "
        "{%0,%1,%2,%3}, {%4,%5,%6,%7}, {%8,%9}, {%0,%1,%2,%3};"
        : "+f"(d[0]), "+f"(d[1]), "+f"(d[2]), "+f"(d[3])
        : "r"(a[0]), "r"(a[1]), "r"(a[2]), "r"(a[3]), "r"(b0), "r"(b1));
}

// ---------------- GroupNorm -------------------------------------------------
__global__ __launch_bounds__(256) void groupnorm_kernel(
    const float* __restrict__ x, const float* __restrict__ gw,
    const float* __restrict__ gb, float* __restrict__ xn)
{
    const int bg = blockIdx.x;
    const int b = bg / GROUPS;
    const int g = bg % GROUPS;
    const size_t base = ((size_t)b * C + (size_t)g * CPG) * L;
    const float4* px4 = (const float4*)(x + base);
    float4* pxn4 = (float4*)(xn + base);
    const int n4 = CPG * L / 4;

    const int tid = threadIdx.x;
    float s = 0.f, ss = 0.f;
    for (int i = tid; i < n4; i += 256) {
        float4 v = px4[i];
        s  += v.x + v.y + v.z + v.w;
        ss += v.x*v.x + v.y*v.y + v.z*v.z + v.w*v.w;
    }
    __shared__ float sh_s[32], sh_ss[32];
    for (int o = 16; o > 0; o >>= 1) {
        s  += __shfl_down_sync(0xffffffff, s, o);
        ss += __shfl_down_sync(0xffffffff, ss, o);
    }
    if ((tid & 31) == 0) { sh_s[tid >> 5] = s; sh_ss[tid >> 5] = ss; }
    __syncthreads();
    if (tid < 32) {
        s  = (tid < 8) ? sh_s[tid]  : 0.f;
        ss = (tid < 8) ? sh_ss[tid] : 0.f;
        for (int o = 4; o > 0; o >>= 1) {
            s  += __shfl_down_sync(0xffffffff, s, o);
            ss += __shfl_down_sync(0xffffffff, ss, o);
        }
        if (tid == 0) { sh_s[0] = s; sh_ss[0] = ss; }
    }
    __syncthreads();
    const float inv_n = 1.f / (float)(CPG * L);
    const float mean  = sh_s[0] * inv_n;
    const float var   = sh_ss[0] * inv_n - mean * mean;
    const float rstd  = rsqrtf(var + EPS);

    for (int i = tid; i < n4; i += 256) {
        const int ch = g * CPG + (i >> 10);
        const float w = gw[ch], bb = gb[ch];
        float4 v = px4[i];
        v.x = (v.x - mean) * rstd * w + bb;
        v.y = (v.y - mean) * rstd * w + bb;
        v.z = (v.z - mean) * rstd * w + bb;
        v.w = (v.w - mean) * rstd * w + bb;
        pxn4[i] = v;
    }
}

// ---------------- Transpose [C,L] fp32 -> [L,C] fp16 -----------------------
__global__ __launch_bounds__(256) void transpose_h_kernel(
    const float* __restrict__ in, __half* __restrict__ out)
{
    __shared__ float tile[32][33];
    const int b = blockIdx.z;
    in  += (size_t)b * C * L;
    out += (size_t)b * L * C;
    const int l0 = blockIdx.x * 32, c0 = blockIdx.y * 32;
    const int tx = threadIdx.x, ty = threadIdx.y;
    #pragma unroll
    for (int j = ty; j < 32; j += 8)
        tile[j][tx] = in[(size_t)(c0 + j) * L + l0 + tx];
    __syncthreads();
    #pragma unroll
    for (int j = ty; j < 32; j += 8)
        out[(size_t)(l0 + j) * C + c0 + tx] = __float2half(tile[tx][j]);
}

// ---------------- fp32 -> fp16 convert --------------------------------------
__global__ __launch_bounds__(256) void cvt_kernel(
    const float* __restrict__ in, __half* __restrict__ out, int n)
{
    const int i = blockIdx.x * 256 + threadIdx.x;
    if (i < n) out[i] = __float2half(in[i]);
}

// ---------------- Row softmax (fp32 in, fp16 out) ---------------------------
__global__ __launch_bounds__(128) void softmax512_kernel(
    const float* __restrict__ logits, __half* __restrict__ attn)
{
    const size_t row = blockIdx.x;
    const float4* p = (const float4*)(logits + row * C);
    const int tid = threadIdx.x;

    float4 v = p[tid];
    float m = fmaxf(fmaxf(v.x, v.y), fmaxf(v.z, v.w));
    __shared__ float sh[4];
    for (int o = 16; o > 0; o >>= 1) m = fmaxf(m, __shfl_xor_sync(0xffffffff, m, o));
    if ((tid & 31) == 0) sh[tid >> 5] = m;
    __syncthreads();
    m = fmaxf(fmaxf(sh[0], sh[1]), fmaxf(sh[2], sh[3]));

    v.x = expf(v.x - m); v.y = expf(v.y - m);
    v.z = expf(v.z - m); v.w = expf(v.w - m);
    float s = v.x + v.y + v.z + v.w;
    for (int o = 16; o > 0; o >>= 1) s += __shfl_xor_sync(0xffffffff, s, o);
    __shared__ float shs[4];
    if ((tid & 31) == 0) shs[tid >> 5] = s;
    __syncthreads();
    s = shs[0] + shs[1] + shs[2] + shs[3];
    const float inv = 1.f / s;

    __half2* o2 = (__half2*)(attn + row * C);
    o2[tid * 2 + 0] = __floats2half2_rn(v.x * inv, v.y * inv);
    o2[tid * 2 + 1] = __floats2half2_rn(v.z * inv, v.w * inv);
}

// ---------------- fp16 tensor-core NT GEMM ---------------------------------
// D[M,N] = alpha * A[M,K] * B[N,K]^T (+bias) (+res). A,B fp16 K-major.
// 128x128 tile, BK=64, 256 threads (2m x 4n warps, warp tile 64x32),
// 3-stage cp.async, swizzled SMEM, ldmatrix + mma.sync.m16n8k16.
#define STAGE_BYTES 32768          // A 16KB + B 16KB
#define GEMM_SMEM  (3 * STAGE_BYTES)

__device__ __forceinline__ void load_stage(
    const __half* __restrict__ gA, const __half* __restrict__ gB,
    int lda, int ldb, uint32_t stA, uint32_t stB, int tid)
{
    #pragma unroll
    for (int j = 0; j < 4; j++) {
        const int slot = tid + 256 * j;
        const int row  = slot >> 3;           // 0..127
        const int c    = slot & 7;            // 16B chunk in 128B row
        const uint32_t off = (uint32_t)row * 128u + (uint32_t)((c ^ (row & 7)) << 4);
        CP_ASYNC16(stA + off, gA + (size_t)row * lda + c * 8);
        CP_ASYNC16(stB + off, gB + (size_t)row * ldb + c * 8);
    }
    CP_COMMIT();
}

template<typename OutT, int BIAS_MODE, bool ADD_RES>
__global__ __launch_bounds__(256, 2) void hgemm_kernel(
    const __half* __restrict__ A, long long sA, int lda,
    const __half* __restrict__ B, long long sB, int ldb,
    OutT* __restrict__ D, long long sD, int ldd,
    int K,
    const float* __restrict__ bias,
    const float* __restrict__ res, long long sRes, int ldres,
    float alpha)
{
    extern __shared__ __align__(128) char smem[];
    const uint32_t sbase = smem_u32(smem);

    const int bz = blockIdx.z;
    A += (size_t)bz * sA;
    B += (size_t)bz * sB;
    D += (size_t)bz * sD;
    if (ADD_RES) res += (size_t)bz * sRes;

    const int bm = blockIdx.y * 128;
    const int bn = blockIdx.x * 128;
    const int tid = threadIdx.x;
    const int lane = tid & 31;
    const int wm = (tid >> 5) & 1;     // 0..1 (m)
    const int wn = tid >> 6;           // 0..3 (n)

    const __half* gA = A + (size_t)bm * lda;
    const __half* gB = B + (size_t)bn * ldb;
    const int T = K >> 6;              // K/64 (>= 8 for all our shapes)

    // ldmatrix per-thread row/sel components
    const int a_row_lo = lane & 15;
    const int a_sel    = lane >> 4;             // 0/1 -> k chunk
    const int b_row_lo = (lane & 7) + ((lane >> 4) << 3);
    const int b_sel    = (lane >> 3) & 1;

    float acc[4][4][4];
    #pragma unroll
    for (int i = 0; i < 4; i++)
        #pragma unroll
        for (int j = 0; j < 4; j++)
            #pragma unroll
            for (int q = 0; q < 4; q++) acc[i][j][q] = 0.f;

    // prologue: 3 stages
    #pragma unroll
    for (int s = 0; s < 3; s++)
        load_stage(gA + s * 64, gB + s * 64, lda, ldb,
                   sbase + s * STAGE_BYTES, sbase + s * STAGE_BYTES + 16384, tid);

    for (int t = 0; t < T; t++) {
        CP_WAIT2();
        __syncthreads();
        const uint32_t stA = sbase + (t % 3) * STAGE_BYTES;
        const uint32_t stB = stA + 16384;

        #pragma unroll
        for (int ks = 0; ks < 4; ks++) {
            uint32_t aF[4][4];
            uint32_t bF[2][4];
            #pragma unroll
            for (int mi = 0; mi < 4; mi++) {
                const int row = wm * 64 + mi * 16 + a_row_lo;
                const int ch  = ks * 2 + a_sel;
                ldsm_x4(aF[mi], stA + (uint32_t)row * 128u + (uint32_t)((ch ^ (row & 7)) << 4));
            }
            #pragma unroll
            for (int nb = 0; nb < 2; nb++) {
                const int row = wn * 32 + nb * 16 + b_row_lo;
                const int ch  = ks * 2 + b_sel;
                ldsm_x4(bF[nb], stB + (uint32_t)row * 128u + (uint32_t)((ch ^ (row & 7)) << 4));
            }
            #pragma unroll
            for (int mi = 0; mi < 4; mi++)
                #pragma unroll
                for (int nj = 0; nj < 4; nj++)
                    mma16816(acc[mi][nj], aF[mi],
                             bF[nj >> 1][(nj & 1) * 2], bF[nj >> 1][(nj & 1) * 2 + 1]);
        }
        __syncthreads();
        if (t + 3 < T) {
            const uint32_t st = sbase + ((t + 3) % 3) * STAGE_BYTES;
            load_stage(gA + (t + 3) * 64, gB + (t + 3) * 64, lda, ldb, st, st + 16384, tid);
        } else {
            CP_COMMIT();   // keep group count constant for CP_WAIT2
        }
    }

    // epilogue
    const int m0 = bm + wm * 64;
    const int n0 = bn + wn * 32;
    #pragma unroll
    for (int mi = 0; mi < 4; mi++) {
        const int r0 = m0 + mi * 16 + (lane >> 2);
        const int r1 = r0 + 8;
        float br0 = 0.f, br1 = 0.f;
        if (BIAS_MODE == 1) { br0 = bias[r0]; br1 = bias[r1]; }
        #pragma unroll
        for (int nj = 0; nj < 4; nj++) {
            const int c0 = n0 + nj * 8 + (lane & 3) * 2;
            float v0 = acc[mi][nj][0] * alpha;
            float v1 = acc[mi][nj][1] * alpha;
            float v2 = acc[mi][nj][2] * alpha;
            float v3 = acc[mi][nj][3] * alpha;
            if (BIAS_MODE == 1) { v0 += br0; v1 += br0; v2 += br1; v3 += br1; }
            if (BIAS_MODE == 2) {
                const float bc0 = bias[c0], bc1 = bias[c0 + 1];
                v0 += bc0; v1 += bc1; v2 += bc0; v3 += bc1;
            }
            if (ADD_RES) {
                const float2 q0 = *(const float2*)&res[(size_t)r0 * ldres + c0];
                const float2 q1 = *(const float2*)&res[(size_t)r1 * ldres + c0];
                v0 += q0.x; v1 += q0.y; v2 += q1.x; v3 += q1.y;
            }
            if constexpr (sizeof(OutT) == 2) {
                *reinterpret_cast<__half2*>(&D[(size_t)r0 * ldd + c0]) = __floats2half2_rn(v0, v1);
                *reinterpret_cast<__half2*>(&D[(size_t)r1 * ldd + c0]) = __floats2half2_rn(v2, v3);
            } else {
                *reinterpret_cast<float2*>(&D[(size_t)r0 * ldd + c0]) = make_float2(v0, v1);
                *reinterpret_cast<float2*>(&D[(size_t)r1 * ldd + c0]) = make_float2(v2, v3);
            }
        }
    }
}

// ---------------------------------------------------------------------------
extern "C" void kernel_launch(void* const* d_in, const int* in_sizes, int n_in,
                              void* d_out, int out_size)
{
    const float* x      = (const float*)d_in[0];
    const float* gn_w   = (const float*)d_in[1];
    const float* gn_b   = (const float*)d_in[2];
    const float* qkv_w  = (const float*)d_in[3];
    const float* qkv_b  = (const float*)d_in[4];
    const float* proj_w = (const float*)d_in[5];
    const float* proj_b = (const float*)d_in[6];
    float* out = (float*)d_out;

    float *xn, *logits;
    __half *xnT, *qk, *vT, *attn, *retT, *wh;
    cudaGetSymbolAddress((void**)&xn,     g_xn);
    cudaGetSymbolAddress((void**)&xnT,    g_xnT);
    cudaGetSymbolAddress((void**)&qk,     g_qk);
    cudaGetSymbolAddress((void**)&vT,     g_vT);
    cudaGetSymbolAddress((void**)&logits, g_logits);
    cudaGetSymbolAddress((void**)&attn,   g_attn);
    cudaGetSymbolAddress((void**)&retT,   g_retT);
    cudaGetSymbolAddress((void**)&wh,     g_wh);

    cudaFuncSetAttribute(hgemm_kernel<__half, 1, false>, cudaFuncAttributeMaxDynamicSharedMemorySize, GEMM_SMEM);
    cudaFuncSetAttribute(hgemm_kernel<__half, 2, false>, cudaFuncAttributeMaxDynamicSharedMemorySize, GEMM_SMEM);
    cudaFuncSetAttribute(hgemm_kernel<float,  0, false>, cudaFuncAttributeMaxDynamicSharedMemorySize, GEMM_SMEM);
    cudaFuncSetAttribute(hgemm_kernel<__half, 0, false>, cudaFuncAttributeMaxDynamicSharedMemorySize, GEMM_SMEM);
    cudaFuncSetAttribute(hgemm_kernel<float,  1, true>,  cudaFuncAttributeMaxDynamicSharedMemorySize, GEMM_SMEM);

    const long long sXN  = (long long)C * L;
    const long long sXNT = (long long)L * C;
    const long long sQK  = (long long)1024 * L;
    const long long sATT = (long long)C * C;

    // 0) weights -> fp16
    cvt_kernel<<<(3 * C * C + 255) / 256, 256>>>(qkv_w, wh, 3 * C * C);
    cvt_kernel<<<(C * C + 255) / 256, 256>>>(proj_w, wh + (size_t)3 * C * C, C * C);

    // 1) GroupNorm -> xn (fp32)
    groupnorm_kernel<<<BATCH * GROUPS, 256>>>(x, gn_w, gn_b, xn);

    // 2) transpose -> xnT fp16 [L,C]
    {
        dim3 grid(L / 32, C / 32, BATCH);
        transpose_h_kernel<<<grid, dim3(32, 8)>>>(xn, xnT);
    }

    // 3a) qk[o,l] = Wqk[o,:] . xnT[l,:] + qkv_b[o]   (M=1024, N=4096, K=512)
    {
        dim3 grid(L / 128, 1024 / 128, BATCH);
        hgemm_kernel<__half, 1, false><<<grid, 256, GEMM_SMEM>>>(
            wh, 0LL, C, xnT, sXNT, C, qk, sQK, L, C,
            qkv_b, nullptr, 0LL, 0, 1.0f);
    }
    // 3b) vT[l,o] = xnT[l,:] . Wv[o,:] + qkv_b[1024+o]  (M=4096, N=512, K=512)
    {
        dim3 grid(C / 128, L / 128, BATCH);
        hgemm_kernel<__half, 2, false><<<grid, 256, GEMM_SMEM>>>(
            xnT, sXNT, C, wh + (size_t)1024 * C, 0LL, C, vT, sXNT, C, C,
            qkv_b + 1024, nullptr, 0LL, 0, 1.0f);
    }
    // 4) logits[q,k] = Q[q,:] . K[k,:] / 64   (M=512, N=512, K=4096)
    {
        dim3 grid(C / 128, C / 128, BATCH);
        hgemm_kernel<float, 0, false><<<grid, 256, GEMM_SMEM>>>(
            qk, sQK, L, qk + (size_t)C * L, sQK, L, logits, sATT, C, L,
            nullptr, nullptr, 0LL, 0, 0.015625f);
    }
    // 5) softmax -> attn fp16
    softmax512_kernel<<<BATCH * C, 128>>>(logits, attn);

    // 6) retT[l,q] = vT[l,:] . attn[q,:]   (M=4096, N=512, K=512)
    {
        dim3 grid(C / 128, L / 128, BATCH);
        hgemm_kernel<__half, 0, false><<<grid, 256, GEMM_SMEM>>>(
            vT, sXNT, C, attn, sATT, C, retT, sXNT, C, C,
            nullptr, nullptr, 0LL, 0, 1.0f);
    }
    // 7) out[o,l] = P[o,:] . retT[l,:] + proj_b[o] + xn[o,l]  (M=512, N=4096, K=512)
    {
        dim3 grid(L / 128, C / 128, BATCH);
        hgemm_kernel<float, 1, true><<<grid, 256, GEMM_SMEM>>>(
            wh + (size_t)3 * C * C, 0LL, C, retT, sXNT, C, out, sXN, L, C,
            proj_b, xn, sXN, L, 1.0f);
    }
}

// round 4
// speedup vs baseline: 6.9322x; 1.0231x over previous
#include <cuda_runtime.h>
#include <cuda_fp16.h>
#include <cstdint>
#include <math.h>

#define BATCH 32
#define C 512
#define L 4096
#define GROUPS 32
#define CPG 16
#define EPS 1e-5f

// ---------------- scratch (device globals; allocation-free rule) -----------
__device__ __align__(256) __half g_xnh   [(size_t)BATCH * C * L];      // [C,L] fp16 (residual + transpose src)
__device__ __align__(256) __half g_xnT   [(size_t)BATCH * L * C];      // [L,C] fp16
__device__ __align__(256) __half g_qk    [(size_t)BATCH * 1024 * L];   // q rows 0..511, k rows 512..1023
__device__ __align__(256) __half g_vT    [(size_t)BATCH * L * C];      // [L,C]
__device__ __align__(256) __half g_logits[(size_t)BATCH * C * C];
__device__ __align__(256) __half g_attn  [(size_t)BATCH * C * C];
__device__ __align__(256) __half g_retT  [(size_t)BATCH * L * C];
__device__ __align__(256) __half g_wh    [(size_t)4 * C * C];          // qkv_w (3C*C) + proj_w (C*C)

// ---------------- PTX helpers ----------------------------------------------
__device__ __forceinline__ uint32_t smem_u32(const void* p) {
    uint32_t a;
    asm("{ .reg .u64 t; cvta.to.shared.u64 t, %1; cvt.u32.u64 %0, t; }" : "=r"(a) : "l"(p));
    return a;
}
#define CP_ASYNC16(dst, src) \
    asm volatile("cp.async.cg.shared.global [%0], [%1], 16;" :: "r"(dst), "l"(src) : "memory")
#define CP_COMMIT() asm volatile("cp.async.commit_group;" ::: "memory")
#define CP_WAIT2()  asm volatile("cp.async.wait_group 2;" ::: "memory")

__device__ __forceinline__ void ldsm_x4(uint32_t (&r)[4], uint32_t addr) {
    asm volatile("ldmatrix.sync.aligned.m8n8.x4.shared.b16 {%0,%1,%2,%3}, [%4];"
        : "=r"(r[0]), "=r"(r[1]), "=r"(r[2]), "=r"(r[3]) : "r"(addr));
}
__device__ __forceinline__ void mma16816(float (&d)[4], const uint32_t (&a)[4],
                                         uint32_t b0, uint32_t b1) {
    asm volatile(
        "mma.sync.aligned.m16n8k16.row.col.f32.f16.f16.f32 "
        "{%0,%1,%2,%3}, {%4,%5,%6,%7}, {%8,%9}, {%0,%1,%2,%3};"
        : "+f"(d[0]), "+f"(d[1]), "+f"(d[2]), "+f"(d[3])
        : "r"(a[0]), "r"(a[1]), "r"(a[2]), "r"(a[3]), "r"(b0), "r"(b1));
}

// ---------------- GroupNorm -> fp16 [C,L] -----------------------------------
__global__ __launch_bounds__(256) void groupnorm_kernel(
    const float* __restrict__ x, const float* __restrict__ gw,
    const float* __restrict__ gb, __half* __restrict__ xnh)
{
    const int bg = blockIdx.x;
    const int b = bg / GROUPS;
    const int g = bg % GROUPS;
    const size_t base = ((size_t)b * C + (size_t)g * CPG) * L;
    const float4* px4 = (const float4*)(x + base);
    __half2* outh = (__half2*)(xnh + base);
    const int n4 = CPG * L / 4;

    const int tid = threadIdx.x;
    float s = 0.f, ss = 0.f;
    for (int i = tid; i < n4; i += 256) {
        float4 v = px4[i];
        s  += v.x + v.y + v.z + v.w;
        ss += v.x*v.x + v.y*v.y + v.z*v.z + v.w*v.w;
    }
    __shared__ float sh_s[32], sh_ss[32];
    for (int o = 16; o > 0; o >>= 1) {
        s  += __shfl_down_sync(0xffffffff, s, o);
        ss += __shfl_down_sync(0xffffffff, ss, o);
    }
    if ((tid & 31) == 0) { sh_s[tid >> 5] = s; sh_ss[tid >> 5] = ss; }
    __syncthreads();
    if (tid < 32) {
        s  = (tid < 8) ? sh_s[tid]  : 0.f;
        ss = (tid < 8) ? sh_ss[tid] : 0.f;
        for (int o = 4; o > 0; o >>= 1) {
            s  += __shfl_down_sync(0xffffffff, s, o);
            ss += __shfl_down_sync(0xffffffff, ss, o);
        }
        if (tid == 0) { sh_s[0] = s; sh_ss[0] = ss; }
    }
    __syncthreads();
    const float inv_n = 1.f / (float)(CPG * L);
    const float mean  = sh_s[0] * inv_n;
    const float var   = sh_ss[0] * inv_n - mean * mean;
    const float rstd  = rsqrtf(var + EPS);

    for (int i = tid; i < n4; i += 256) {
        const int ch = g * CPG + (i >> 10);
        const float w = gw[ch] * rstd;
        const float bb = gb[ch] - mean * w;
        float4 v = px4[i];
        outh[i * 2 + 0] = __floats2half2_rn(fmaf(v.x, w, bb), fmaf(v.y, w, bb));
        outh[i * 2 + 1] = __floats2half2_rn(fmaf(v.z, w, bb), fmaf(v.w, w, bb));
    }
}

// ---------------- Transpose [C,L] fp16 -> [L,C] fp16 ------------------------
__global__ __launch_bounds__(256) void transpose_h_kernel(
    const __half* __restrict__ in, __half* __restrict__ out)
{
    __shared__ __half tile[32][33];
    const int b = blockIdx.z;
    in  += (size_t)b * C * L;
    out += (size_t)b * L * C;
    const int l0 = blockIdx.x * 32, c0 = blockIdx.y * 32;
    const int tx = threadIdx.x, ty = threadIdx.y;
    #pragma unroll
    for (int j = ty; j < 32; j += 8)
        tile[j][tx] = in[(size_t)(c0 + j) * L + l0 + tx];
    __syncthreads();
    #pragma unroll
    for (int j = ty; j < 32; j += 8)
        out[(size_t)(l0 + j) * C + c0 + tx] = tile[tx][j];
}

// ---------------- fp32 -> fp16 weight convert (both mats, one launch) ------
__global__ __launch_bounds__(256) void cvt_w_kernel(
    const float* __restrict__ qkvw, const float* __restrict__ projw,
    __half* __restrict__ out)
{
    const int i = blockIdx.x * 256 + threadIdx.x;
    const int n_qkv = 3 * C * C;
    if (i < n_qkv) out[i] = __float2half(qkvw[i]);
    else if (i < 4 * C * C) out[i] = __float2half(projw[i - n_qkv]);
}

// ---------------- Row softmax (fp16 in, fp16 out) ---------------------------
__global__ __launch_bounds__(128) void softmax512_kernel(
    const __half* __restrict__ logits, __half* __restrict__ attn)
{
    const size_t row = blockIdx.x;
    const __half2* p = (const __half2*)(logits + row * C);
    const int tid = threadIdx.x;

    float2 a = __half22float2(p[tid * 2 + 0]);
    float2 b = __half22float2(p[tid * 2 + 1]);
    float m = fmaxf(fmaxf(a.x, a.y), fmaxf(b.x, b.y));
    __shared__ float sh[4];
    for (int o = 16; o > 0; o >>= 1) m = fmaxf(m, __shfl_xor_sync(0xffffffff, m, o));
    if ((tid & 31) == 0) sh[tid >> 5] = m;
    __syncthreads();
    m = fmaxf(fmaxf(sh[0], sh[1]), fmaxf(sh[2], sh[3]));

    a.x = expf(a.x - m); a.y = expf(a.y - m);
    b.x = expf(b.x - m); b.y = expf(b.y - m);
    float s = a.x + a.y + b.x + b.y;
    for (int o = 16; o > 0; o >>= 1) s += __shfl_xor_sync(0xffffffff, s, o);
    __shared__ float shs[4];
    if ((tid & 31) == 0) shs[tid >> 5] = s;
    __syncthreads();
    s = shs[0] + shs[1] + shs[2] + shs[3];
    const float inv = 1.f / s;

    __half2* o2 = (__half2*)(attn + row * C);
    o2[tid * 2 + 0] = __floats2half2_rn(a.x * inv, a.y * inv);
    o2[tid * 2 + 1] = __floats2half2_rn(b.x * inv, b.y * inv);
}

// ---------------- fp16 tensor-core NT GEMM ---------------------------------
// D[M,N] = alpha * A[M,K] * B[N,K]^T (+bias) (+res fp16). A,B fp16 K-major.
// 128x128 tile, BK=64, 256 threads (2m x 4n warps, warp tile 64x32),
// 3-stage cp.async, swizzled SMEM, ldmatrix + mma.sync.m16n8k16.
#define STAGE_BYTES 32768          // A 16KB + B 16KB
#define GEMM_SMEM  (3 * STAGE_BYTES)

__device__ __forceinline__ void load_stage(
    const __half* __restrict__ gA, const __half* __restrict__ gB,
    int lda, int ldb, uint32_t stA, uint32_t stB, int tid)
{
    #pragma unroll
    for (int j = 0; j < 4; j++) {
        const int slot = tid + 256 * j;
        const int row  = slot >> 3;           // 0..127
        const int c    = slot & 7;            // 16B chunk in 128B row
        const uint32_t off = (uint32_t)row * 128u + (uint32_t)((c ^ (row & 7)) << 4);
        CP_ASYNC16(stA + off, gA + (size_t)row * lda + c * 8);
        CP_ASYNC16(stB + off, gB + (size_t)row * ldb + c * 8);
    }
    CP_COMMIT();
}

template<typename OutT, int BIAS_MODE, bool ADD_RES>
__global__ __launch_bounds__(256, 2) void hgemm_kernel(
    const __half* __restrict__ A, long long sA, int lda,
    const __half* __restrict__ B, long long sB, int ldb,
    OutT* __restrict__ D, long long sD, int ldd,
    int K,
    const float* __restrict__ bias,
    const __half* __restrict__ res, long long sRes, int ldres,
    float alpha)
{
    extern __shared__ __align__(128) char smem[];
    const uint32_t sbase = smem_u32(smem);

    const int bz = blockIdx.z;
    A += (size_t)bz * sA;
    B += (size_t)bz * sB;
    D += (size_t)bz * sD;
    if (ADD_RES) res += (size_t)bz * sRes;

    const int bm = blockIdx.y * 128;
    const int bn = blockIdx.x * 128;
    const int tid = threadIdx.x;
    const int lane = tid & 31;
    const int wm = (tid >> 5) & 1;     // 0..1 (m)
    const int wn = tid >> 6;           // 0..3 (n)

    const __half* gA = A + (size_t)bm * lda;
    const __half* gB = B + (size_t)bn * ldb;
    const int T = K >> 6;              // K/64

    const int a_row_lo = lane & 15;
    const int a_sel    = lane >> 4;
    const int b_row_lo = (lane & 7) + ((lane >> 4) << 3);
    const int b_sel    = (lane >> 3) & 1;

    float acc[4][4][4];
    #pragma unroll
    for (int i = 0; i < 4; i++)
        #pragma unroll
        for (int j = 0; j < 4; j++)
            #pragma unroll
            for (int q = 0; q < 4; q++) acc[i][j][q] = 0.f;

    #pragma unroll
    for (int s = 0; s < 3; s++)
        load_stage(gA + s * 64, gB + s * 64, lda, ldb,
                   sbase + s * STAGE_BYTES, sbase + s * STAGE_BYTES + 16384, tid);

    for (int t = 0; t < T; t++) {
        CP_WAIT2();
        __syncthreads();
        const uint32_t stA = sbase + (t % 3) * STAGE_BYTES;
        const uint32_t stB = stA + 16384;

        #pragma unroll
        for (int ks = 0; ks < 4; ks++) {
            uint32_t aF[4][4];
            uint32_t bF[2][4];
            #pragma unroll
            for (int mi = 0; mi < 4; mi++) {
                const int row = wm * 64 + mi * 16 + a_row_lo;
                const int ch  = ks * 2 + a_sel;
                ldsm_x4(aF[mi], stA + (uint32_t)row * 128u + (uint32_t)((ch ^ (row & 7)) << 4));
            }
            #pragma unroll
            for (int nb = 0; nb < 2; nb++) {
                const int row = wn * 32 + nb * 16 + b_row_lo;
                const int ch  = ks * 2 + b_sel;
                ldsm_x4(bF[nb], stB + (uint32_t)row * 128u + (uint32_t)((ch ^ (row & 7)) << 4));
            }
            #pragma unroll
            for (int mi = 0; mi < 4; mi++)
                #pragma unroll
                for (int nj = 0; nj < 4; nj++)
                    mma16816(acc[mi][nj], aF[mi],
                             bF[nj >> 1][(nj & 1) * 2], bF[nj >> 1][(nj & 1) * 2 + 1]);
        }
        __syncthreads();
        if (t + 3 < T) {
            const uint32_t st = sbase + ((t + 3) % 3) * STAGE_BYTES;
            load_stage(gA + (t + 3) * 64, gB + (t + 3) * 64, lda, ldb, st, st + 16384, tid);
        } else {
            CP_COMMIT();
        }
    }

    // epilogue
    const int m0 = bm + wm * 64;
    const int n0 = bn + wn * 32;
    #pragma unroll
    for (int mi = 0; mi < 4; mi++) {
        const int r0 = m0 + mi * 16 + (lane >> 2);
        const int r1 = r0 + 8;
        float br0 = 0.f, br1 = 0.f;
        if (BIAS_MODE == 1) { br0 = bias[r0]; br1 = bias[r1]; }
        #pragma unroll
        for (int nj = 0; nj < 4; nj++) {
            const int c0 = n0 + nj * 8 + (lane & 3) * 2;
            float v0 = acc[mi][nj][0] * alpha;
            float v1 = acc[mi][nj][1] * alpha;
            float v2 = acc[mi][nj][2] * alpha;
            float v3 = acc[mi][nj][3] * alpha;
            if (BIAS_MODE == 1) { v0 += br0; v1 += br0; v2 += br1; v3 += br1; }
            if (BIAS_MODE == 2) {
                const float bc0 = bias[c0], bc1 = bias[c0 + 1];
                v0 += bc0; v1 += bc1; v2 += bc0; v3 += bc1;
            }
            if (ADD_RES) {
                const float2 q0 = __half22float2(*(const __half2*)&res[(size_t)r0 * ldres + c0]);
                const float2 q1 = __half22float2(*(const __half2*)&res[(size_t)r1 * ldres + c0]);
                v0 += q0.x; v1 += q0.y; v2 += q1.x; v3 += q1.y;
            }
            if constexpr (sizeof(OutT) == 2) {
                *reinterpret_cast<__half2*>(&D[(size_t)r0 * ldd + c0]) = __floats2half2_rn(v0, v1);
                *reinterpret_cast<__half2*>(&D[(size_t)r1 * ldd + c0]) = __floats2half2_rn(v2, v3);
            } else {
                *reinterpret_cast<float2*>(&D[(size_t)r0 * ldd + c0]) = make_float2(v0, v1);
                *reinterpret_cast<float2*>(&D[(size_t)r1 * ldd + c0]) = make_float2(v2, v3);
            }
        }
    }
}

// ---------------------------------------------------------------------------
extern "C" void kernel_launch(void* const* d_in, const int* in_sizes, int n_in,
                              void* d_out, int out_size)
{
    const float* x      = (const float*)d_in[0];
    const float* gn_w   = (const float*)d_in[1];
    const float* gn_b   = (const float*)d_in[2];
    const float* qkv_w  = (const float*)d_in[3];
    const float* qkv_b  = (const float*)d_in[4];
    const float* proj_w = (const float*)d_in[5];
    const float* proj_b = (const float*)d_in[6];
    float* out = (float*)d_out;

    __half *xnh, *xnT, *qk, *vT, *logits, *attn, *retT, *wh;
    cudaGetSymbolAddress((void**)&xnh,    g_xnh);
    cudaGetSymbolAddress((void**)&xnT,    g_xnT);
    cudaGetSymbolAddress((void**)&qk,     g_qk);
    cudaGetSymbolAddress((void**)&vT,     g_vT);
    cudaGetSymbolAddress((void**)&logits, g_logits);
    cudaGetSymbolAddress((void**)&attn,   g_attn);
    cudaGetSymbolAddress((void**)&retT,   g_retT);
    cudaGetSymbolAddress((void**)&wh,     g_wh);

    cudaFuncSetAttribute(hgemm_kernel<__half, 1, false>, cudaFuncAttributeMaxDynamicSharedMemorySize, GEMM_SMEM);
    cudaFuncSetAttribute(hgemm_kernel<__half, 2, false>, cudaFuncAttributeMaxDynamicSharedMemorySize, GEMM_SMEM);
    cudaFuncSetAttribute(hgemm_kernel<__half, 0, false>, cudaFuncAttributeMaxDynamicSharedMemorySize, GEMM_SMEM);
    cudaFuncSetAttribute(hgemm_kernel<float,  1, true>,  cudaFuncAttributeMaxDynamicSharedMemorySize, GEMM_SMEM);

    const long long sXN  = (long long)C * L;
    const long long sXNT = (long long)L * C;
    const long long sQK  = (long long)1024 * L;
    const long long sATT = (long long)C * C;

    // 0) weights -> fp16 (single launch)
    cvt_w_kernel<<<(4 * C * C + 255) / 256, 256>>>(qkv_w, proj_w, wh);

    // 1) GroupNorm -> xnh fp16 [C,L]
    groupnorm_kernel<<<BATCH * GROUPS, 256>>>(x, gn_w, gn_b, xnh);

    // 2) transpose -> xnT fp16 [L,C]
    {
        dim3 grid(L / 32, C / 32, BATCH);
        transpose_h_kernel<<<grid, dim3(32, 8)>>>(xnh, xnT);
    }

    // 3a) qk[o,l] = Wqk[o,:] . xnT[l,:] + qkv_b[o]   (M=1024, N=4096, K=512)
    {
        dim3 grid(L / 128, 1024 / 128, BATCH);
        hgemm_kernel<__half, 1, false><<<grid, 256, GEMM_SMEM>>>(
            wh, 0LL, C, xnT, sXNT, C, qk, sQK, L, C,
            qkv_b, nullptr, 0LL, 0, 1.0f);
    }
    // 3b) vT[l,o] = xnT[l,:] . Wv[o,:] + qkv_b[1024+o]  (M=4096, N=512, K=512)
    {
        dim3 grid(C / 128, L / 128, BATCH);
        hgemm_kernel<__half, 2, false><<<grid, 256, GEMM_SMEM>>>(
            xnT, sXNT, C, wh + (size_t)1024 * C, 0LL, C, vT, sXNT, C, C,
            qkv_b + 1024, nullptr, 0LL, 0, 1.0f);
    }
    // 4) logits[q,k] = Q[q,:] . K[k,:] / 64   (M=512, N=512, K=4096) -> fp16
    {
        dim3 grid(C / 128, C / 128, BATCH);
        hgemm_kernel<__half, 0, false><<<grid, 256, GEMM_SMEM>>>(
            qk, sQK, L, qk + (size_t)C * L, sQK, L, logits, sATT, C, L,
            nullptr, nullptr, 0LL, 0, 0.015625f);
    }
    // 5) softmax -> attn fp16
    softmax512_kernel<<<BATCH * C, 128>>>(logits, attn);

    // 6) retT[l,q] = vT[l,:] . attn[q,:]   (M=4096, N=512, K=512)
    {
        dim3 grid(C / 128, L / 128, BATCH);
        hgemm_kernel<__half, 0, false><<<grid, 256, GEMM_SMEM>>>(
            vT, sXNT, C, attn, sATT, C, retT, sXNT, C, C,
            nullptr, nullptr, 0LL, 0, 1.0f);
    }
    // 7) out[o,l] = P[o,:] . retT[l,:] + proj_b[o] + xnh[o,l]  (M=512, N=4096, K=512)
    {
        dim3 grid(L / 128, C / 128, BATCH);
        hgemm_kernel<float, 1, true><<<grid, 256, GEMM_SMEM>>>(
            wh + (size_t)3 * C * C, 0LL, C, retT, sXNT, C, out, sXN, L, C,
            proj_b, xnh, sXN, L, 1.0f);
    }
}

// round 5
// speedup vs baseline: 7.2928x; 1.0520x over previous
#include <cuda_runtime.h>
#include <cuda_fp16.h>
#include <cstdint>
#include <math.h>

#define BATCH 32
#define C 512
#define L 4096
#define GROUPS 32
#define CPG 16
#define EPS 1e-5f

// ---------------- scratch (device globals; allocation-free rule) -----------
__device__ __align__(256) __half g_xnh   [(size_t)BATCH * C * L];        // [C,L] normed (residual + GEMM B)
__device__ __align__(256) __half g_qkv   [(size_t)BATCH * 3 * C * L];    // rows: Q 0..511, K 512..1023, V 1024..1535
__device__ __align__(256) __half g_logits[(size_t)BATCH * C * C];
__device__ __align__(256) __half g_attn  [(size_t)BATCH * C * C];
__device__ __align__(256) __half g_ret   [(size_t)BATCH * C * L];        // [C,L]
__device__ __align__(256) __half g_wh    [(size_t)4 * C * C];            // qkv_w + proj_w

// ---------------- PTX helpers ----------------------------------------------
__device__ __forceinline__ uint32_t smem_u32(const void* p) {
    uint32_t a;
    asm("{ .reg .u64 t; cvta.to.shared.u64 t, %1; cvt.u32.u64 %0, t; }" : "=r"(a) : "l"(p));
    return a;
}
#define CP_ASYNC16(dst, src) \
    asm volatile("cp.async.cg.shared.global [%0], [%1], 16;" :: "r"(dst), "l"(src) : "memory")
#define CP_COMMIT() asm volatile("cp.async.commit_group;" ::: "memory")
#define CP_WAIT1()  asm volatile("cp.async.wait_group 1;" ::: "memory")
#define CP_WAIT0()  asm volatile("cp.async.wait_group 0;" ::: "memory")

__device__ __forceinline__ void ldsm_x4(uint32_t (&r)[4], uint32_t addr) {
    asm volatile("ldmatrix.sync.aligned.m8n8.x4.shared.b16 {%0,%1,%2,%3}, [%4];"
        : "=r"(r[0]), "=r"(r[1]), "=r"(r[2]), "=r"(r[3]) : "r"(addr));
}
__device__ __forceinline__ void ldsm_x4_t(uint32_t (&r)[4], uint32_t addr) {
    asm volatile("ldmatrix.sync.aligned.m8n8.x4.trans.shared.b16 {%0,%1,%2,%3}, [%4];"
        : "=r"(r[0]), "=r"(r[1]), "=r"(r[2]), "=r"(r[3]) : "r"(addr));
}
__device__ __forceinline__ void mma16816(float (&d)[4], const uint32_t (&a)[4],
                                         uint32_t b0, uint32_t b1) {
    asm volatile(
        "mma.sync.aligned.m16n8k16.row.col.f32.f16.f16.f32 "
        "{%0,%1,%2,%3}, {%4,%5,%6,%7}, {%8,%9}, {%0,%1,%2,%3};"
        : "+f"(d[0]), "+f"(d[1]), "+f"(d[2]), "+f"(d[3])
        : "r"(a[0]), "r"(a[1]), "r"(a[2]), "r"(a[3]), "r"(b0), "r"(b1));
}

// ---------------- GroupNorm -> fp16 [C,L] -----------------------------------
__global__ __launch_bounds__(256) void groupnorm_kernel(
    const float* __restrict__ x, const float* __restrict__ gw,
    const float* __restrict__ gb, __half* __restrict__ xnh)
{
    const int bg = blockIdx.x;
    const int b = bg / GROUPS;
    const int g = bg % GROUPS;
    const size_t base = ((size_t)b * C + (size_t)g * CPG) * L;
    const float4* px4 = (const float4*)(x + base);
    __half2* outh = (__half2*)(xnh + base);
    const int n4 = CPG * L / 4;

    const int tid = threadIdx.x;
    float s = 0.f, ss = 0.f;
    for (int i = tid; i < n4; i += 256) {
        float4 v = px4[i];
        s  += v.x + v.y + v.z + v.w;
        ss += v.x*v.x + v.y*v.y + v.z*v.z + v.w*v.w;
    }
    __shared__ float sh_s[32], sh_ss[32];
    for (int o = 16; o > 0; o >>= 1) {
        s  += __shfl_down_sync(0xffffffff, s, o);
        ss += __shfl_down_sync(0xffffffff, ss, o);
    }
    if ((tid & 31) == 0) { sh_s[tid >> 5] = s; sh_ss[tid >> 5] = ss; }
    __syncthreads();
    if (tid < 32) {
        s  = (tid < 8) ? sh_s[tid]  : 0.f;
        ss = (tid < 8) ? sh_ss[tid] : 0.f;
        for (int o = 4; o > 0; o >>= 1) {
            s  += __shfl_down_sync(0xffffffff, s, o);
            ss += __shfl_down_sync(0xffffffff, ss, o);
        }
        if (tid == 0) { sh_s[0] = s; sh_ss[0] = ss; }
    }
    __syncthreads();
    const float inv_n = 1.f / (float)(CPG * L);
    const float mean  = sh_s[0] * inv_n;
    const float var   = sh_ss[0] * inv_n - mean * mean;
    const float rstd  = rsqrtf(var + EPS);

    for (int i = tid; i < n4; i += 256) {
        const int ch = g * CPG + (i >> 10);
        const float w = gw[ch] * rstd;
        const float bb = gb[ch] - mean * w;
        float4 v = px4[i];
        outh[i * 2 + 0] = __floats2half2_rn(fmaf(v.x, w, bb), fmaf(v.y, w, bb));
        outh[i * 2 + 1] = __floats2half2_rn(fmaf(v.z, w, bb), fmaf(v.w, w, bb));
    }
}

// ---------------- fp32 -> fp16 weight convert -------------------------------
__global__ __launch_bounds__(256) void cvt_w_kernel(
    const float* __restrict__ qkvw, const float* __restrict__ projw,
    __half* __restrict__ out)
{
    const int i = blockIdx.x * 256 + threadIdx.x;
    const int n_qkv = 3 * C * C;
    if (i < n_qkv) out[i] = __float2half(qkvw[i]);
    else if (i < 4 * C * C) out[i] = __float2half(projw[i - n_qkv]);
}

// ---------------- Row softmax (fp16 in, fp16 out) ---------------------------
__global__ __launch_bounds__(128) void softmax512_kernel(
    const __half* __restrict__ logits, __half* __restrict__ attn)
{
    const size_t row = blockIdx.x;
    const __half2* p = (const __half2*)(logits + row * C);
    const int tid = threadIdx.x;

    float2 a = __half22float2(p[tid * 2 + 0]);
    float2 b = __half22float2(p[tid * 2 + 1]);
    float m = fmaxf(fmaxf(a.x, a.y), fmaxf(b.x, b.y));
    __shared__ float sh[4];
    for (int o = 16; o > 0; o >>= 1) m = fmaxf(m, __shfl_xor_sync(0xffffffff, m, o));
    if ((tid & 31) == 0) sh[tid >> 5] = m;
    __syncthreads();
    m = fmaxf(fmaxf(sh[0], sh[1]), fmaxf(sh[2], sh[3]));

    a.x = expf(a.x - m); a.y = expf(a.y - m);
    b.x = expf(b.x - m); b.y = expf(b.y - m);
    float s = a.x + a.y + b.x + b.y;
    for (int o = 16; o > 0; o >>= 1) s += __shfl_xor_sync(0xffffffff, s, o);
    __shared__ float shs[4];
    if ((tid & 31) == 0) shs[tid >> 5] = s;
    __syncthreads();
    s = shs[0] + shs[1] + shs[2] + shs[3];
    const float inv = 1.f / s;

    __half2* o2 = (__half2*)(attn + row * C);
    o2[tid * 2 + 0] = __floats2half2_rn(a.x * inv, a.y * inv);
    o2[tid * 2 + 1] = __floats2half2_rn(b.x * inv, b.y * inv);
}

// ---------------- fp16 tensor-core GEMM -------------------------------------
// D[M,N] = alpha * A[M,K] * B (+bias) (+res fp16).
//   A: [M,K] row-major (K-major).
//   B_TRANS=false: B is [N,K] row-major (NT GEMM).
//   B_TRANS=true : B is [K,N] row-major (loaded via ldmatrix.trans).
// 128x128 tile, BK=64, 256 threads (2m x 4n warps, warp tile 64x32),
// 3-stage cp.async ring w/ single __syncthreads per K-tile.
#define STAGE_BYTES 32768          // A 16KB + B 16KB
#define GEMM_SMEM  (3 * STAGE_BYTES)

// A tile: 128 rows x 64 halfs (128B rows), swizzled
__device__ __forceinline__ void load_A(const __half* __restrict__ gA, int lda,
                                       uint32_t st, int tid)
{
    #pragma unroll
    for (int j = 0; j < 4; j++) {
        const int slot = tid + 256 * j;
        const int row  = slot >> 3;           // 0..127
        const int c    = slot & 7;            // 16B chunk
        const uint32_t off = (uint32_t)row * 128u + (uint32_t)((c ^ (row & 7)) << 4);
        CP_ASYNC16(st + off, gA + (size_t)row * lda + c * 8);
    }
}
// B NT tile: 128 n-rows x 64 halfs (128B rows), same swizzle as A
__device__ __forceinline__ void load_B_nt(const __half* __restrict__ gB, int ldb,
                                          uint32_t st, int tid)
{
    #pragma unroll
    for (int j = 0; j < 4; j++) {
        const int slot = tid + 256 * j;
        const int row  = slot >> 3;
        const int c    = slot & 7;
        const uint32_t off = (uint32_t)row * 128u + (uint32_t)((c ^ (row & 7)) << 4);
        CP_ASYNC16(st + off, gB + (size_t)row * ldb + c * 8);
    }
}
// B trans tile: 64 k-rows x 128 halfs (256B rows as 2x128B), swizzled per k row
__device__ __forceinline__ void load_B_t(const __half* __restrict__ gB, int ldb,
                                         uint32_t st, int tid)
{
    #pragma unroll
    for (int j = 0; j < 4; j++) {
        const int slot = tid + 256 * j;
        const int row  = slot >> 4;           // 0..63 (k)
        const int c    = slot & 15;           // 16B chunk (n/8)
        const uint32_t off = (uint32_t)((row * 2 + (c >> 3)) * 128)
                           + (uint32_t)(((c & 7) ^ (row & 7)) << 4);
        CP_ASYNC16(st + off, gB + (size_t)row * ldb + c * 8);
    }
}

template<typename OutT, int BIAS_MODE, bool ADD_RES, bool B_TRANS>
__global__ __launch_bounds__(256, 2) void hgemm_kernel(
    const __half* __restrict__ A, long long sA, int lda,
    const __half* __restrict__ B, long long sB, int ldb,
    OutT* __restrict__ D, long long sD, int ldd,
    int K,
    const float* __restrict__ bias,
    const __half* __restrict__ res, long long sRes, int ldres,
    float alpha)
{
    extern __shared__ __align__(128) char smem[];
    const uint32_t sbase = smem_u32(smem);

    const int bz = blockIdx.z;
    A += (size_t)bz * sA;
    B += (size_t)bz * sB;
    D += (size_t)bz * sD;
    if (ADD_RES) res += (size_t)bz * sRes;

    const int bm = blockIdx.y * 128;
    const int bn = blockIdx.x * 128;
    const int tid = threadIdx.x;
    const int lane = tid & 31;
    const int wm = (tid >> 5) & 1;
    const int wn = tid >> 6;

    const __half* gA = A + (size_t)bm * lda;
    const __half* gB = B_TRANS ? (B + bn) : (B + (size_t)bn * ldb);
    const int T = K >> 6;

    const int a_row_lo = lane & 15;
    const int a_sel    = lane >> 4;
    // NT B fragment addressing
    const int b_row_lo = (lane & 7) + ((lane >> 4) << 3);
    const int b_sel    = (lane >> 3) & 1;
    // trans-B fragment addressing
    const int bt_k_lo  = lane & 15;          // k row within 16
    const int bt_n8    = (lane >> 4) << 3;   // 0 or 8

    float acc[4][4][4];
    #pragma unroll
    for (int i = 0; i < 4; i++)
        #pragma unroll
        for (int j = 0; j < 4; j++)
            #pragma unroll
            for (int q = 0; q < 4; q++) acc[i][j][q] = 0.f;

    // prologue: stages 0,1
    #pragma unroll
    for (int s = 0; s < 2; s++) {
        const uint32_t st = sbase + s * STAGE_BYTES;
        load_A(gA + s * 64, lda, st, tid);
        if (B_TRANS) load_B_t(gB + (size_t)(s * 64) * ldb, ldb, st + 16384, tid);
        else         load_B_nt(gB + s * 64, ldb, st + 16384, tid);
        CP_COMMIT();
    }

    for (int t = 0; t < T; t++) {
        if (t < T - 1) CP_WAIT1(); else CP_WAIT0();
        __syncthreads();

        if (t + 2 < T) {
            const int s = t + 2;
            const uint32_t st = sbase + (s % 3) * STAGE_BYTES;
            load_A(gA + s * 64, lda, st, tid);
            if (B_TRANS) load_B_t(gB + (size_t)(s * 64) * ldb, ldb, st + 16384, tid);
            else         load_B_nt(gB + s * 64, ldb, st + 16384, tid);
            CP_COMMIT();
        }

        const uint32_t stA = sbase + (t % 3) * STAGE_BYTES;
        const uint32_t stB = stA + 16384;

        #pragma unroll
        for (int ks = 0; ks < 4; ks++) {
            uint32_t aF[4][4];
            uint32_t bF[2][4];
            #pragma unroll
            for (int mi = 0; mi < 4; mi++) {
                const int row = wm * 64 + mi * 16 + a_row_lo;
                const int ch  = ks * 2 + a_sel;
                ldsm_x4(aF[mi], stA + (uint32_t)row * 128u + (uint32_t)((ch ^ (row & 7)) << 4));
            }
            if (B_TRANS) {
                const int krow = ks * 16 + bt_k_lo;    // 0..63
                #pragma unroll
                for (int nb = 0; nb < 2; nb++) {
                    const int n = wn * 32 + nb * 16 + bt_n8;
                    const uint32_t addr = stB
                        + (uint32_t)((krow * 2 + (n >> 6)) * 128)
                        + (uint32_t)((((n >> 3) & 7) ^ (krow & 7)) << 4);
                    ldsm_x4_t(bF[nb], addr);
                }
            } else {
                #pragma unroll
                for (int nb = 0; nb < 2; nb++) {
                    const int row = wn * 32 + nb * 16 + b_row_lo;
                    const int ch  = ks * 2 + b_sel;
                    ldsm_x4(bF[nb], stB + (uint32_t)row * 128u + (uint32_t)((ch ^ (row & 7)) << 4));
                }
            }
            #pragma unroll
            for (int mi = 0; mi < 4; mi++)
                #pragma unroll
                for (int nj = 0; nj < 4; nj++)
                    mma16816(acc[mi][nj], aF[mi],
                             bF[nj >> 1][(nj & 1) * 2], bF[nj >> 1][(nj & 1) * 2 + 1]);
        }
    }

    // epilogue
    const int m0 = bm + wm * 64;
    const int n0 = bn + wn * 32;
    #pragma unroll
    for (int mi = 0; mi < 4; mi++) {
        const int r0 = m0 + mi * 16 + (lane >> 2);
        const int r1 = r0 + 8;
        float br0 = 0.f, br1 = 0.f;
        if (BIAS_MODE == 1) { br0 = bias[r0]; br1 = bias[r1]; }
        #pragma unroll
        for (int nj = 0; nj < 4; nj++) {
            const int c0 = n0 + nj * 8 + (lane & 3) * 2;
            float v0 = acc[mi][nj][0] * alpha;
            float v1 = acc[mi][nj][1] * alpha;
            float v2 = acc[mi][nj][2] * alpha;
            float v3 = acc[mi][nj][3] * alpha;
            if (BIAS_MODE == 1) { v0 += br0; v1 += br0; v2 += br1; v3 += br1; }
            if (ADD_RES) {
                const float2 q0 = __half22float2(*(const __half2*)&res[(size_t)r0 * ldres + c0]);
                const float2 q1 = __half22float2(*(const __half2*)&res[(size_t)r1 * ldres + c0]);
                v0 += q0.x; v1 += q0.y; v2 += q1.x; v3 += q1.y;
            }
            if constexpr (sizeof(OutT) == 2) {
                *reinterpret_cast<__half2*>(&D[(size_t)r0 * ldd + c0]) = __floats2half2_rn(v0, v1);
                *reinterpret_cast<__half2*>(&D[(size_t)r1 * ldd + c0]) = __floats2half2_rn(v2, v3);
            } else {
                *reinterpret_cast<float2*>(&D[(size_t)r0 * ldd + c0]) = make_float2(v0, v1);
                *reinterpret_cast<float2*>(&D[(size_t)r1 * ldd + c0]) = make_float2(v2, v3);
            }
        }
    }
}

// ---------------------------------------------------------------------------
extern "C" void kernel_launch(void* const* d_in, const int* in_sizes, int n_in,
                              void* d_out, int out_size)
{
    const float* x      = (const float*)d_in[0];
    const float* gn_w   = (const float*)d_in[1];
    const float* gn_b   = (const float*)d_in[2];
    const float* qkv_w  = (const float*)d_in[3];
    const float* qkv_b  = (const float*)d_in[4];
    const float* proj_w = (const float*)d_in[5];
    const float* proj_b = (const float*)d_in[6];
    float* out = (float*)d_out;

    __half *xnh, *qkv, *logits, *attn, *ret, *wh;
    cudaGetSymbolAddress((void**)&xnh,    g_xnh);
    cudaGetSymbolAddress((void**)&qkv,    g_qkv);
    cudaGetSymbolAddress((void**)&logits, g_logits);
    cudaGetSymbolAddress((void**)&attn,   g_attn);
    cudaGetSymbolAddress((void**)&ret,    g_ret);
    cudaGetSymbolAddress((void**)&wh,     g_wh);

    cudaFuncSetAttribute(hgemm_kernel<__half, 1, false, true>,  cudaFuncAttributeMaxDynamicSharedMemorySize, GEMM_SMEM);
    cudaFuncSetAttribute(hgemm_kernel<__half, 0, false, false>, cudaFuncAttributeMaxDynamicSharedMemorySize, GEMM_SMEM);
    cudaFuncSetAttribute(hgemm_kernel<__half, 0, false, true>,  cudaFuncAttributeMaxDynamicSharedMemorySize, GEMM_SMEM);
    cudaFuncSetAttribute(hgemm_kernel<float,  1, true,  true>,  cudaFuncAttributeMaxDynamicSharedMemorySize, GEMM_SMEM);

    const long long sXN  = (long long)C * L;
    const long long sQKV = (long long)3 * C * L;
    const long long sATT = (long long)C * C;

    // 0) weights -> fp16
    cvt_w_kernel<<<(4 * C * C + 255) / 256, 256>>>(qkv_w, proj_w, wh);

    // 1) GroupNorm -> xnh fp16 [C,L]
    groupnorm_kernel<<<BATCH * GROUPS, 256>>>(x, gn_w, gn_b, xnh);

    // 2) QKV (incl. V): qkv[o,l] = Wqkv[o,:]·xnh[:,l] + b[o]  (M=1536,N=4096,K=512)
    {
        dim3 grid(L / 128, 1536 / 128, BATCH);
        hgemm_kernel<__half, 1, false, true><<<grid, 256, GEMM_SMEM>>>(
            wh, 0LL, C, xnh, sXN, L, qkv, sQKV, L, C,
            qkv_b, nullptr, 0LL, 0, 1.0f);
    }
    // 3) logits[q,k] = Q[q,:]·K[k,:] / 64   (M=512,N=512,K=4096), NT
    {
        dim3 grid(C / 128, C / 128, BATCH);
        hgemm_kernel<__half, 0, false, false><<<grid, 256, GEMM_SMEM>>>(
            qkv, sQKV, L, qkv + (size_t)C * L, sQKV, L, logits, sATT, C, L,
            nullptr, nullptr, 0LL, 0, 0.015625f);
    }
    // 4) softmax -> attn fp16
    softmax512_kernel<<<BATCH * C, 128>>>(logits, attn);

    // 5) ret[q,l] = attn[q,:]·V[:,l]   (M=512,N=4096,K=512), trans-B
    {
        dim3 grid(L / 128, C / 128, BATCH);
        hgemm_kernel<__half, 0, false, true><<<grid, 256, GEMM_SMEM>>>(
            attn, sATT, C, qkv + (size_t)2 * C * L, sQKV, L, ret, sXN, L, C,
            nullptr, nullptr, 0LL, 0, 1.0f);
    }
    // 6) out[o,l] = P[o,:]·ret[:,l] + proj_b[o] + xnh[o,l]  (M=512,N=4096,K=512)
    {
        dim3 grid(L / 128, C / 128, BATCH);
        hgemm_kernel<float, 1, true, true><<<grid, 256, GEMM_SMEM>>>(
            wh + (size_t)3 * C * C, 0LL, C, ret, sXN, L, out, sXN, L, C,
            proj_b, xnh, sXN, L, 1.0f);
    }
}

// round 6
// speedup vs baseline: 8.0583x; 1.1050x over previous
#include <cuda_runtime.h>
#include <cuda_fp16.h>
#include <cstdint>
#include <math.h>

#define BATCH 32
#define C 512
#define L 4096
#define GROUPS 32
#define CPG 16
#define EPS 1e-5f

// ---------------- scratch (device globals; allocation-free rule) -----------
__device__ __align__(256) __half g_xnh   [(size_t)BATCH * C * L];        // [C,L] normed (residual + GEMM B)
__device__ __align__(256) __half g_qkv   [(size_t)BATCH * 3 * C * L];    // rows: Q 0..511, K 512..1023, V 1024..1535
__device__ __align__(256) __half g_logits[(size_t)BATCH * C * C];
__device__ __align__(256) __half g_attn  [(size_t)BATCH * C * C];
__device__ __align__(256) __half g_ret   [(size_t)BATCH * C * L];        // [C,L]
__device__ __align__(256) __half g_wh    [(size_t)4 * C * C];            // qkv_w + proj_w

// ---------------- PTX helpers ----------------------------------------------
__device__ __forceinline__ uint32_t smem_u32(const void* p) {
    uint32_t a;
    asm("{ .reg .u64 t; cvta.to.shared.u64 t, %1; cvt.u32.u64 %0, t; }" : "=r"(a) : "l"(p));
    return a;
}
#define CP_ASYNC16(dst, src) \
    asm volatile("cp.async.cg.shared.global [%0], [%1], 16;" :: "r"(dst), "l"(src) : "memory")
#define CP_COMMIT() asm volatile("cp.async.commit_group;" ::: "memory")
#define CP_WAIT1()  asm volatile("cp.async.wait_group 1;" ::: "memory")
#define CP_WAIT0()  asm volatile("cp.async.wait_group 0;" ::: "memory")

__device__ __forceinline__ void ldsm_x4(uint32_t (&r)[4], uint32_t addr) {
    asm volatile("ldmatrix.sync.aligned.m8n8.x4.shared.b16 {%0,%1,%2,%3}, [%4];"
        : "=r"(r[0]), "=r"(r[1]), "=r"(r[2]), "=r"(r[3]) : "r"(addr));
}
__device__ __forceinline__ void ldsm_x4_t(uint32_t (&r)[4], uint32_t addr) {
    asm volatile("ldmatrix.sync.aligned.m8n8.x4.trans.shared.b16 {%0,%1,%2,%3}, [%4];"
        : "=r"(r[0]), "=r"(r[1]), "=r"(r[2]), "=r"(r[3]) : "r"(addr));
}
__device__ __forceinline__ void mma16816(float (&d)[4], const uint32_t (&a)[4],
                                         uint32_t b0, uint32_t b1) {
    asm volatile(
        "mma.sync.aligned.m16n8k16.row.col.f32.f16.f16.f32 "
        "{%0,%1,%2,%3}, {%4,%5,%6,%7}, {%8,%9}, {%0,%1,%2,%3};"
        : "+f"(d[0]), "+f"(d[1]), "+f"(d[2]), "+f"(d[3])
        : "r"(a[0]), "r"(a[1]), "r"(a[2]), "r"(a[3]), "r"(b0), "r"(b1));
}

// ---------------- GroupNorm -> fp16 [C,L] -----------------------------------
__global__ __launch_bounds__(256) void groupnorm_kernel(
    const float* __restrict__ x, const float* __restrict__ gw,
    const float* __restrict__ gb, __half* __restrict__ xnh)
{
    const int bg = blockIdx.x;
    const int b = bg / GROUPS;
    const int g = bg % GROUPS;
    const size_t base = ((size_t)b * C + (size_t)g * CPG) * L;
    const float4* px4 = (const float4*)(x + base);
    __half2* outh = (__half2*)(xnh + base);
    const int n4 = CPG * L / 4;

    const int tid = threadIdx.x;
    float s = 0.f, ss = 0.f;
    for (int i = tid; i < n4; i += 256) {
        float4 v = px4[i];
        s  += v.x + v.y + v.z + v.w;
        ss += v.x*v.x + v.y*v.y + v.z*v.z + v.w*v.w;
    }
    __shared__ float sh_s[32], sh_ss[32];
    for (int o = 16; o > 0; o >>= 1) {
        s  += __shfl_down_sync(0xffffffff, s, o);
        ss += __shfl_down_sync(0xffffffff, ss, o);
    }
    if ((tid & 31) == 0) { sh_s[tid >> 5] = s; sh_ss[tid >> 5] = ss; }
    __syncthreads();
    if (tid < 32) {
        s  = (tid < 8) ? sh_s[tid]  : 0.f;
        ss = (tid < 8) ? sh_ss[tid] : 0.f;
        for (int o = 4; o > 0; o >>= 1) {
            s  += __shfl_down_sync(0xffffffff, s, o);
            ss += __shfl_down_sync(0xffffffff, ss, o);
        }
        if (tid == 0) { sh_s[0] = s; sh_ss[0] = ss; }
    }
    __syncthreads();
    const float inv_n = 1.f / (float)(CPG * L);
    const float mean  = sh_s[0] * inv_n;
    const float var   = sh_ss[0] * inv_n - mean * mean;
    const float rstd  = rsqrtf(var + EPS);

    for (int i = tid; i < n4; i += 256) {
        const int ch = g * CPG + (i >> 10);
        const float w = gw[ch] * rstd;
        const float bb = gb[ch] - mean * w;
        float4 v = px4[i];
        outh[i * 2 + 0] = __floats2half2_rn(fmaf(v.x, w, bb), fmaf(v.y, w, bb));
        outh[i * 2 + 1] = __floats2half2_rn(fmaf(v.z, w, bb), fmaf(v.w, w, bb));
    }
}

// ---------------- fp32 -> fp16 weight convert -------------------------------
__global__ __launch_bounds__(256) void cvt_w_kernel(
    const float* __restrict__ qkvw, const float* __restrict__ projw,
    __half* __restrict__ out)
{
    const int i = blockIdx.x * 256 + threadIdx.x;
    const int n_qkv = 3 * C * C;
    if (i < n_qkv) out[i] = __float2half(qkvw[i]);
    else if (i < 4 * C * C) out[i] = __float2half(projw[i - n_qkv]);
}

// ---------------- Row softmax (fp16 in, fp16 out) ---------------------------
__global__ __launch_bounds__(128) void softmax512_kernel(
    const __half* __restrict__ logits, __half* __restrict__ attn)
{
    const size_t row = blockIdx.x;
    const __half2* p = (const __half2*)(logits + row * C);
    const int tid = threadIdx.x;

    float2 a = __half22float2(p[tid * 2 + 0]);
    float2 b = __half22float2(p[tid * 2 + 1]);
    float m = fmaxf(fmaxf(a.x, a.y), fmaxf(b.x, b.y));
    __shared__ float sh[4];
    for (int o = 16; o > 0; o >>= 1) m = fmaxf(m, __shfl_xor_sync(0xffffffff, m, o));
    if ((tid & 31) == 0) sh[tid >> 5] = m;
    __syncthreads();
    m = fmaxf(fmaxf(sh[0], sh[1]), fmaxf(sh[2], sh[3]));

    a.x = expf(a.x - m); a.y = expf(a.y - m);
    b.x = expf(b.x - m); b.y = expf(b.y - m);
    float s = a.x + a.y + b.x + b.y;
    for (int o = 16; o > 0; o >>= 1) s += __shfl_xor_sync(0xffffffff, s, o);
    __shared__ float shs[4];
    if ((tid & 31) == 0) shs[tid >> 5] = s;
    __syncthreads();
    s = shs[0] + shs[1] + shs[2] + shs[3];
    const float inv = 1.f / s;

    __half2* o2 = (__half2*)(attn + row * C);
    o2[tid * 2 + 0] = __floats2half2_rn(a.x * inv, a.y * inv);
    o2[tid * 2 + 1] = __floats2half2_rn(b.x * inv, b.y * inv);
}

// ---------------- fp16 tensor-core GEMM -------------------------------------
// D[M,N] = alpha * A[M,K] * B (+bias) (+res fp16).
//   A: [M,K] row-major (K-major).
//   B_TRANS=false: B is [N,K] row-major (NT GEMM).
//   B_TRANS=true : B is [K,N] row-major (loaded via ldmatrix.trans).
// CTA tile 128x128, BK=64, 128 threads = 4 warps (2m x 2n), warp tile 64x64.
// 3-stage cp.async ring, single __syncthreads per K-tile.
#define STAGE_BYTES 32768          // A 16KB + B 16KB
#define GEMM_SMEM  (3 * STAGE_BYTES)

// A tile: 128 rows x 64 halfs (128B rows), swizzled. 128 threads.
__device__ __forceinline__ void load_A(const __half* __restrict__ gA, int lda,
                                       uint32_t st, int tid)
{
    #pragma unroll
    for (int j = 0; j < 8; j++) {
        const int slot = tid + 128 * j;
        const int row  = slot >> 3;           // 0..127
        const int c    = slot & 7;            // 16B chunk
        const uint32_t off = (uint32_t)row * 128u + (uint32_t)((c ^ (row & 7)) << 4);
        CP_ASYNC16(st + off, gA + (size_t)row * lda + c * 8);
    }
}
// B NT tile: 128 n-rows x 64 halfs (128B rows), same swizzle as A
__device__ __forceinline__ void load_B_nt(const __half* __restrict__ gB, int ldb,
                                          uint32_t st, int tid)
{
    #pragma unroll
    for (int j = 0; j < 8; j++) {
        const int slot = tid + 128 * j;
        const int row  = slot >> 3;
        const int c    = slot & 7;
        const uint32_t off = (uint32_t)row * 128u + (uint32_t)((c ^ (row & 7)) << 4);
        CP_ASYNC16(st + off, gB + (size_t)row * ldb + c * 8);
    }
}
// B trans tile: 64 k-rows x 128 halfs (256B rows as 2x128B), swizzled per k row
__device__ __forceinline__ void load_B_t(const __half* __restrict__ gB, int ldb,
                                         uint32_t st, int tid)
{
    #pragma unroll
    for (int j = 0; j < 8; j++) {
        const int slot = tid + 128 * j;
        const int row  = slot >> 4;           // 0..63 (k)
        const int c    = slot & 15;           // 16B chunk (n/8)
        const uint32_t off = (uint32_t)((row * 2 + (c >> 3)) * 128)
                           + (uint32_t)(((c & 7) ^ (row & 7)) << 4);
        CP_ASYNC16(st + off, gB + (size_t)row * ldb + c * 8);
    }
}

template<typename OutT, int BIAS_MODE, bool ADD_RES, bool B_TRANS>
__global__ __launch_bounds__(128, 2) void hgemm_kernel(
    const __half* __restrict__ A, long long sA, int lda,
    const __half* __restrict__ B, long long sB, int ldb,
    OutT* __restrict__ D, long long sD, int ldd,
    int K,
    const float* __restrict__ bias,
    const __half* __restrict__ res, long long sRes, int ldres,
    float alpha)
{
    extern __shared__ __align__(128) char smem[];
    const uint32_t sbase = smem_u32(smem);

    const int bz = blockIdx.z;
    A += (size_t)bz * sA;
    B += (size_t)bz * sB;
    D += (size_t)bz * sD;
    if (ADD_RES) res += (size_t)bz * sRes;

    const int bm = blockIdx.y * 128;
    const int bn = blockIdx.x * 128;
    const int tid = threadIdx.x;
    const int lane = tid & 31;
    const int wid = tid >> 5;
    const int wm = wid & 1;           // 0..1 (m)
    const int wn = wid >> 1;          // 0..1 (n)

    const __half* gA = A + (size_t)bm * lda;
    const __half* gB = B_TRANS ? (B + bn) : (B + (size_t)bn * ldb);
    const int T = K >> 6;

    const int a_row_lo = lane & 15;
    const int a_sel    = lane >> 4;
    // NT B fragment addressing
    const int b_row_lo = (lane & 7) + ((lane >> 4) << 3);
    const int b_sel    = (lane >> 3) & 1;
    // trans-B fragment addressing
    const int bt_k_lo  = lane & 15;          // k row within 16
    const int bt_n8    = (lane >> 4) << 3;   // 0 or 8

    float acc[4][8][4];
    #pragma unroll
    for (int i = 0; i < 4; i++)
        #pragma unroll
        for (int j = 0; j < 8; j++)
            #pragma unroll
            for (int q = 0; q < 4; q++) acc[i][j][q] = 0.f;

    // prologue: stages 0,1
    #pragma unroll
    for (int s = 0; s < 2; s++) {
        const uint32_t st = sbase + s * STAGE_BYTES;
        load_A(gA + s * 64, lda, st, tid);
        if (B_TRANS) load_B_t(gB + (size_t)(s * 64) * ldb, ldb, st + 16384, tid);
        else         load_B_nt(gB + s * 64, ldb, st + 16384, tid);
        CP_COMMIT();
    }

    for (int t = 0; t < T; t++) {
        if (t < T - 1) CP_WAIT1(); else CP_WAIT0();
        __syncthreads();

        if (t + 2 < T) {
            const int s = t + 2;
            const uint32_t st = sbase + (s % 3) * STAGE_BYTES;
            load_A(gA + s * 64, lda, st, tid);
            if (B_TRANS) load_B_t(gB + (size_t)(s * 64) * ldb, ldb, st + 16384, tid);
            else         load_B_nt(gB + s * 64, ldb, st + 16384, tid);
            CP_COMMIT();
        }

        const uint32_t stA = sbase + (t % 3) * STAGE_BYTES;
        const uint32_t stB = stA + 16384;

        #pragma unroll
        for (int ks = 0; ks < 4; ks++) {
            uint32_t aF[4][4];
            uint32_t bF[4][4];
            #pragma unroll
            for (int mi = 0; mi < 4; mi++) {
                const int row = wm * 64 + mi * 16 + a_row_lo;
                const int ch  = ks * 2 + a_sel;
                ldsm_x4(aF[mi], stA + (uint32_t)row * 128u + (uint32_t)((ch ^ (row & 7)) << 4));
            }
            if (B_TRANS) {
                const int krow = ks * 16 + bt_k_lo;    // 0..63
                #pragma unroll
                for (int nb = 0; nb < 4; nb++) {
                    const int n = wn * 64 + nb * 16 + bt_n8;
                    const uint32_t addr = stB
                        + (uint32_t)((krow * 2 + (n >> 6)) * 128)
                        + (uint32_t)((((n >> 3) & 7) ^ (krow & 7)) << 4);
                    ldsm_x4_t(bF[nb], addr);
                }
            } else {
                #pragma unroll
                for (int nb = 0; nb < 4; nb++) {
                    const int row = wn * 64 + nb * 16 + b_row_lo;
                    const int ch  = ks * 2 + b_sel;
                    ldsm_x4(bF[nb], stB + (uint32_t)row * 128u + (uint32_t)((ch ^ (row & 7)) << 4));
                }
            }
            #pragma unroll
            for (int mi = 0; mi < 4; mi++)
                #pragma unroll
                for (int nj = 0; nj < 8; nj++)
                    mma16816(acc[mi][nj], aF[mi],
                             bF[nj >> 1][(nj & 1) * 2], bF[nj >> 1][(nj & 1) * 2 + 1]);
        }
    }

    // epilogue
    const int m0 = bm + wm * 64;
    const int n0 = bn + wn * 64;
    #pragma unroll
    for (int mi = 0; mi < 4; mi++) {
        const int r0 = m0 + mi * 16 + (lane >> 2);
        const int r1 = r0 + 8;
        float br0 = 0.f, br1 = 0.f;
        if (BIAS_MODE == 1) { br0 = bias[r0]; br1 = bias[r1]; }
        #pragma unroll
        for (int nj = 0; nj < 8; nj++) {
            const int c0 = n0 + nj * 8 + (lane & 3) * 2;
            float v0 = acc[mi][nj][0] * alpha;
            float v1 = acc[mi][nj][1] * alpha;
            float v2 = acc[mi][nj][2] * alpha;
            float v3 = acc[mi][nj][3] * alpha;
            if (BIAS_MODE == 1) { v0 += br0; v1 += br0; v2 += br1; v3 += br1; }
            if (ADD_RES) {
                const float2 q0 = __half22float2(*(const __half2*)&res[(size_t)r0 * ldres + c0]);
                const float2 q1 = __half22float2(*(const __half2*)&res[(size_t)r1 * ldres + c0]);
                v0 += q0.x; v1 += q0.y; v2 += q1.x; v3 += q1.y;
            }
            if constexpr (sizeof(OutT) == 2) {
                *reinterpret_cast<__half2*>(&D[(size_t)r0 * ldd + c0]) = __floats2half2_rn(v0, v1);
                *reinterpret_cast<__half2*>(&D[(size_t)r1 * ldd + c0]) = __floats2half2_rn(v2, v3);
            } else {
                *reinterpret_cast<float2*>(&D[(size_t)r0 * ldd + c0]) = make_float2(v0, v1);
                *reinterpret_cast<float2*>(&D[(size_t)r1 * ldd + c0]) = make_float2(v2, v3);
            }
        }
    }
}

// ---------------------------------------------------------------------------
extern "C" void kernel_launch(void* const* d_in, const int* in_sizes, int n_in,
                              void* d_out, int out_size)
{
    const float* x      = (const float*)d_in[0];
    const float* gn_w   = (const float*)d_in[1];
    const float* gn_b   = (const float*)d_in[2];
    const float* qkv_w  = (const float*)d_in[3];
    const float* qkv_b  = (const float*)d_in[4];
    const float* proj_w = (const float*)d_in[5];
    const float* proj_b = (const float*)d_in[6];
    float* out = (float*)d_out;

    __half *xnh, *qkv, *logits, *attn, *ret, *wh;
    cudaGetSymbolAddress((void**)&xnh,    g_xnh);
    cudaGetSymbolAddress((void**)&qkv,    g_qkv);
    cudaGetSymbolAddress((void**)&logits, g_logits);
    cudaGetSymbolAddress((void**)&attn,   g_attn);
    cudaGetSymbolAddress((void**)&ret,    g_ret);
    cudaGetSymbolAddress((void**)&wh,     g_wh);

    cudaFuncSetAttribute(hgemm_kernel<__half, 1, false, true>,  cudaFuncAttributeMaxDynamicSharedMemorySize, GEMM_SMEM);
    cudaFuncSetAttribute(hgemm_kernel<__half, 0, false, false>, cudaFuncAttributeMaxDynamicSharedMemorySize, GEMM_SMEM);
    cudaFuncSetAttribute(hgemm_kernel<__half, 0, false, true>,  cudaFuncAttributeMaxDynamicSharedMemorySize, GEMM_SMEM);
    cudaFuncSetAttribute(hgemm_kernel<float,  1, true,  true>,  cudaFuncAttributeMaxDynamicSharedMemorySize, GEMM_SMEM);

    const long long sXN  = (long long)C * L;
    const long long sQKV = (long long)3 * C * L;
    const long long sATT = (long long)C * C;

    // 0) weights -> fp16
    cvt_w_kernel<<<(4 * C * C + 255) / 256, 256>>>(qkv_w, proj_w, wh);

    // 1) GroupNorm -> xnh fp16 [C,L]
    groupnorm_kernel<<<BATCH * GROUPS, 256>>>(x, gn_w, gn_b, xnh);

    // 2) QKV (incl. V): qkv[o,l] = Wqkv[o,:]·xnh[:,l] + b[o]  (M=1536,N=4096,K=512)
    {
        dim3 grid(L / 128, 1536 / 128, BATCH);
        hgemm_kernel<__half, 1, false, true><<<grid, 128, GEMM_SMEM>>>(
            wh, 0LL, C, xnh, sXN, L, qkv, sQKV, L, C,
            qkv_b, nullptr, 0LL, 0, 1.0f);
    }
    // 3) logits[q,k] = Q[q,:]·K[k,:] / 64   (M=512,N=512,K=4096), NT
    {
        dim3 grid(C / 128, C / 128, BATCH);
        hgemm_kernel<__half, 0, false, false><<<grid, 128, GEMM_SMEM>>>(
            qkv, sQKV, L, qkv + (size_t)C * L, sQKV, L, logits, sATT, C, L,
            nullptr, nullptr, 0LL, 0, 0.015625f);
    }
    // 4) softmax -> attn fp16
    softmax512_kernel<<<BATCH * C, 128>>>(logits, attn);

    // 5) ret[q,l] = attn[q,:]·V[:,l]   (M=512,N=4096,K=512), trans-B
    {
        dim3 grid(L / 128, C / 128, BATCH);
        hgemm_kernel<__half, 0, false, true><<<grid, 128, GEMM_SMEM>>>(
            attn, sATT, C, qkv + (size_t)2 * C * L, sQKV, L, ret, sXN, L, C,
            nullptr, nullptr, 0LL, 0, 1.0f);
    }
    // 6) out[o,l] = P[o,:]·ret[:,l] + proj_b[o] + xnh[o,l]  (M=512,N=4096,K=512)
    {
        dim3 grid(L / 128, C / 128, BATCH);
        hgemm_kernel<float, 1, true, true><<<grid, 128, GEMM_SMEM>>>(
            wh + (size_t)3 * C * C, 0LL, C, ret, sXN, L, out, sXN, L, C,
            proj_b, xnh, sXN, L, 1.0f);
    }
}

// round 7
// speedup vs baseline: 8.1848x; 1.0157x over previous
#include <cuda_runtime.h>
#include <cuda_fp16.h>
#include <cstdint>
#include <math.h>

#define BATCH 32
#define C 512
#define L 4096
#define GROUPS 32
#define CPG 16
#define EPS 1e-5f

// ---------------- scratch (device globals; allocation-free rule) -----------
__device__ __align__(256) __half g_xnh   [(size_t)BATCH * C * L];        // [C,L] normed
__device__ __align__(256) __half g_qkv   [(size_t)BATCH * 3 * C * L];    // Q 0..511, K 512..1023, V 1024..1535
__device__ __align__(256) __half g_logits[(size_t)BATCH * C * C];
__device__ __align__(256) __half g_attn  [(size_t)BATCH * C * C];
__device__ __align__(256) __half g_ret   [(size_t)BATCH * C * L];        // [C,L]
__device__ __align__(256) __half g_wh    [(size_t)4 * C * C];            // qkv_w + proj_w

// ---------------- PTX helpers ----------------------------------------------
__device__ __forceinline__ uint32_t smem_u32(const void* p) {
    uint32_t a;
    asm("{ .reg .u64 t; cvta.to.shared.u64 t, %1; cvt.u32.u64 %0, t; }" : "=r"(a) : "l"(p));
    return a;
}
#define CP_ASYNC16(dst, src) \
    asm volatile("cp.async.cg.shared.global [%0], [%1], 16;" :: "r"(dst), "l"(src) : "memory")
#define CP_COMMIT() asm volatile("cp.async.commit_group;" ::: "memory")
#define CP_WAIT1()  asm volatile("cp.async.wait_group 1;" ::: "memory")
#define CP_WAIT0()  asm volatile("cp.async.wait_group 0;" ::: "memory")

__device__ __forceinline__ void ldsm_x4(uint32_t (&r)[4], uint32_t addr) {
    asm volatile("ldmatrix.sync.aligned.m8n8.x4.shared.b16 {%0,%1,%2,%3}, [%4];"
        : "=r"(r[0]), "=r"(r[1]), "=r"(r[2]), "=r"(r[3]) : "r"(addr));
}
__device__ __forceinline__ void ldsm_x4_t(uint32_t (&r)[4], uint32_t addr) {
    asm volatile("ldmatrix.sync.aligned.m8n8.x4.trans.shared.b16 {%0,%1,%2,%3}, [%4];"
        : "=r"(r[0]), "=r"(r[1]), "=r"(r[2]), "=r"(r[3]) : "r"(addr));
}
__device__ __forceinline__ void mma16816(float (&d)[4], const uint32_t (&a)[4],
                                         uint32_t b0, uint32_t b1) {
    asm volatile(
        "mma.sync.aligned.m16n8k16.row.col.f32.f16.f16.f32 "
        "{%0,%1,%2,%3}, {%4,%5,%6,%7}, {%8,%9}, {%0,%1,%2,%3};"
        : "+f"(d[0]), "+f"(d[1]), "+f"(d[2]), "+f"(d[3])
        : "r"(a[0]), "r"(a[1]), "r"(a[2]), "r"(a[3]), "r"(b0), "r"(b1));
}

// ---------------- GroupNorm (+weight convert) fused launch ------------------
// blocks [0, 1024): GroupNorm (b,g). blocks [1024, 2048): weight fp32->fp16.
__global__ __launch_bounds__(256) void gn_cvt_kernel(
    const float* __restrict__ x, const float* __restrict__ gw,
    const float* __restrict__ gb, __half* __restrict__ xnh,
    const float* __restrict__ qkvw, const float* __restrict__ projw,
    __half* __restrict__ wh)
{
    const int bid = blockIdx.x;
    const int tid = threadIdx.x;

    if (bid >= BATCH * GROUPS) {
        // weight convert: 1024 blocks x 256 thr x 4 elems (float4 -> 2x half2)
        const int i4 = (bid - BATCH * GROUPS) * 256 + tid;   // float4 index
        const int n_qkv4 = 3 * C * C / 4;                    // 196608
        float4 v;
        if (i4 < n_qkv4) v = ((const float4*)qkvw)[i4];
        else             v = ((const float4*)projw)[i4 - n_qkv4];
        __half2* o = (__half2*)(wh + (size_t)i4 * 4);
        o[0] = __floats2half2_rn(v.x, v.y);
        o[1] = __floats2half2_rn(v.z, v.w);
        return;
    }

    const int b = bid / GROUPS;
    const int g = bid % GROUPS;
    const size_t base = ((size_t)b * C + (size_t)g * CPG) * L;
    const float4* px4 = (const float4*)(x + base);
    __half2* outh = (__half2*)(xnh + base);
    const int n4 = CPG * L / 4;

    float s = 0.f, ss = 0.f;
    for (int i = tid; i < n4; i += 256) {
        float4 v = px4[i];
        s  += v.x + v.y + v.z + v.w;
        ss += v.x*v.x + v.y*v.y + v.z*v.z + v.w*v.w;
    }
    __shared__ float sh_s[32], sh_ss[32];
    for (int o = 16; o > 0; o >>= 1) {
        s  += __shfl_down_sync(0xffffffff, s, o);
        ss += __shfl_down_sync(0xffffffff, ss, o);
    }
    if ((tid & 31) == 0) { sh_s[tid >> 5] = s; sh_ss[tid >> 5] = ss; }
    __syncthreads();
    if (tid < 32) {
        s  = (tid < 8) ? sh_s[tid]  : 0.f;
        ss = (tid < 8) ? sh_ss[tid] : 0.f;
        for (int o = 4; o > 0; o >>= 1) {
            s  += __shfl_down_sync(0xffffffff, s, o);
            ss += __shfl_down_sync(0xffffffff, ss, o);
        }
        if (tid == 0) { sh_s[0] = s; sh_ss[0] = ss; }
    }
    __syncthreads();
    const float inv_n = 1.f / (float)(CPG * L);
    const float mean  = sh_s[0] * inv_n;
    const float var   = sh_ss[0] * inv_n - mean * mean;
    const float rstd  = rsqrtf(var + EPS);

    for (int i = tid; i < n4; i += 256) {
        const int ch = g * CPG + (i >> 10);
        const float w = gw[ch] * rstd;
        const float bb = gb[ch] - mean * w;
        float4 v = px4[i];
        outh[i * 2 + 0] = __floats2half2_rn(fmaf(v.x, w, bb), fmaf(v.y, w, bb));
        outh[i * 2 + 1] = __floats2half2_rn(fmaf(v.z, w, bb), fmaf(v.w, w, bb));
    }
}

// ---------------- Row softmax (fp16 in, fp16 out) ---------------------------
__global__ __launch_bounds__(128) void softmax512_kernel(
    const __half* __restrict__ logits, __half* __restrict__ attn)
{
    const size_t row = blockIdx.x;
    const __half2* p = (const __half2*)(logits + row * C);
    const int tid = threadIdx.x;

    float2 a = __half22float2(p[tid * 2 + 0]);
    float2 b = __half22float2(p[tid * 2 + 1]);
    float m = fmaxf(fmaxf(a.x, a.y), fmaxf(b.x, b.y));
    __shared__ float sh[4];
    for (int o = 16; o > 0; o >>= 1) m = fmaxf(m, __shfl_xor_sync(0xffffffff, m, o));
    if ((tid & 31) == 0) sh[tid >> 5] = m;
    __syncthreads();
    m = fmaxf(fmaxf(sh[0], sh[1]), fmaxf(sh[2], sh[3]));

    a.x = expf(a.x - m); a.y = expf(a.y - m);
    b.x = expf(b.x - m); b.y = expf(b.y - m);
    float s = a.x + a.y + b.x + b.y;
    for (int o = 16; o > 0; o >>= 1) s += __shfl_xor_sync(0xffffffff, s, o);
    __shared__ float shs[4];
    if ((tid & 31) == 0) shs[tid >> 5] = s;
    __syncthreads();
    s = shs[0] + shs[1] + shs[2] + shs[3];
    const float inv = 1.f / s;

    __half2* o2 = (__half2*)(attn + row * C);
    o2[tid * 2 + 0] = __floats2half2_rn(a.x * inv, a.y * inv);
    o2[tid * 2 + 1] = __floats2half2_rn(b.x * inv, b.y * inv);
}

// ---------------- fp16 tensor-core GEMM core --------------------------------
// D[M,N] = alpha * A[M,K] * B (+bias) (+res fp16).
//   A: [M,K] row-major. B_TRANS=false: B [N,K] rm. B_TRANS=true: B [K,N] rm.
// CTA tile 128x128, BK=64, 128 threads = 4 warps (2m x 2n), warp tile 64x64.
#define STAGE_BYTES 32768          // A 16KB + B 16KB
#define GEMM_SMEM  (3 * STAGE_BYTES)

__device__ __forceinline__ void load_A(const __half* __restrict__ gA, int lda,
                                       uint32_t st, int tid)
{
    #pragma unroll
    for (int j = 0; j < 8; j++) {
        const int slot = tid + 128 * j;
        const int row  = slot >> 3;
        const int c    = slot & 7;
        const uint32_t off = (uint32_t)row * 128u + (uint32_t)((c ^ (row & 7)) << 4);
        CP_ASYNC16(st + off, gA + (size_t)row * lda + c * 8);
    }
}
__device__ __forceinline__ void load_B_nt(const __half* __restrict__ gB, int ldb,
                                          uint32_t st, int tid)
{
    #pragma unroll
    for (int j = 0; j < 8; j++) {
        const int slot = tid + 128 * j;
        const int row  = slot >> 3;
        const int c    = slot & 7;
        const uint32_t off = (uint32_t)row * 128u + (uint32_t)((c ^ (row & 7)) << 4);
        CP_ASYNC16(st + off, gB + (size_t)row * ldb + c * 8);
    }
}
__device__ __forceinline__ void load_B_t(const __half* __restrict__ gB, int ldb,
                                         uint32_t st, int tid)
{
    #pragma unroll
    for (int j = 0; j < 8; j++) {
        const int slot = tid + 128 * j;
        const int row  = slot >> 4;           // 0..63 (k)
        const int c    = slot & 15;           // 16B chunk (n/8)
        const uint32_t off = (uint32_t)((row * 2 + (c >> 3)) * 128)
                           + (uint32_t)(((c & 7) ^ (row & 7)) << 4);
        CP_ASYNC16(st + off, gB + (size_t)row * ldb + c * 8);
    }
}

template<typename OutT, int BIAS_MODE, bool ADD_RES, bool B_TRANS>
__device__ __forceinline__ void gemm_core(
    int bx, int by, int bz, uint32_t sbase,
    const __half* __restrict__ A, long long sA, int lda,
    const __half* __restrict__ B, long long sB, int ldb,
    OutT* __restrict__ D, long long sD, int ldd,
    int K,
    const float* __restrict__ bias,
    const __half* __restrict__ res, long long sRes, int ldres,
    float alpha)
{
    A += (size_t)bz * sA;
    B += (size_t)bz * sB;
    D += (size_t)bz * sD;
    if (ADD_RES) res += (size_t)bz * sRes;

    const int bm = by * 128;
    const int bn = bx * 128;
    const int tid = threadIdx.x;
    const int lane = tid & 31;
    const int wid = tid >> 5;
    const int wm = wid & 1;
    const int wn = wid >> 1;

    const __half* gA = A + (size_t)bm * lda;
    const __half* gB = B_TRANS ? (B + bn) : (B + (size_t)bn * ldb);
    const int T = K >> 6;

    const int a_row_lo = lane & 15;
    const int a_sel    = lane >> 4;
    const int b_row_lo = (lane & 7) + ((lane >> 4) << 3);
    const int b_sel    = (lane >> 3) & 1;
    const int bt_k_lo  = lane & 15;
    const int bt_n8    = (lane >> 4) << 3;

    float acc[4][8][4];
    #pragma unroll
    for (int i = 0; i < 4; i++)
        #pragma unroll
        for (int j = 0; j < 8; j++)
            #pragma unroll
            for (int q = 0; q < 4; q++) acc[i][j][q] = 0.f;

    #pragma unroll
    for (int s = 0; s < 2; s++) {
        const uint32_t st = sbase + s * STAGE_BYTES;
        load_A(gA + s * 64, lda, st, tid);
        if (B_TRANS) load_B_t(gB + (size_t)(s * 64) * ldb, ldb, st + 16384, tid);
        else         load_B_nt(gB + s * 64, ldb, st + 16384, tid);
        CP_COMMIT();
    }

    for (int t = 0; t < T; t++) {
        if (t < T - 1) CP_WAIT1(); else CP_WAIT0();
        __syncthreads();

        if (t + 2 < T) {
            const int s = t + 2;
            const uint32_t st = sbase + (s % 3) * STAGE_BYTES;
            load_A(gA + s * 64, lda, st, tid);
            if (B_TRANS) load_B_t(gB + (size_t)(s * 64) * ldb, ldb, st + 16384, tid);
            else         load_B_nt(gB + s * 64, ldb, st + 16384, tid);
            CP_COMMIT();
        }

        const uint32_t stA = sbase + (t % 3) * STAGE_BYTES;
        const uint32_t stB = stA + 16384;

        #pragma unroll
        for (int ks = 0; ks < 4; ks++) {
            uint32_t aF[4][4];
            uint32_t bF[4][4];
            #pragma unroll
            for (int mi = 0; mi < 4; mi++) {
                const int row = wm * 64 + mi * 16 + a_row_lo;
                const int ch  = ks * 2 + a_sel;
                ldsm_x4(aF[mi], stA + (uint32_t)row * 128u + (uint32_t)((ch ^ (row & 7)) << 4));
            }
            if (B_TRANS) {
                const int krow = ks * 16 + bt_k_lo;
                #pragma unroll
                for (int nb = 0; nb < 4; nb++) {
                    const int n = wn * 64 + nb * 16 + bt_n8;
                    const uint32_t addr = stB
                        + (uint32_t)((krow * 2 + (n >> 6)) * 128)
                        + (uint32_t)((((n >> 3) & 7) ^ (krow & 7)) << 4);
                    ldsm_x4_t(bF[nb], addr);
                }
            } else {
                #pragma unroll
                for (int nb = 0; nb < 4; nb++) {
                    const int row = wn * 64 + nb * 16 + b_row_lo;
                    const int ch  = ks * 2 + b_sel;
                    ldsm_x4(bF[nb], stB + (uint32_t)row * 128u + (uint32_t)((ch ^ (row & 7)) << 4));
                }
            }
            #pragma unroll
            for (int mi = 0; mi < 4; mi++)
                #pragma unroll
                for (int nj = 0; nj < 8; nj++)
                    mma16816(acc[mi][nj], aF[mi],
                             bF[nj >> 1][(nj & 1) * 2], bF[nj >> 1][(nj & 1) * 2 + 1]);
        }
    }

    const int m0 = bm + wm * 64;
    const int n0 = bn + wn * 64;
    #pragma unroll
    for (int mi = 0; mi < 4; mi++) {
        const int r0 = m0 + mi * 16 + (lane >> 2);
        const int r1 = r0 + 8;
        float br0 = 0.f, br1 = 0.f;
        if (BIAS_MODE == 1) { br0 = bias[r0]; br1 = bias[r1]; }
        #pragma unroll
        for (int nj = 0; nj < 8; nj++) {
            const int c0 = n0 + nj * 8 + (lane & 3) * 2;
            float v0 = acc[mi][nj][0] * alpha;
            float v1 = acc[mi][nj][1] * alpha;
            float v2 = acc[mi][nj][2] * alpha;
            float v3 = acc[mi][nj][3] * alpha;
            if (BIAS_MODE == 1) { v0 += br0; v1 += br0; v2 += br1; v3 += br1; }
            if (ADD_RES) {
                const float2 q0 = __half22float2(*(const __half2*)&res[(size_t)r0 * ldres + c0]);
                const float2 q1 = __half22float2(*(const __half2*)&res[(size_t)r1 * ldres + c0]);
                v0 += q0.x; v1 += q0.y; v2 += q1.x; v3 += q1.y;
            }
            if constexpr (sizeof(OutT) == 2) {
                *reinterpret_cast<__half2*>(&D[(size_t)r0 * ldd + c0]) = __floats2half2_rn(v0, v1);
                *reinterpret_cast<__half2*>(&D[(size_t)r1 * ldd + c0]) = __floats2half2_rn(v2, v3);
            } else {
                *reinterpret_cast<float2*>(&D[(size_t)r0 * ldd + c0]) = make_float2(v0, v1);
                *reinterpret_cast<float2*>(&D[(size_t)r1 * ldd + c0]) = make_float2(v2, v3);
            }
        }
    }
}

// ---------------- plain GEMM wrapper ----------------------------------------
template<typename OutT, int BIAS_MODE, bool ADD_RES, bool B_TRANS>
__global__ __launch_bounds__(128, 2) void hgemm_kernel(
    const __half* __restrict__ A, long long sA, int lda,
    const __half* __restrict__ B, long long sB, int ldb,
    OutT* __restrict__ D, long long sD, int ldd,
    int K,
    const float* __restrict__ bias,
    const __half* __restrict__ res, long long sRes, int ldres,
    float alpha)
{
    extern __shared__ __align__(128) char smem[];
    gemm_core<OutT, BIAS_MODE, ADD_RES, B_TRANS>(
        blockIdx.x, blockIdx.y, blockIdx.z, smem_u32(smem),
        A, sA, lda, B, sB, ldb, D, sD, ldd, K, bias, res, sRes, ldres, alpha);
}

// ---------------- fused logits + V-projection launch ------------------------
// blocks [0,512): logits tiles (x=id&3, y=(id>>2)&3, z=id>>4)
// blocks [512, 512+4096): V-proj tiles (x=id&31, y=(id>>5)&3, z=id>>7)
__global__ __launch_bounds__(128, 2) void fused_lv_kernel(
    const __half* __restrict__ qkv, __half* __restrict__ logits,
    const __half* __restrict__ wv,  const float* __restrict__ vb,
    const __half* __restrict__ xnh, __half* __restrict__ vout)
{
    extern __shared__ __align__(128) char smem[];
    const uint32_t sbase = smem_u32(smem);
    const long long sQKV = (long long)3 * C * L;
    const long long sXN  = (long long)C * L;
    const long long sATT = (long long)C * C;

    int id = blockIdx.x;
    if (id < 512) {
        // logits[q,k] = Q[q,:]·K[k,:] / 64, NT, K=L
        gemm_core<__half, 0, false, false>(
            id & 3, (id >> 2) & 3, id >> 4, sbase,
            qkv, sQKV, L, qkv + (size_t)C * L, sQKV, L,
            logits, sATT, C, L, nullptr, nullptr, 0LL, 0, 0.015625f);
    } else {
        id -= 512;
        // V[o,l] = Wv[o,:]·xnh[:,l] + vb[o], trans-B, K=C
        gemm_core<__half, 1, false, true>(
            id & 31, (id >> 5) & 3, id >> 7, sbase,
            wv, 0LL, C, xnh, sXN, L,
            vout, sQKV, L, C, vb, nullptr, 0LL, 0, 1.0f);
    }
}

// ---------------------------------------------------------------------------
extern "C" void kernel_launch(void* const* d_in, const int* in_sizes, int n_in,
                              void* d_out, int out_size)
{
    const float* x      = (const float*)d_in[0];
    const float* gn_w   = (const float*)d_in[1];
    const float* gn_b   = (const float*)d_in[2];
    const float* qkv_w  = (const float*)d_in[3];
    const float* qkv_b  = (const float*)d_in[4];
    const float* proj_w = (const float*)d_in[5];
    const float* proj_b = (const float*)d_in[6];
    float* out = (float*)d_out;

    __half *xnh, *qkv, *logits, *attn, *ret, *wh;
    cudaGetSymbolAddress((void**)&xnh,    g_xnh);
    cudaGetSymbolAddress((void**)&qkv,    g_qkv);
    cudaGetSymbolAddress((void**)&logits, g_logits);
    cudaGetSymbolAddress((void**)&attn,   g_attn);
    cudaGetSymbolAddress((void**)&ret,    g_ret);
    cudaGetSymbolAddress((void**)&wh,     g_wh);

    cudaFuncSetAttribute(hgemm_kernel<__half, 1, false, true>,  cudaFuncAttributeMaxDynamicSharedMemorySize, GEMM_SMEM);
    cudaFuncSetAttribute(hgemm_kernel<__half, 0, false, true>,  cudaFuncAttributeMaxDynamicSharedMemorySize, GEMM_SMEM);
    cudaFuncSetAttribute(hgemm_kernel<float,  1, true,  true>,  cudaFuncAttributeMaxDynamicSharedMemorySize, GEMM_SMEM);
    cudaFuncSetAttribute(fused_lv_kernel, cudaFuncAttributeMaxDynamicSharedMemorySize, GEMM_SMEM);

    const long long sXN  = (long long)C * L;
    const long long sQKV = (long long)3 * C * L;
    const long long sATT = (long long)C * C;

    // 1) GroupNorm -> xnh fp16 [C,L]  (+ weight convert, fused launch)
    gn_cvt_kernel<<<BATCH * GROUPS + 1024, 256>>>(
        x, gn_w, gn_b, xnh, qkv_w, proj_w, wh);

    // 2) QK only: qkv[o,l] = Wqk[o,:]·xnh[:,l] + b[o]  (M=1024,N=4096,K=512)
    {
        dim3 grid(L / 128, 1024 / 128, BATCH);
        hgemm_kernel<__half, 1, false, true><<<grid, 128, GEMM_SMEM>>>(
            wh, 0LL, C, xnh, sXN, L, qkv, sQKV, L, C,
            qkv_b, nullptr, 0LL, 0, 1.0f);
    }
    // 3) fused: logits (Q·K^T/64) + V projection (concurrent, independent)
    fused_lv_kernel<<<512 + 4096, 128, GEMM_SMEM>>>(
        qkv, logits,
        wh + (size_t)1024 * C, qkv_b + 1024,
        xnh, qkv + (size_t)2 * C * L);

    // 4) softmax -> attn fp16
    softmax512_kernel<<<BATCH * C, 128>>>(logits, attn);

    // 5) ret[q,l] = attn[q,:]·V[:,l]   (M=512,N=4096,K=512), trans-B
    {
        dim3 grid(L / 128, C / 128, BATCH);
        hgemm_kernel<__half, 0, false, true><<<grid, 128, GEMM_SMEM>>>(
            attn, sATT, C, qkv + (size_t)2 * C * L, sQKV, L, ret, sXN, L, C,
            nullptr, nullptr, 0LL, 0, 1.0f);
    }
    // 6) out[o,l] = P[o,:]·ret[:,l] + proj_b[o] + xnh[o,l]  (M=512,N=4096,K=512)
    {
        dim3 grid(L / 128, C / 128, BATCH);
        hgemm_kernel<float, 1, true, true><<<grid, 128, GEMM_SMEM>>>(
            wh + (size_t)3 * C * C, 0LL, C, ret, sXN, L, out, sXN, L, C,
            proj_b, xnh, sXN, L, 1.0f);
    }
}

// round 9
// speedup vs baseline: 9.3514x; 1.1425x over previous
#include <cuda_runtime.h>
#include <cuda_fp16.h>
#include <cstdint>
#include <math.h>

#define BATCH 32
#define C 512
#define L 4096
#define GROUPS 32
#define CPG 16
#define EPS 1e-5f

// ---------------- scratch (device globals; allocation-free rule) -----------
__device__ __align__(256) __half g_xnh   [(size_t)BATCH * C * L];        // [C,L] normed
__device__ __align__(256) __half g_qkv   [(size_t)BATCH * 3 * C * L];    // Q 0..511, K 512..1023, V 1024..1535
__device__ __align__(256) __half g_logits[(size_t)BATCH * C * C];
__device__ __align__(256) __half g_attn  [(size_t)BATCH * C * C];
__device__ __align__(256) __half g_pm    [(size_t)BATCH * C * C];        // M = P·attn
__device__ __align__(256) __half g_wh    [(size_t)4 * C * C];            // qkv_w + proj_w

// ---------------- PTX helpers ----------------------------------------------
__device__ __forceinline__ uint32_t smem_u32(const void* p) {
    uint32_t a;
    asm("{ .reg .u64 t; cvta.to.shared.u64 t, %1; cvt.u32.u64 %0, t; }" : "=r"(a) : "l"(p));
    return a;
}
#define CP_ASYNC16(dst, src) \
    asm volatile("cp.async.cg.shared.global [%0], [%1], 16;" :: "r"(dst), "l"(src) : "memory")
#define CP_COMMIT() asm volatile("cp.async.commit_group;" ::: "memory")
#define CP_WAIT1()  asm volatile("cp.async.wait_group 1;" ::: "memory")
#define CP_WAIT0()  asm volatile("cp.async.wait_group 0;" ::: "memory")

__device__ __forceinline__ void ldsm_x4(uint32_t (&r)[4], uint32_t addr) {
    asm volatile("ldmatrix.sync.aligned.m8n8.x4.shared.b16 {%0,%1,%2,%3}, [%4];"
        : "=r"(r[0]), "=r"(r[1]), "=r"(r[2]), "=r"(r[3]) : "r"(addr));
}
__device__ __forceinline__ void ldsm_x4_t(uint32_t (&r)[4], uint32_t addr) {
    asm volatile("ldmatrix.sync.aligned.m8n8.x4.trans.shared.b16 {%0,%1,%2,%3}, [%4];"
        : "=r"(r[0]), "=r"(r[1]), "=r"(r[2]), "=r"(r[3]) : "r"(addr));
}
__device__ __forceinline__ void mma16816(float (&d)[4], const uint32_t (&a)[4],
                                         uint32_t b0, uint32_t b1) {
    asm volatile(
        "mma.sync.aligned.m16n8k16.row.col.f32.f16.f16.f32 "
        "{%0,%1,%2,%3}, {%4,%5,%6,%7}, {%8,%9}, {%0,%1,%2,%3};"
        : "+f"(d[0]), "+f"(d[1]), "+f"(d[2]), "+f"(d[3])
        : "r"(a[0]), "r"(a[1]), "r"(a[2]), "r"(a[3]), "r"(b0), "r"(b1));
}

// ---------------- GroupNorm (+weight convert) fused launch ------------------
__global__ __launch_bounds__(256) void gn_cvt_kernel(
    const float* __restrict__ x, const float* __restrict__ gw,
    const float* __restrict__ gb, __half* __restrict__ xnh,
    const float* __restrict__ qkvw, const float* __restrict__ projw,
    __half* __restrict__ wh)
{
    const int bid = blockIdx.x;
    const int tid = threadIdx.x;

    if (bid >= BATCH * GROUPS) {
        const int i4 = (bid - BATCH * GROUPS) * 256 + tid;
        const int n_qkv4 = 3 * C * C / 4;
        float4 v;
        if (i4 < n_qkv4) v = ((const float4*)qkvw)[i4];
        else             v = ((const float4*)projw)[i4 - n_qkv4];
        __half2* o = (__half2*)(wh + (size_t)i4 * 4);
        o[0] = __floats2half2_rn(v.x, v.y);
        o[1] = __floats2half2_rn(v.z, v.w);
        return;
    }

    const int b = bid / GROUPS;
    const int g = bid % GROUPS;
    const size_t base = ((size_t)b * C + (size_t)g * CPG) * L;
    const float4* px4 = (const float4*)(x + base);
    __half2* outh = (__half2*)(xnh + base);
    const int n4 = CPG * L / 4;

    float s = 0.f, ss = 0.f;
    for (int i = tid; i < n4; i += 256) {
        float4 v = px4[i];
        s  += v.x + v.y + v.z + v.w;
        ss += v.x*v.x + v.y*v.y + v.z*v.z + v.w*v.w;
    }
    __shared__ float sh_s[32], sh_ss[32];
    for (int o = 16; o > 0; o >>= 1) {
        s  += __shfl_down_sync(0xffffffff, s, o);
        ss += __shfl_down_sync(0xffffffff, ss, o);
    }
    if ((tid & 31) == 0) { sh_s[tid >> 5] = s; sh_ss[tid >> 5] = ss; }
    __syncthreads();
    if (tid < 32) {
        s  = (tid < 8) ? sh_s[tid]  : 0.f;
        ss = (tid < 8) ? sh_ss[tid] : 0.f;
        for (int o = 4; o > 0; o >>= 1) {
            s  += __shfl_down_sync(0xffffffff, s, o);
            ss += __shfl_down_sync(0xffffffff, ss, o);
        }
        if (tid == 0) { sh_s[0] = s; sh_ss[0] = ss; }
    }
    __syncthreads();
    const float inv_n = 1.f / (float)(CPG * L);
    const float mean  = sh_s[0] * inv_n;
    const float var   = sh_ss[0] * inv_n - mean * mean;
    const float rstd  = rsqrtf(var + EPS);

    for (int i = tid; i < n4; i += 256) {
        const int ch = g * CPG + (i >> 10);
        const float w = gw[ch] * rstd;
        const float bb = gb[ch] - mean * w;
        float4 v = px4[i];
        outh[i * 2 + 0] = __floats2half2_rn(fmaf(v.x, w, bb), fmaf(v.y, w, bb));
        outh[i * 2 + 1] = __floats2half2_rn(fmaf(v.z, w, bb), fmaf(v.w, w, bb));
    }
}

// ---------------- Row softmax (fp16 in, fp16 out) ---------------------------
__global__ __launch_bounds__(128) void softmax512_kernel(
    const __half* __restrict__ logits, __half* __restrict__ attn)
{
    const size_t row = blockIdx.x;
    const __half2* p = (const __half2*)(logits + row * C);
    const int tid = threadIdx.x;

    float2 a = __half22float2(p[tid * 2 + 0]);
    float2 b = __half22float2(p[tid * 2 + 1]);
    float m = fmaxf(fmaxf(a.x, a.y), fmaxf(b.x, b.y));
    __shared__ float sh[4];
    for (int o = 16; o > 0; o >>= 1) m = fmaxf(m, __shfl_xor_sync(0xffffffff, m, o));
    if ((tid & 31) == 0) sh[tid >> 5] = m;
    __syncthreads();
    m = fmaxf(fmaxf(sh[0], sh[1]), fmaxf(sh[2], sh[3]));

    a.x = expf(a.x - m); a.y = expf(a.y - m);
    b.x = expf(b.x - m); b.y = expf(b.y - m);
    float s = a.x + a.y + b.x + b.y;
    for (int o = 16; o > 0; o >>= 1) s += __shfl_xor_sync(0xffffffff, s, o);
    __shared__ float shs[4];
    if ((tid & 31) == 0) shs[tid >> 5] = s;
    __syncthreads();
    s = shs[0] + shs[1] + shs[2] + shs[3];
    const float inv = 1.f / s;

    __half2* o2 = (__half2*)(attn + row * C);
    o2[tid * 2 + 0] = __floats2half2_rn(a.x * inv, a.y * inv);
    o2[tid * 2 + 1] = __floats2half2_rn(b.x * inv, b.y * inv);
}

// ---------------- fp16 tensor-core GEMM core --------------------------------
#define STAGE_BYTES 32768          // A 16KB + B 16KB
#define GEMM_SMEM  (3 * STAGE_BYTES)

__device__ __forceinline__ void load_A(const __half* __restrict__ gA, int lda,
                                       uint32_t st, int tid)
{
    #pragma unroll
    for (int j = 0; j < 8; j++) {
        const int slot = tid + 128 * j;
        const int row  = slot >> 3;
        const int c    = slot & 7;
        const uint32_t off = (uint32_t)row * 128u + (uint32_t)((c ^ (row & 7)) << 4);
        CP_ASYNC16(st + off, gA + (size_t)row * lda + c * 8);
    }
}
__device__ __forceinline__ void load_B_nt(const __half* __restrict__ gB, int ldb,
                                          uint32_t st, int tid)
{
    #pragma unroll
    for (int j = 0; j < 8; j++) {
        const int slot = tid + 128 * j;
        const int row  = slot >> 3;
        const int c    = slot & 7;
        const uint32_t off = (uint32_t)row * 128u + (uint32_t)((c ^ (row & 7)) << 4);
        CP_ASYNC16(st + off, gB + (size_t)row * ldb + c * 8);
    }
}
__device__ __forceinline__ void load_B_t(const __half* __restrict__ gB, int ldb,
                                         uint32_t st, int tid)
{
    #pragma unroll
    for (int j = 0; j < 8; j++) {
        const int slot = tid + 128 * j;
        const int row  = slot >> 4;           // 0..63 (k)
        const int c    = slot & 15;           // 16B chunk (n/8)
        const uint32_t off = (uint32_t)((row * 2 + (c >> 3)) * 128)
                           + (uint32_t)(((c & 7) ^ (row & 7)) << 4);
        CP_ASYNC16(st + off, gB + (size_t)row * ldb + c * 8);
    }
}

template<typename OutT, int BIAS_MODE, bool ADD_RES, bool B_TRANS>
__device__ __forceinline__ void gemm_core(
    int bx, int by, int bz, uint32_t sbase,
    const __half* __restrict__ A, long long sA, int lda,
    const __half* __restrict__ B, long long sB, int ldb,
    OutT* __restrict__ D, long long sD, int ldd,
    int K,
    const float* __restrict__ bias,
    const __half* __restrict__ res, long long sRes, int ldres,
    float alpha)
{
    A += (size_t)bz * sA;
    B += (size_t)bz * sB;
    D += (size_t)bz * sD;
    if (ADD_RES) res += (size_t)bz * sRes;

    const int bm = by * 128;
    const int bn = bx * 128;
    const int tid = threadIdx.x;
    const int lane = tid & 31;
    const int wid = tid >> 5;
    const int wm = wid & 1;
    const int wn = wid >> 1;

    const __half* gA = A + (size_t)bm * lda;
    const __half* gB = B_TRANS ? (B + bn) : (B + (size_t)bn * ldb);
    const int T = K >> 6;

    const int a_row_lo = lane & 15;
    const int a_sel    = lane >> 4;
    const int b_row_lo = (lane & 7) + ((lane >> 4) << 3);
    const int b_sel    = (lane >> 3) & 1;
    const int bt_k_lo  = lane & 15;
    const int bt_n8    = (lane >> 4) << 3;

    float acc[4][8][4];
    #pragma unroll
    for (int i = 0; i < 4; i++)
        #pragma unroll
        for (int j = 0; j < 8; j++)
            #pragma unroll
            for (int q = 0; q < 4; q++) acc[i][j][q] = 0.f;

    #pragma unroll
    for (int s = 0; s < 2; s++) {
        const uint32_t st = sbase + s * STAGE_BYTES;
        load_A(gA + s * 64, lda, st, tid);
        if (B_TRANS) load_B_t(gB + (size_t)(s * 64) * ldb, ldb, st + 16384, tid);
        else         load_B_nt(gB + s * 64, ldb, st + 16384, tid);
        CP_COMMIT();
    }

    for (int t = 0; t < T; t++) {
        if (t < T - 1) CP_WAIT1(); else CP_WAIT0();
        __syncthreads();

        if (t + 2 < T) {
            const int s = t + 2;
            const uint32_t st = sbase + (s % 3) * STAGE_BYTES;
            load_A(gA + s * 64, lda, st, tid);
            if (B_TRANS) load_B_t(gB + (size_t)(s * 64) * ldb, ldb, st + 16384, tid);
            else         load_B_nt(gB + s * 64, ldb, st + 16384, tid);
            CP_COMMIT();
        }

        const uint32_t stA = sbase + (t % 3) * STAGE_BYTES;
        const uint32_t stB = stA + 16384;

        #pragma unroll
        for (int ks = 0; ks < 4; ks++) {
            uint32_t aF[4][4];
            uint32_t bF[4][4];
            #pragma unroll
            for (int mi = 0; mi < 4; mi++) {
                const int row = wm * 64 + mi * 16 + a_row_lo;
                const int ch  = ks * 2 + a_sel;
                ldsm_x4(aF[mi], stA + (uint32_t)row * 128u + (uint32_t)((ch ^ (row & 7)) << 4));
            }
            if (B_TRANS) {
                const int krow = ks * 16 + bt_k_lo;
                #pragma unroll
                for (int nb = 0; nb < 4; nb++) {
                    const int n = wn * 64 + nb * 16 + bt_n8;
                    const uint32_t addr = stB
                        + (uint32_t)((krow * 2 + (n >> 6)) * 128)
                        + (uint32_t)((((n >> 3) & 7) ^ (krow & 7)) << 4);
                    ldsm_x4_t(bF[nb], addr);
                }
            } else {
                #pragma unroll
                for (int nb = 0; nb < 4; nb++) {
                    const int row = wn * 64 + nb * 16 + b_row_lo;
                    const int ch  = ks * 2 + b_sel;
                    ldsm_x4(bF[nb], stB + (uint32_t)row * 128u + (uint32_t)((ch ^ (row & 7)) << 4));
                }
            }
            #pragma unroll
            for (int mi = 0; mi < 4; mi++)
                #pragma unroll
                for (int nj = 0; nj < 8; nj++)
                    mma16816(acc[mi][nj], aF[mi],
                             bF[nj >> 1][(nj & 1) * 2], bF[nj >> 1][(nj & 1) * 2 + 1]);
        }
    }

    const int m0 = bm + wm * 64;
    const int n0 = bn + wn * 64;
    #pragma unroll
    for (int mi = 0; mi < 4; mi++) {
        const int r0 = m0 + mi * 16 + (lane >> 2);
        const int r1 = r0 + 8;
        float br0 = 0.f, br1 = 0.f;
        if (BIAS_MODE == 1) { br0 = bias[r0]; br1 = bias[r1]; }
        #pragma unroll
        for (int nj = 0; nj < 8; nj++) {
            const int c0 = n0 + nj * 8 + (lane & 3) * 2;
            float v0 = acc[mi][nj][0] * alpha;
            float v1 = acc[mi][nj][1] * alpha;
            float v2 = acc[mi][nj][2] * alpha;
            float v3 = acc[mi][nj][3] * alpha;
            if (BIAS_MODE == 1) { v0 += br0; v1 += br0; v2 += br1; v3 += br1; }
            if (ADD_RES) {
                const float2 q0 = __half22float2(*(const __half2*)&res[(size_t)r0 * ldres + c0]);
                const float2 q1 = __half22float2(*(const __half2*)&res[(size_t)r1 * ldres + c0]);
                v0 += q0.x; v1 += q0.y; v2 += q1.x; v3 += q1.y;
            }
            if constexpr (sizeof(OutT) == 2) {
                *reinterpret_cast<__half2*>(&D[(size_t)r0 * ldd + c0]) = __floats2half2_rn(v0, v1);
                *reinterpret_cast<__half2*>(&D[(size_t)r1 * ldd + c0]) = __floats2half2_rn(v2, v3);
            } else {
                *reinterpret_cast<float2*>(&D[(size_t)r0 * ldd + c0]) = make_float2(v0, v1);
                *reinterpret_cast<float2*>(&D[(size_t)r1 * ldd + c0]) = make_float2(v2, v3);
            }
        }
    }
}

// ---------------- plain GEMM wrapper ----------------------------------------
template<typename OutT, int BIAS_MODE, bool ADD_RES, bool B_TRANS>
__global__ __launch_bounds__(128, 2) void hgemm_kernel(
    const __half* __restrict__ A, long long sA, int lda,
    const __half* __restrict__ B, long long sB, int ldb,
    OutT* __restrict__ D, long long sD, int ldd,
    int K,
    const float* __restrict__ bias,
    const __half* __restrict__ res, long long sRes, int ldres,
    float alpha)
{
    extern __shared__ __align__(128) char smem[];
    gemm_core<OutT, BIAS_MODE, ADD_RES, B_TRANS>(
        blockIdx.x, blockIdx.y, blockIdx.z, smem_u32(smem),
        A, sA, lda, B, sB, ldb, D, sD, ldd, K, bias, res, sRes, ldres, alpha);
}

// ---------------- fused logits + V-projection launch ------------------------
__global__ __launch_bounds__(128, 2) void fused_lv_kernel(
    const __half* __restrict__ qkv, __half* __restrict__ logits,
    const __half* __restrict__ wv,  const float* __restrict__ vb,
    const __half* __restrict__ xnh, __half* __restrict__ vout)
{
    extern __shared__ __align__(128) char smem[];
    const uint32_t sbase = smem_u32(smem);
    const long long sQKV = (long long)3 * C * L;
    const long long sXN  = (long long)C * L;
    const long long sATT = (long long)C * C;

    int id = blockIdx.x;
    if (id < 512) {
        gemm_core<__half, 0, false, false>(
            id & 3, (id >> 2) & 3, id >> 4, sbase,
            qkv, sQKV, L, qkv + (size_t)C * L, sQKV, L,
            logits, sATT, C, L, nullptr, nullptr, 0LL, 0, 0.015625f);
    } else {
        id -= 512;
        gemm_core<__half, 1, false, true>(
            id & 31, (id >> 5) & 3, id >> 7, sbase,
            wv, 0LL, C, xnh, sXN, L,
            vout, sQKV, L, C, vb, nullptr, 0LL, 0, 1.0f);
    }
}

// ---------------------------------------------------------------------------
extern "C" void kernel_launch(void* const* d_in, const int* in_sizes, int n_in,
                              void* d_out, int out_size)
{
    const float* x      = (const float*)d_in[0];
    const float* gn_w   = (const float*)d_in[1];
    const float* gn_b   = (const float*)d_in[2];
    const float* qkv_w  = (const float*)d_in[3];
    const float* qkv_b  = (const float*)d_in[4];
    const float* proj_w = (const float*)d_in[5];
    const float* proj_b = (const float*)d_in[6];
    float* out = (float*)d_out;

    __half *xnh, *qkv, *logits, *attn, *pm, *wh;
    cudaGetSymbolAddress((void**)&xnh,    g_xnh);
    cudaGetSymbolAddress((void**)&qkv,    g_qkv);
    cudaGetSymbolAddress((void**)&logits, g_logits);
    cudaGetSymbolAddress((void**)&attn,   g_attn);
    cudaGetSymbolAddress((void**)&pm,     g_pm);
    cudaGetSymbolAddress((void**)&wh,     g_wh);

    cudaFuncSetAttribute(hgemm_kernel<__half, 1, false, true>,  cudaFuncAttributeMaxDynamicSharedMemorySize, GEMM_SMEM);
    cudaFuncSetAttribute(hgemm_kernel<__half, 0, false, true>,  cudaFuncAttributeMaxDynamicSharedMemorySize, GEMM_SMEM);
    cudaFuncSetAttribute(hgemm_kernel<float,  1, true,  true>,  cudaFuncAttributeMaxDynamicSharedMemorySize, GEMM_SMEM);
    cudaFuncSetAttribute(fused_lv_kernel, cudaFuncAttributeMaxDynamicSharedMemorySize, GEMM_SMEM);

    const long long sXN  = (long long)C * L;
    const long long sQKV = (long long)3 * C * L;
    const long long sATT = (long long)C * C;

    // 1) GroupNorm -> xnh fp16 [C,L]  (+ weight convert, fused launch)
    gn_cvt_kernel<<<BATCH * GROUPS + 1024, 256>>>(
        x, gn_w, gn_b, xnh, qkv_w, proj_w, wh);

    // 2) QK: qkv[o,l] = Wqk[o,:]·xnh[:,l] + b[o]  (M=1024,N=4096,K=512)
    {
        dim3 grid(L / 128, 1024 / 128, BATCH);
        hgemm_kernel<__half, 1, false, true><<<grid, 128, GEMM_SMEM>>>(
            wh, 0LL, C, xnh, sXN, L, qkv, sQKV, L, C,
            qkv_b, nullptr, 0LL, 0, 1.0f);
    }
    // 3) fused: logits (Q·K^T/64) + V projection (concurrent, independent)
    fused_lv_kernel<<<512 + 4096, 128, GEMM_SMEM>>>(
        qkv, logits,
        wh + (size_t)1024 * C, qkv_b + 1024,
        xnh, qkv + (size_t)2 * C * L);

    // 4) softmax -> attn fp16
    softmax512_kernel<<<BATCH * C, 128>>>(logits, attn);

    // 5) M[o,k] = Σ_q P[o,q]·attn[q,k]  (trans-B, M=512,N=512,K=512)
    //    attn is [q,k] row-major = [K,N] rm -> B_TRANS path, ldb=C.
    {
        dim3 grid(C / 128, C / 128, BATCH);
        hgemm_kernel<__half, 0, false, true><<<grid, 128, GEMM_SMEM>>>(
            wh + (size_t)3 * C * C, 0LL, C, attn, sATT, C, pm, sATT, C, C,
            nullptr, nullptr, 0LL, 0, 1.0f);
    }
    // 6) out[o,l] = M[o,:]·V[:,l] + proj_b[o] + xnh[o,l]  (M=512,N=4096,K=512)
    {
        dim3 grid(L / 128, C / 128, BATCH);
        hgemm_kernel<float, 1, true, true><<<grid, 128, GEMM_SMEM>>>(
            pm, sATT, C, qkv + (size_t)2 * C * L, sQKV, L, out, sXN, L, C,
            proj_b, xnh, sXN, L, 1.0f);
    }
}

// round 10
// speedup vs baseline: 12.8751x; 1.3768x over previous
#include <cuda_runtime.h>
#include <cuda_fp16.h>
#include <cstdint>
#include <math.h>

#define BATCH 32
#define C 512
#define L 4096
#define GROUPS 32
#define CPG 16
#define EPS 1e-5f

// ---------------- scratch (device globals; allocation-free rule) -----------
__device__ __align__(256) __half g_xnh   [(size_t)BATCH * C * L];   // [C,L] normed
__device__ __align__(256) __half g_v     [(size_t)BATCH * C * L];   // V [C,L]
__device__ __align__(256) __half g_gram  [(size_t)BATCH * C * C];   // G = xn·xn^T
__device__ __align__(256) __half g_t1    [(size_t)BATCH * C * C];   // Wq·G
__device__ __align__(256) __half g_logits[(size_t)BATCH * C * C];
__device__ __align__(256) __half g_attn  [(size_t)BATCH * C * C];
__device__ __align__(256) __half g_pm    [(size_t)BATCH * C * C];   // M = P·attn
__device__ __align__(256) __half g_wh    [(size_t)4 * C * C];       // qkv_w + proj_w (fp16)
__device__ __align__(256) float  g_s     [(size_t)BATCH * C];       // row sums of xn
__device__ __align__(256) float  g_uv    [(size_t)BATCH * 1024];    // [v=Wq·s | u=Wk·s+L·bk]

// ---------------- PTX helpers ----------------------------------------------
__device__ __forceinline__ uint32_t smem_u32(const void* p) {
    uint32_t a;
    asm("{ .reg .u64 t; cvta.to.shared.u64 t, %1; cvt.u32.u64 %0, t; }" : "=r"(a) : "l"(p));
    return a;
}
#define CP_ASYNC16(dst, src) \
    asm volatile("cp.async.cg.shared.global [%0], [%1], 16;" :: "r"(dst), "l"(src) : "memory")
#define CP_COMMIT() asm volatile("cp.async.commit_group;" ::: "memory")
#define CP_WAIT1()  asm volatile("cp.async.wait_group 1;" ::: "memory")
#define CP_WAIT0()  asm volatile("cp.async.wait_group 0;" ::: "memory")

__device__ __forceinline__ void ldsm_x4(uint32_t (&r)[4], uint32_t addr) {
    asm volatile("ldmatrix.sync.aligned.m8n8.x4.shared.b16 {%0,%1,%2,%3}, [%4];"
        : "=r"(r[0]), "=r"(r[1]), "=r"(r[2]), "=r"(r[3]) : "r"(addr));
}
__device__ __forceinline__ void ldsm_x4_t(uint32_t (&r)[4], uint32_t addr) {
    asm volatile("ldmatrix.sync.aligned.m8n8.x4.trans.shared.b16 {%0,%1,%2,%3}, [%4];"
        : "=r"(r[0]), "=r"(r[1]), "=r"(r[2]), "=r"(r[3]) : "r"(addr));
}
__device__ __forceinline__ void mma16816(float (&d)[4], const uint32_t (&a)[4],
                                         uint32_t b0, uint32_t b1) {
    asm volatile(
        "mma.sync.aligned.m16n8k16.row.col.f32.f16.f16.f32 "
        "{%0,%1,%2,%3}, {%4,%5,%6,%7}, {%8,%9}, {%0,%1,%2,%3};"
        : "+f"(d[0]), "+f"(d[1]), "+f"(d[2]), "+f"(d[3])
        : "r"(a[0]), "r"(a[1]), "r"(a[2]), "r"(a[3]), "r"(b0), "r"(b1));
}

// ---------------- GroupNorm (+weight convert, +row sums) fused launch -------
__global__ __launch_bounds__(256) void gn_cvt_kernel(
    const float* __restrict__ x, const float* __restrict__ gw,
    const float* __restrict__ gb, __half* __restrict__ xnh,
    const float* __restrict__ qkvw, const float* __restrict__ projw,
    __half* __restrict__ wh, float* __restrict__ srow)
{
    const int bid = blockIdx.x;
    const int tid = threadIdx.x;

    if (bid >= BATCH * GROUPS) {
        const int i4 = (bid - BATCH * GROUPS) * 256 + tid;
        const int n_qkv4 = 3 * C * C / 4;
        float4 v;
        if (i4 < n_qkv4) v = ((const float4*)qkvw)[i4];
        else             v = ((const float4*)projw)[i4 - n_qkv4];
        __half2* o = (__half2*)(wh + (size_t)i4 * 4);
        o[0] = __floats2half2_rn(v.x, v.y);
        o[1] = __floats2half2_rn(v.z, v.w);
        return;
    }

    const int b = bid / GROUPS;
    const int g = bid % GROUPS;
    const size_t base = ((size_t)b * C + (size_t)g * CPG) * L;
    const float4* px4 = (const float4*)(x + base);
    __half2* outh = (__half2*)(xnh + base);
    const int n4 = CPG * L / 4;

    float s = 0.f, ss = 0.f;
    for (int i = tid; i < n4; i += 256) {
        float4 v = px4[i];
        s  += v.x + v.y + v.z + v.w;
        ss += v.x*v.x + v.y*v.y + v.z*v.z + v.w*v.w;
    }
    __shared__ float sh_s[32], sh_ss[32];
    for (int o = 16; o > 0; o >>= 1) {
        s  += __shfl_down_sync(0xffffffff, s, o);
        ss += __shfl_down_sync(0xffffffff, ss, o);
    }
    if ((tid & 31) == 0) { sh_s[tid >> 5] = s; sh_ss[tid >> 5] = ss; }
    __syncthreads();
    if (tid < 32) {
        s  = (tid < 8) ? sh_s[tid]  : 0.f;
        ss = (tid < 8) ? sh_ss[tid] : 0.f;
        for (int o = 4; o > 0; o >>= 1) {
            s  += __shfl_down_sync(0xffffffff, s, o);
            ss += __shfl_down_sync(0xffffffff, ss, o);
        }
        if (tid == 0) { sh_s[0] = s; sh_ss[0] = ss; }
    }
    __syncthreads();
    const float inv_n = 1.f / (float)(CPG * L);
    const float mean  = sh_s[0] * inv_n;
    const float var   = sh_ss[0] * inv_n - mean * mean;
    const float rstd  = rsqrtf(var + EPS);

    // per-channel row sums while writing (ch = j>>2 for this thread layout)
    float csum[16];
    #pragma unroll
    for (int c = 0; c < 16; c++) csum[c] = 0.f;

    for (int j = 0; j < 64; j++) {
        const int i = tid + 256 * j;
        const int ch = j >> 2;                    // exact: (tid+256j)>>10 == j>>2
        const float w = gw[g * CPG + ch] * rstd;
        const float bb = gb[g * CPG + ch] - mean * w;
        float4 v = px4[i];
        const float e0 = fmaf(v.x, w, bb), e1 = fmaf(v.y, w, bb);
        const float e2 = fmaf(v.z, w, bb), e3 = fmaf(v.w, w, bb);
        outh[i * 2 + 0] = __floats2half2_rn(e0, e1);
        outh[i * 2 + 1] = __floats2half2_rn(e2, e3);
        csum[ch] += (e0 + e1) + (e2 + e3);
    }
    __shared__ float s_part[16][8];
    #pragma unroll
    for (int c = 0; c < 16; c++) {
        float t = csum[c];
        for (int o = 16; o > 0; o >>= 1) t += __shfl_down_sync(0xffffffff, t, o);
        if ((tid & 31) == 0) s_part[c][tid >> 5] = t;
    }
    __syncthreads();
    if (tid < 16) {
        float t = 0.f;
        #pragma unroll
        for (int w8 = 0; w8 < 8; w8++) t += s_part[tid][w8];
        srow[b * C + g * CPG + tid] = t;
    }
}

// ---------------- Row softmax (fp16 in, fp16 out) ---------------------------
__global__ __launch_bounds__(128) void softmax512_kernel(
    const __half* __restrict__ logits, __half* __restrict__ attn)
{
    const size_t row = blockIdx.x;
    const __half2* p = (const __half2*)(logits + row * C);
    const int tid = threadIdx.x;

    float2 a = __half22float2(p[tid * 2 + 0]);
    float2 b = __half22float2(p[tid * 2 + 1]);
    float m = fmaxf(fmaxf(a.x, a.y), fmaxf(b.x, b.y));
    __shared__ float sh[4];
    for (int o = 16; o > 0; o >>= 1) m = fmaxf(m, __shfl_xor_sync(0xffffffff, m, o));
    if ((tid & 31) == 0) sh[tid >> 5] = m;
    __syncthreads();
    m = fmaxf(fmaxf(sh[0], sh[1]), fmaxf(sh[2], sh[3]));

    a.x = expf(a.x - m); a.y = expf(a.y - m);
    b.x = expf(b.x - m); b.y = expf(b.y - m);
    float s = a.x + a.y + b.x + b.y;
    for (int o = 16; o > 0; o >>= 1) s += __shfl_xor_sync(0xffffffff, s, o);
    __shared__ float shs[4];
    if ((tid & 31) == 0) shs[tid >> 5] = s;
    __syncthreads();
    s = shs[0] + shs[1] + shs[2] + shs[3];
    const float inv = 1.f / s;

    __half2* o2 = (__half2*)(attn + row * C);
    o2[tid * 2 + 0] = __floats2half2_rn(a.x * inv, a.y * inv);
    o2[tid * 2 + 1] = __floats2half2_rn(b.x * inv, b.y * inv);
}

// ---------------- fp16 tensor-core GEMM core --------------------------------
// BIAS_MODE: 0 none, 1 row bias, 3 rank-1 logits epilogue
//   (mode 3: out = alpha*(acc + uv[r]*bias[512+c] + bias[r]*uv[512+c]))
#define STAGE_BYTES 32768          // A 16KB + B 16KB
#define GEMM_SMEM  (3 * STAGE_BYTES)

__device__ __forceinline__ void load_A(const __half* __restrict__ gA, int lda,
                                       uint32_t st, int tid)
{
    #pragma unroll
    for (int j = 0; j < 8; j++) {
        const int slot = tid + 128 * j;
        const int row  = slot >> 3;
        const int c    = slot & 7;
        const uint32_t off = (uint32_t)row * 128u + (uint32_t)((c ^ (row & 7)) << 4);
        CP_ASYNC16(st + off, gA + (size_t)row * lda + c * 8);
    }
}
__device__ __forceinline__ void load_B_nt(const __half* __restrict__ gB, int ldb,
                                          uint32_t st, int tid)
{
    #pragma unroll
    for (int j = 0; j < 8; j++) {
        const int slot = tid + 128 * j;
        const int row  = slot >> 3;
        const int c    = slot & 7;
        const uint32_t off = (uint32_t)row * 128u + (uint32_t)((c ^ (row & 7)) << 4);
        CP_ASYNC16(st + off, gB + (size_t)row * ldb + c * 8);
    }
}
__device__ __forceinline__ void load_B_t(const __half* __restrict__ gB, int ldb,
                                         uint32_t st, int tid)
{
    #pragma unroll
    for (int j = 0; j < 8; j++) {
        const int slot = tid + 128 * j;
        const int row  = slot >> 4;           // 0..63 (k)
        const int c    = slot & 15;           // 16B chunk (n/8)
        const uint32_t off = (uint32_t)((row * 2 + (c >> 3)) * 128)
                           + (uint32_t)(((c & 7) ^ (row & 7)) << 4);
        CP_ASYNC16(st + off, gB + (size_t)row * ldb + c * 8);
    }
}

template<typename OutT, int BIAS_MODE, bool ADD_RES, bool B_TRANS>
__device__ __forceinline__ void gemm_core(
    int bx, int by, int bz, uint32_t sbase,
    const __half* __restrict__ A, long long sA, int lda,
    const __half* __restrict__ B, long long sB, int ldb,
    OutT* __restrict__ D, long long sD, int ldd,
    int K,
    const float* __restrict__ bias,
    const __half* __restrict__ res, long long sRes, int ldres,
    const float* __restrict__ uv,
    float alpha)
{
    A += (size_t)bz * sA;
    B += (size_t)bz * sB;
    D += (size_t)bz * sD;
    if (ADD_RES) res += (size_t)bz * sRes;
    if (BIAS_MODE == 3) uv += (size_t)bz * 1024;

    const int bm = by * 128;
    const int bn = bx * 128;
    const int tid = threadIdx.x;
    const int lane = tid & 31;
    const int wid = tid >> 5;
    const int wm = wid & 1;
    const int wn = wid >> 1;

    const __half* gA = A + (size_t)bm * lda;
    const __half* gB = B_TRANS ? (B + bn) : (B + (size_t)bn * ldb);
    const int T = K >> 6;

    const int a_row_lo = lane & 15;
    const int a_sel    = lane >> 4;
    const int b_row_lo = (lane & 7) + ((lane >> 4) << 3);
    const int b_sel    = (lane >> 3) & 1;
    const int bt_k_lo  = lane & 15;
    const int bt_n8    = (lane >> 4) << 3;

    float acc[4][8][4];
    #pragma unroll
    for (int i = 0; i < 4; i++)
        #pragma unroll
        for (int j = 0; j < 8; j++)
            #pragma unroll
            for (int q = 0; q < 4; q++) acc[i][j][q] = 0.f;

    #pragma unroll
    for (int s = 0; s < 2; s++) {
        const uint32_t st = sbase + s * STAGE_BYTES;
        load_A(gA + s * 64, lda, st, tid);
        if (B_TRANS) load_B_t(gB + (size_t)(s * 64) * ldb, ldb, st + 16384, tid);
        else         load_B_nt(gB + s * 64, ldb, st + 16384, tid);
        CP_COMMIT();
    }

    for (int t = 0; t < T; t++) {
        if (t < T - 1) CP_WAIT1(); else CP_WAIT0();
        __syncthreads();

        if (t + 2 < T) {
            const int s = t + 2;
            const uint32_t st = sbase + (s % 3) * STAGE_BYTES;
            load_A(gA + s * 64, lda, st, tid);
            if (B_TRANS) load_B_t(gB + (size_t)(s * 64) * ldb, ldb, st + 16384, tid);
            else         load_B_nt(gB + s * 64, ldb, st + 16384, tid);
            CP_COMMIT();
        }

        const uint32_t stA = sbase + (t % 3) * STAGE_BYTES;
        const uint32_t stB = stA + 16384;

        #pragma unroll
        for (int ks = 0; ks < 4; ks++) {
            uint32_t aF[4][4];
            uint32_t bF[4][4];
            #pragma unroll
            for (int mi = 0; mi < 4; mi++) {
                const int row = wm * 64 + mi * 16 + a_row_lo;
                const int ch  = ks * 2 + a_sel;
                ldsm_x4(aF[mi], stA + (uint32_t)row * 128u + (uint32_t)((ch ^ (row & 7)) << 4));
            }
            if (B_TRANS) {
                const int krow = ks * 16 + bt_k_lo;
                #pragma unroll
                for (int nb = 0; nb < 4; nb++) {
                    const int n = wn * 64 + nb * 16 + bt_n8;
                    const uint32_t addr = stB
                        + (uint32_t)((krow * 2 + (n >> 6)) * 128)
                        + (uint32_t)((((n >> 3) & 7) ^ (krow & 7)) << 4);
                    ldsm_x4_t(bF[nb], addr);
                }
            } else {
                #pragma unroll
                for (int nb = 0; nb < 4; nb++) {
                    const int row = wn * 64 + nb * 16 + b_row_lo;
                    const int ch  = ks * 2 + b_sel;
                    ldsm_x4(bF[nb], stB + (uint32_t)row * 128u + (uint32_t)((ch ^ (row & 7)) << 4));
                }
            }
            #pragma unroll
            for (int mi = 0; mi < 4; mi++)
                #pragma unroll
                for (int nj = 0; nj < 8; nj++)
                    mma16816(acc[mi][nj], aF[mi],
                             bF[nj >> 1][(nj & 1) * 2], bF[nj >> 1][(nj & 1) * 2 + 1]);
        }
    }

    const int m0 = bm + wm * 64;
    const int n0 = bn + wn * 64;
    #pragma unroll
    for (int mi = 0; mi < 4; mi++) {
        const int r0 = m0 + mi * 16 + (lane >> 2);
        const int r1 = r0 + 8;
        float br0 = 0.f, br1 = 0.f;
        if (BIAS_MODE == 1) { br0 = bias[r0]; br1 = bias[r1]; }
        float bq0 = 0.f, bq1 = 0.f, vv0 = 0.f, vv1 = 0.f;
        if (BIAS_MODE == 3) {
            bq0 = bias[r0]; bq1 = bias[r1];
            vv0 = uv[r0];   vv1 = uv[r1];
        }
        #pragma unroll
        for (int nj = 0; nj < 8; nj++) {
            const int c0 = n0 + nj * 8 + (lane & 3) * 2;
            float v0 = acc[mi][nj][0];
            float v1 = acc[mi][nj][1];
            float v2 = acc[mi][nj][2];
            float v3 = acc[mi][nj][3];
            if (BIAS_MODE == 3) {
                const float bkc0 = bias[512 + c0], bkc1 = bias[512 + c0 + 1];
                const float uc0  = uv[512 + c0],   uc1  = uv[512 + c0 + 1];
                v0 += vv0 * bkc0 + bq0 * uc0;
                v1 += vv0 * bkc1 + bq0 * uc1;
                v2 += vv1 * bkc0 + bq1 * uc0;
                v3 += vv1 * bkc1 + bq1 * uc1;
            }
            v0 *= alpha; v1 *= alpha; v2 *= alpha; v3 *= alpha;
            if (BIAS_MODE == 1) { v0 += br0; v1 += br0; v2 += br1; v3 += br1; }
            if (ADD_RES) {
                const float2 q0 = __half22float2(*(const __half2*)&res[(size_t)r0 * ldres + c0]);
                const float2 q1 = __half22float2(*(const __half2*)&res[(size_t)r1 * ldres + c0]);
                v0 += q0.x; v1 += q0.y; v2 += q1.x; v3 += q1.y;
            }
            if constexpr (sizeof(OutT) == 2) {
                *reinterpret_cast<__half2*>(&D[(size_t)r0 * ldd + c0]) = __floats2half2_rn(v0, v1);
                *reinterpret_cast<__half2*>(&D[(size_t)r1 * ldd + c0]) = __floats2half2_rn(v2, v3);
            } else {
                *reinterpret_cast<float2*>(&D[(size_t)r0 * ldd + c0]) = make_float2(v0, v1);
                *reinterpret_cast<float2*>(&D[(size_t)r1 * ldd + c0]) = make_float2(v2, v3);
            }
        }
    }
}

// ---------------- plain GEMM wrapper ----------------------------------------
template<typename OutT, int BIAS_MODE, bool ADD_RES, bool B_TRANS>
__global__ __launch_bounds__(128, 2) void hgemm_kernel(
    const __half* __restrict__ A, long long sA, int lda,
    const __half* __restrict__ B, long long sB, int ldb,
    OutT* __restrict__ D, long long sD, int ldd,
    int K,
    const float* __restrict__ bias,
    const __half* __restrict__ res, long long sRes, int ldres,
    const float* __restrict__ uv,
    float alpha)
{
    extern __shared__ __align__(128) char smem[];
    gemm_core<OutT, BIAS_MODE, ADD_RES, B_TRANS>(
        blockIdx.x, blockIdx.y, blockIdx.z, smem_u32(smem),
        A, sA, lda, B, sB, ldb, D, sD, ldd, K, bias, res, sRes, ldres, uv, alpha);
}

// ---------------- fused Gram + V-projection + matvec launch -----------------
// ids [0,512): G = xn·xn^T    ids [512,4608): V-proj    ids [4608,4864): matvec
__global__ __launch_bounds__(128, 2) void fused_gv_kernel(
    const __half* __restrict__ xnh, __half* __restrict__ gram,
    const __half* __restrict__ wv,  const float* __restrict__ vb,
    __half* __restrict__ vout,
    const float* __restrict__ qkvw, const float* __restrict__ qkvb,
    const float* __restrict__ srow, float* __restrict__ uv)
{
    extern __shared__ __align__(128) char smem[];
    const uint32_t sbase = smem_u32(smem);
    const long long sXN  = (long long)C * L;
    const long long sATT = (long long)C * C;
    const int tid = threadIdx.x;

    int id = blockIdx.x;
    if (id < 512) {
        // G[b] = xnh·xnh^T  (NT, M=N=512, K=4096)
        gemm_core<__half, 0, false, false>(
            id & 3, (id >> 2) & 3, id >> 4, sbase,
            xnh, sXN, L, xnh, sXN, L,
            gram, sATT, C, L, nullptr, nullptr, 0LL, 0, nullptr, 1.0f);
    } else if (id < 4608) {
        id -= 512;
        // V[o,l] = Wv[o,:]·xnh[:,l] + bv[o]  (trans-B, M=512,N=4096,K=512)
        gemm_core<__half, 1, false, true>(
            id & 31, (id >> 5) & 3, id >> 7, sbase,
            wv, 0LL, C, xnh, sXN, L,
            vout, sXN, L, C, vb, nullptr, 0LL, 0, nullptr, 1.0f);
    } else {
        // matvec: uv[b][r] = qkv_w[r,:]·s[b,:]  (+ L·qkv_b[r] for r>=512)
        id -= 4608;                        // 0..255
        const int b = id >> 3;
        const int r = (id & 7) * 128 + tid;    // 0..1023
        float* ss = (float*)smem;
        for (int i = tid; i < C; i += 128) ss[i] = srow[b * C + i];
        __syncthreads();
        const float4* w4 = (const float4*)(qkvw + (size_t)r * C);
        float d = 0.f;
        #pragma unroll 4
        for (int i = 0; i < C / 4; i++) {
            const float4 wv4 = w4[i];
            d += wv4.x * ss[i*4] + wv4.y * ss[i*4+1]
               + wv4.z * ss[i*4+2] + wv4.w * ss[i*4+3];
        }
        if (r >= 512) d += (float)L * qkvb[r];
        uv[b * 1024 + r] = d;
    }
}

// ---------------------------------------------------------------------------
extern "C" void kernel_launch(void* const* d_in, const int* in_sizes, int n_in,
                              void* d_out, int out_size)
{
    const float* x      = (const float*)d_in[0];
    const float* gn_w   = (const float*)d_in[1];
    const float* gn_b   = (const float*)d_in[2];
    const float* qkv_w  = (const float*)d_in[3];
    const float* qkv_b  = (const float*)d_in[4];
    const float* proj_w = (const float*)d_in[5];
    const float* proj_b = (const float*)d_in[6];
    float* out = (float*)d_out;

    __half *xnh, *v, *gram, *t1, *logits, *attn, *pm, *wh;
    float *srow, *uv;
    cudaGetSymbolAddress((void**)&xnh,    g_xnh);
    cudaGetSymbolAddress((void**)&v,      g_v);
    cudaGetSymbolAddress((void**)&gram,   g_gram);
    cudaGetSymbolAddress((void**)&t1,     g_t1);
    cudaGetSymbolAddress((void**)&logits, g_logits);
    cudaGetSymbolAddress((void**)&attn,   g_attn);
    cudaGetSymbolAddress((void**)&pm,     g_pm);
    cudaGetSymbolAddress((void**)&wh,     g_wh);
    cudaGetSymbolAddress((void**)&srow,   g_s);
    cudaGetSymbolAddress((void**)&uv,     g_uv);

    cudaFuncSetAttribute(hgemm_kernel<__half, 0, false, false>, cudaFuncAttributeMaxDynamicSharedMemorySize, GEMM_SMEM);
    cudaFuncSetAttribute(hgemm_kernel<__half, 3, false, false>, cudaFuncAttributeMaxDynamicSharedMemorySize, GEMM_SMEM);
    cudaFuncSetAttribute(hgemm_kernel<__half, 0, false, true>,  cudaFuncAttributeMaxDynamicSharedMemorySize, GEMM_SMEM);
    cudaFuncSetAttribute(hgemm_kernel<float,  1, true,  true>,  cudaFuncAttributeMaxDynamicSharedMemorySize, GEMM_SMEM);
    cudaFuncSetAttribute(fused_gv_kernel, cudaFuncAttributeMaxDynamicSharedMemorySize, GEMM_SMEM);

    const long long sXN  = (long long)C * L;
    const long long sATT = (long long)C * C;

    // 1) GroupNorm -> xnh fp16 (+ row sums s, + weight convert)
    gn_cvt_kernel<<<BATCH * GROUPS + 1024, 256>>>(
        x, gn_w, gn_b, xnh, qkv_w, proj_w, wh, srow);

    // 2) fused: G = xn·xn^T  +  V projection  +  u/v matvecs
    fused_gv_kernel<<<512 + 4096 + 256, 128, GEMM_SMEM>>>(
        xnh, gram,
        wh + (size_t)1024 * C, qkv_b + 1024, v,
        qkv_w, qkv_b, srow, uv);

    // 3) T1 = Wq·G  (NT, G symmetric; M=512,N=512,K=512)
    {
        dim3 grid(C / 128, C / 128, BATCH);
        hgemm_kernel<__half, 0, false, false><<<grid, 128, GEMM_SMEM>>>(
            wh, 0LL, C, gram, sATT, C, t1, sATT, C, C,
            nullptr, nullptr, 0LL, 0, nullptr, 1.0f);
    }
    // 4) logits = (T1·Wk^T + v⊗bk + bq⊗u) / 64  (NT, rank-1 epilogue)
    {
        dim3 grid(C / 128, C / 128, BATCH);
        hgemm_kernel<__half, 3, false, false><<<grid, 128, GEMM_SMEM>>>(
            t1, sATT, C, wh + (size_t)512 * C, 0LL, C, logits, sATT, C, C,
            qkv_b, nullptr, 0LL, 0, uv, 0.015625f);
    }
    // 5) softmax -> attn fp16
    softmax512_kernel<<<BATCH * C, 128>>>(logits, attn);

    // 6) M[o,k] = Σ_q P[o,q]·attn[q,k]  (trans-B, M=512,N=512,K=512)
    {
        dim3 grid(C / 128, C / 128, BATCH);
        hgemm_kernel<__half, 0, false, true><<<grid, 128, GEMM_SMEM>>>(
            wh + (size_t)3 * C * C, 0LL, C, attn, sATT, C, pm, sATT, C, C,
            nullptr, nullptr, 0LL, 0, nullptr, 1.0f);
    }
    // 7) out[o,l] = M[o,:]·V[:,l] + proj_b[o] + xnh[o,l]  (trans-B)
    {
        dim3 grid(L / 128, C / 128, BATCH);
        hgemm_kernel<float, 1, true, true><<<grid, 128, GEMM_SMEM>>>(
            pm, sATT, C, v, sXN, L, out, sXN, L, C,
            proj_b, xnh, sXN, L, nullptr, 1.0f);
    }
}

// round 11
// speedup vs baseline: 12.8855x; 1.0008x over previous
#include <cuda_runtime.h>
#include <cuda_fp16.h>
#include <cstdint>
#include <math.h>

#define BATCH 32
#define C 512
#define L 4096
#define GROUPS 32
#define CPG 16
#define EPS 1e-5f

// ---------------- scratch (device globals; allocation-free rule) -----------
__device__ __align__(256) __half g_xnh   [(size_t)BATCH * C * L];   // [C,L] normed
__device__ __align__(256) __half g_v     [(size_t)BATCH * C * L];   // V [C,L]
__device__ __align__(256) __half g_gram  [(size_t)BATCH * C * C];   // G = xn·xn^T
__device__ __align__(256) __half g_t1    [(size_t)BATCH * C * C];   // Wq·G
__device__ __align__(256) __half g_logits[(size_t)BATCH * C * C];
__device__ __align__(256) __half g_attn  [(size_t)BATCH * C * C];
__device__ __align__(256) __half g_pm    [(size_t)BATCH * C * C];   // M = P·attn
__device__ __align__(256) __half g_wh    [(size_t)4 * C * C];       // qkv_w + proj_w (fp16)
__device__ __align__(256) float  g_s     [(size_t)BATCH * C];       // row sums of xn
__device__ __align__(256) float  g_uv    [(size_t)BATCH * 1024];    // [v=Wq·s | u=Wk·s+L·bk]

// ---------------- PTX helpers ----------------------------------------------
__device__ __forceinline__ uint32_t smem_u32(const void* p) {
    uint32_t a;
    asm("{ .reg .u64 t; cvta.to.shared.u64 t, %1; cvt.u32.u64 %0, t; }" : "=r"(a) : "l"(p));
    return a;
}
#define CP_ASYNC16(dst, src) \
    asm volatile("cp.async.cg.shared.global [%0], [%1], 16;" :: "r"(dst), "l"(src) : "memory")
#define CP_COMMIT() asm volatile("cp.async.commit_group;" ::: "memory")
#define CP_WAIT1()  asm volatile("cp.async.wait_group 1;" ::: "memory")
#define CP_WAIT0()  asm volatile("cp.async.wait_group 0;" ::: "memory")

__device__ __forceinline__ void ldsm_x4(uint32_t (&r)[4], uint32_t addr) {
    asm volatile("ldmatrix.sync.aligned.m8n8.x4.shared.b16 {%0,%1,%2,%3}, [%4];"
        : "=r"(r[0]), "=r"(r[1]), "=r"(r[2]), "=r"(r[3]) : "r"(addr));
}
__device__ __forceinline__ void ldsm_x4_t(uint32_t (&r)[4], uint32_t addr) {
    asm volatile("ldmatrix.sync.aligned.m8n8.x4.trans.shared.b16 {%0,%1,%2,%3}, [%4];"
        : "=r"(r[0]), "=r"(r[1]), "=r"(r[2]), "=r"(r[3]) : "r"(addr));
}
__device__ __forceinline__ void mma16816(float (&d)[4], const uint32_t (&a)[4],
                                         uint32_t b0, uint32_t b1) {
    asm volatile(
        "mma.sync.aligned.m16n8k16.row.col.f32.f16.f16.f32 "
        "{%0,%1,%2,%3}, {%4,%5,%6,%7}, {%8,%9}, {%0,%1,%2,%3};"
        : "+f"(d[0]), "+f"(d[1]), "+f"(d[2]), "+f"(d[3])
        : "r"(a[0]), "r"(a[1]), "r"(a[2]), "r"(a[3]), "r"(b0), "r"(b1));
}

// ---------------- GroupNorm (+weight convert, +row sums) fused launch -------
__global__ __launch_bounds__(256) void gn_cvt_kernel(
    const float* __restrict__ x, const float* __restrict__ gw,
    const float* __restrict__ gb, __half* __restrict__ xnh,
    const float* __restrict__ qkvw, const float* __restrict__ projw,
    __half* __restrict__ wh, float* __restrict__ srow)
{
    const int bid = blockIdx.x;
    const int tid = threadIdx.x;

    if (bid >= BATCH * GROUPS) {
        const int i4 = (bid - BATCH * GROUPS) * 256 + tid;
        const int n_qkv4 = 3 * C * C / 4;
        float4 v;
        if (i4 < n_qkv4) v = ((const float4*)qkvw)[i4];
        else             v = ((const float4*)projw)[i4 - n_qkv4];
        __half2* o = (__half2*)(wh + (size_t)i4 * 4);
        o[0] = __floats2half2_rn(v.x, v.y);
        o[1] = __floats2half2_rn(v.z, v.w);
        return;
    }

    const int b = bid / GROUPS;
    const int g = bid % GROUPS;
    const size_t base = ((size_t)b * C + (size_t)g * CPG) * L;
    const float4* px4 = (const float4*)(x + base);
    __half2* outh = (__half2*)(xnh + base);
    const int n4 = CPG * L / 4;

    float s = 0.f, ss = 0.f;
    for (int i = tid; i < n4; i += 256) {
        float4 v = px4[i];
        s  += v.x + v.y + v.z + v.w;
        ss += v.x*v.x + v.y*v.y + v.z*v.z + v.w*v.w;
    }
    __shared__ float sh_s[32], sh_ss[32];
    for (int o = 16; o > 0; o >>= 1) {
        s  += __shfl_down_sync(0xffffffff, s, o);
        ss += __shfl_down_sync(0xffffffff, ss, o);
    }
    if ((tid & 31) == 0) { sh_s[tid >> 5] = s; sh_ss[tid >> 5] = ss; }
    __syncthreads();
    if (tid < 32) {
        s  = (tid < 8) ? sh_s[tid]  : 0.f;
        ss = (tid < 8) ? sh_ss[tid] : 0.f;
        for (int o = 4; o > 0; o >>= 1) {
            s  += __shfl_down_sync(0xffffffff, s, o);
            ss += __shfl_down_sync(0xffffffff, ss, o);
        }
        if (tid == 0) { sh_s[0] = s; sh_ss[0] = ss; }
    }
    __syncthreads();
    const float inv_n = 1.f / (float)(CPG * L);
    const float mean  = sh_s[0] * inv_n;
    const float var   = sh_ss[0] * inv_n - mean * mean;
    const float rstd  = rsqrtf(var + EPS);

    // per-channel row sums while writing (ch = j>>2 for this thread layout)
    float csum[16];
    #pragma unroll
    for (int c = 0; c < 16; c++) csum[c] = 0.f;

    for (int j = 0; j < 64; j++) {
        const int i = tid + 256 * j;
        const int ch = j >> 2;                    // exact: (tid+256j)>>10 == j>>2
        const float w = gw[g * CPG + ch] * rstd;
        const float bb = gb[g * CPG + ch] - mean * w;
        float4 v = px4[i];
        const float e0 = fmaf(v.x, w, bb), e1 = fmaf(v.y, w, bb);
        const float e2 = fmaf(v.z, w, bb), e3 = fmaf(v.w, w, bb);
        outh[i * 2 + 0] = __floats2half2_rn(e0, e1);
        outh[i * 2 + 1] = __floats2half2_rn(e2, e3);
        csum[ch] += (e0 + e1) + (e2 + e3);
    }
    __shared__ float s_part[16][8];
    #pragma unroll
    for (int c = 0; c < 16; c++) {
        float t = csum[c];
        for (int o = 16; o > 0; o >>= 1) t += __shfl_down_sync(0xffffffff, t, o);
        if ((tid & 31) == 0) s_part[c][tid >> 5] = t;
    }
    __syncthreads();
    if (tid < 16) {
        float t = 0.f;
        #pragma unroll
        for (int w8 = 0; w8 < 8; w8++) t += s_part[tid][w8];
        srow[b * C + g * CPG + tid] = t;
    }
}

// ---------------- Row softmax (fp16 in, fp16 out) ---------------------------
__global__ __launch_bounds__(128) void softmax512_kernel(
    const __half* __restrict__ logits, __half* __restrict__ attn)
{
    const size_t row = blockIdx.x;
    const __half2* p = (const __half2*)(logits + row * C);
    const int tid = threadIdx.x;

    float2 a = __half22float2(p[tid * 2 + 0]);
    float2 b = __half22float2(p[tid * 2 + 1]);
    float m = fmaxf(fmaxf(a.x, a.y), fmaxf(b.x, b.y));
    __shared__ float sh[4];
    for (int o = 16; o > 0; o >>= 1) m = fmaxf(m, __shfl_xor_sync(0xffffffff, m, o));
    if ((tid & 31) == 0) sh[tid >> 5] = m;
    __syncthreads();
    m = fmaxf(fmaxf(sh[0], sh[1]), fmaxf(sh[2], sh[3]));

    a.x = expf(a.x - m); a.y = expf(a.y - m);
    b.x = expf(b.x - m); b.y = expf(b.y - m);
    float s = a.x + a.y + b.x + b.y;
    for (int o = 16; o > 0; o >>= 1) s += __shfl_xor_sync(0xffffffff, s, o);
    __shared__ float shs[4];
    if ((tid & 31) == 0) shs[tid >> 5] = s;
    __syncthreads();
    s = shs[0] + shs[1] + shs[2] + shs[3];
    const float inv = 1.f / s;

    __half2* o2 = (__half2*)(attn + row * C);
    o2[tid * 2 + 0] = __floats2half2_rn(a.x * inv, a.y * inv);
    o2[tid * 2 + 1] = __floats2half2_rn(b.x * inv, b.y * inv);
}

// ---------------- fp16 tensor-core GEMM core --------------------------------
// BIAS_MODE: 0 none, 1 row bias, 3 rank-1 logits epilogue
//   (mode 3: out = alpha*(acc + uv[r]*bias[512+c] + bias[r]*uv[512+c]))
#define STAGE_BYTES 32768          // A 16KB + B 16KB
#define GEMM_SMEM  (3 * STAGE_BYTES)

__device__ __forceinline__ void load_A(const __half* __restrict__ gA, int lda,
                                       uint32_t st, int tid)
{
    #pragma unroll
    for (int j = 0; j < 8; j++) {
        const int slot = tid + 128 * j;
        const int row  = slot >> 3;
        const int c    = slot & 7;
        const uint32_t off = (uint32_t)row * 128u + (uint32_t)((c ^ (row & 7)) << 4);
        CP_ASYNC16(st + off, gA + (size_t)row * lda + c * 8);
    }
}
__device__ __forceinline__ void load_B_nt(const __half* __restrict__ gB, int ldb,
                                          uint32_t st, int tid)
{
    #pragma unroll
    for (int j = 0; j < 8; j++) {
        const int slot = tid + 128 * j;
        const int row  = slot >> 3;
        const int c    = slot & 7;
        const uint32_t off = (uint32_t)row * 128u + (uint32_t)((c ^ (row & 7)) << 4);
        CP_ASYNC16(st + off, gB + (size_t)row * ldb + c * 8);
    }
}
__device__ __forceinline__ void load_B_t(const __half* __restrict__ gB, int ldb,
                                         uint32_t st, int tid)
{
    #pragma unroll
    for (int j = 0; j < 8; j++) {
        const int slot = tid + 128 * j;
        const int row  = slot >> 4;           // 0..63 (k)
        const int c    = slot & 15;           // 16B chunk (n/8)
        const uint32_t off = (uint32_t)((row * 2 + (c >> 3)) * 128)
                           + (uint32_t)(((c & 7) ^ (row & 7)) << 4);
        CP_ASYNC16(st + off, gB + (size_t)row * ldb + c * 8);
    }
}

template<typename OutT, int BIAS_MODE, bool ADD_RES, bool B_TRANS>
__device__ __forceinline__ void gemm_core(
    int bx, int by, int bz, uint32_t sbase,
    const __half* __restrict__ A, long long sA, int lda,
    const __half* __restrict__ B, long long sB, int ldb,
    OutT* __restrict__ D, long long sD, int ldd,
    int K,
    const float* __restrict__ bias,
    const __half* __restrict__ res, long long sRes, int ldres,
    const float* __restrict__ uv,
    float alpha)
{
    A += (size_t)bz * sA;
    B += (size_t)bz * sB;
    D += (size_t)bz * sD;
    if (ADD_RES) res += (size_t)bz * sRes;
    if (BIAS_MODE == 3) uv += (size_t)bz * 1024;

    const int bm = by * 128;
    const int bn = bx * 128;
    const int tid = threadIdx.x;
    const int lane = tid & 31;
    const int wid = tid >> 5;
    const int wm = wid & 1;
    const int wn = wid >> 1;

    const __half* gA = A + (size_t)bm * lda;
    const __half* gB = B_TRANS ? (B + bn) : (B + (size_t)bn * ldb);
    const int T = K >> 6;

    const int a_row_lo = lane & 15;
    const int a_sel    = lane >> 4;
    const int b_row_lo = (lane & 7) + ((lane >> 4) << 3);
    const int b_sel    = (lane >> 3) & 1;
    const int bt_k_lo  = lane & 15;
    const int bt_n8    = (lane >> 4) << 3;

    float acc[4][8][4];
    #pragma unroll
    for (int i = 0; i < 4; i++)
        #pragma unroll
        for (int j = 0; j < 8; j++)
            #pragma unroll
            for (int q = 0; q < 4; q++) acc[i][j][q] = 0.f;

    #pragma unroll
    for (int s = 0; s < 2; s++) {
        const uint32_t st = sbase + s * STAGE_BYTES;
        load_A(gA + s * 64, lda, st, tid);
        if (B_TRANS) load_B_t(gB + (size_t)(s * 64) * ldb, ldb, st + 16384, tid);
        else         load_B_nt(gB + s * 64, ldb, st + 16384, tid);
        CP_COMMIT();
    }

    for (int t = 0; t < T; t++) {
        if (t < T - 1) CP_WAIT1(); else CP_WAIT0();
        __syncthreads();

        if (t + 2 < T) {
            const int s = t + 2;
            const uint32_t st = sbase + (s % 3) * STAGE_BYTES;
            load_A(gA + s * 64, lda, st, tid);
            if (B_TRANS) load_B_t(gB + (size_t)(s * 64) * ldb, ldb, st + 16384, tid);
            else         load_B_nt(gB + s * 64, ldb, st + 16384, tid);
            CP_COMMIT();
        }

        const uint32_t stA = sbase + (t % 3) * STAGE_BYTES;
        const uint32_t stB = stA + 16384;

        #pragma unroll
        for (int ks = 0; ks < 4; ks++) {
            uint32_t aF[4][4];
            uint32_t bF[4][4];
            #pragma unroll
            for (int mi = 0; mi < 4; mi++) {
                const int row = wm * 64 + mi * 16 + a_row_lo;
                const int ch  = ks * 2 + a_sel;
                ldsm_x4(aF[mi], stA + (uint32_t)row * 128u + (uint32_t)((ch ^ (row & 7)) << 4));
            }
            if (B_TRANS) {
                const int krow = ks * 16 + bt_k_lo;
                #pragma unroll
                for (int nb = 0; nb < 4; nb++) {
                    const int n = wn * 64 + nb * 16 + bt_n8;
                    const uint32_t addr = stB
                        + (uint32_t)((krow * 2 + (n >> 6)) * 128)
                        + (uint32_t)((((n >> 3) & 7) ^ (krow & 7)) << 4);
                    ldsm_x4_t(bF[nb], addr);
                }
            } else {
                #pragma unroll
                for (int nb = 0; nb < 4; nb++) {
                    const int row = wn * 64 + nb * 16 + b_row_lo;
                    const int ch  = ks * 2 + b_sel;
                    ldsm_x4(bF[nb], stB + (uint32_t)row * 128u + (uint32_t)((ch ^ (row & 7)) << 4));
                }
            }
            #pragma unroll
            for (int mi = 0; mi < 4; mi++)
                #pragma unroll
                for (int nj = 0; nj < 8; nj++)
                    mma16816(acc[mi][nj], aF[mi],
                             bF[nj >> 1][(nj & 1) * 2], bF[nj >> 1][(nj & 1) * 2 + 1]);
        }
    }

    const int m0 = bm + wm * 64;
    const int n0 = bn + wn * 64;
    #pragma unroll
    for (int mi = 0; mi < 4; mi++) {
        const int r0 = m0 + mi * 16 + (lane >> 2);
        const int r1 = r0 + 8;
        float br0 = 0.f, br1 = 0.f;
        if (BIAS_MODE == 1) { br0 = bias[r0]; br1 = bias[r1]; }
        float bq0 = 0.f, bq1 = 0.f, vv0 = 0.f, vv1 = 0.f;
        if (BIAS_MODE == 3) {
            bq0 = bias[r0]; bq1 = bias[r1];
            vv0 = uv[r0];   vv1 = uv[r1];
        }
        #pragma unroll
        for (int nj = 0; nj < 8; nj++) {
            const int c0 = n0 + nj * 8 + (lane & 3) * 2;
            float v0 = acc[mi][nj][0];
            float v1 = acc[mi][nj][1];
            float v2 = acc[mi][nj][2];
            float v3 = acc[mi][nj][3];
            if (BIAS_MODE == 3) {
                const float bkc0 = bias[512 + c0], bkc1 = bias[512 + c0 + 1];
                const float uc0  = uv[512 + c0],   uc1  = uv[512 + c0 + 1];
                v0 += vv0 * bkc0 + bq0 * uc0;
                v1 += vv0 * bkc1 + bq0 * uc1;
                v2 += vv1 * bkc0 + bq1 * uc0;
                v3 += vv1 * bkc1 + bq1 * uc1;
            }
            v0 *= alpha; v1 *= alpha; v2 *= alpha; v3 *= alpha;
            if (BIAS_MODE == 1) { v0 += br0; v1 += br0; v2 += br1; v3 += br1; }
            if (ADD_RES) {
                const float2 q0 = __half22float2(*(const __half2*)&res[(size_t)r0 * ldres + c0]);
                const float2 q1 = __half22float2(*(const __half2*)&res[(size_t)r1 * ldres + c0]);
                v0 += q0.x; v1 += q0.y; v2 += q1.x; v3 += q1.y;
            }
            if constexpr (sizeof(OutT) == 2) {
                *reinterpret_cast<__half2*>(&D[(size_t)r0 * ldd + c0]) = __floats2half2_rn(v0, v1);
                *reinterpret_cast<__half2*>(&D[(size_t)r1 * ldd + c0]) = __floats2half2_rn(v2, v3);
            } else {
                *reinterpret_cast<float2*>(&D[(size_t)r0 * ldd + c0]) = make_float2(v0, v1);
                *reinterpret_cast<float2*>(&D[(size_t)r1 * ldd + c0]) = make_float2(v2, v3);
            }
        }
    }
}

// ---------------- plain GEMM wrapper ----------------------------------------
template<typename OutT, int BIAS_MODE, bool ADD_RES, bool B_TRANS>
__global__ __launch_bounds__(128, 2) void hgemm_kernel(
    const __half* __restrict__ A, long long sA, int lda,
    const __half* __restrict__ B, long long sB, int ldb,
    OutT* __restrict__ D, long long sD, int ldd,
    int K,
    const float* __restrict__ bias,
    const __half* __restrict__ res, long long sRes, int ldres,
    const float* __restrict__ uv,
    float alpha)
{
    extern __shared__ __align__(128) char smem[];
    gemm_core<OutT, BIAS_MODE, ADD_RES, B_TRANS>(
        blockIdx.x, blockIdx.y, blockIdx.z, smem_u32(smem),
        A, sA, lda, B, sB, ldb, D, sD, ldd, K, bias, res, sRes, ldres, uv, alpha);
}

// ---------------- fused Gram + V-projection + matvec launch -----------------
// ids [0,512): G = xn·xn^T    ids [512,4608): V-proj    ids [4608,4864): matvec
__global__ __launch_bounds__(128, 2) void fused_gv_kernel(
    const __half* __restrict__ xnh, __half* __restrict__ gram,
    const __half* __restrict__ wv,  const float* __restrict__ vb,
    __half* __restrict__ vout,
    const float* __restrict__ qkvw, const float* __restrict__ qkvb,
    const float* __restrict__ srow, float* __restrict__ uv)
{
    extern __shared__ __align__(128) char smem[];
    const uint32_t sbase = smem_u32(smem);
    const long long sXN  = (long long)C * L;
    const long long sATT = (long long)C * C;
    const int tid = threadIdx.x;

    int id = blockIdx.x;
    if (id < 512) {
        // G[b] = xnh·xnh^T  (NT, M=N=512, K=4096)
        gemm_core<__half, 0, false, false>(
            id & 3, (id >> 2) & 3, id >> 4, sbase,
            xnh, sXN, L, xnh, sXN, L,
            gram, sATT, C, L, nullptr, nullptr, 0LL, 0, nullptr, 1.0f);
    } else if (id < 4608) {
        id -= 512;
        // V[o,l] = Wv[o,:]·xnh[:,l] + bv[o]  (trans-B, M=512,N=4096,K=512)
        gemm_core<__half, 1, false, true>(
            id & 31, (id >> 5) & 3, id >> 7, sbase,
            wv, 0LL, C, xnh, sXN, L,
            vout, sXN, L, C, vb, nullptr, 0LL, 0, nullptr, 1.0f);
    } else {
        // matvec: uv[b][r] = qkv_w[r,:]·s[b,:]  (+ L·qkv_b[r] for r>=512)
        id -= 4608;                        // 0..255
        const int b = id >> 3;
        const int r = (id & 7) * 128 + tid;    // 0..1023
        float* ss = (float*)smem;
        for (int i = tid; i < C; i += 128) ss[i] = srow[b * C + i];
        __syncthreads();
        const float4* w4 = (const float4*)(qkvw + (size_t)r * C);
        float d = 0.f;
        #pragma unroll 4
        for (int i = 0; i < C / 4; i++) {
            const float4 wv4 = w4[i];
            d += wv4.x * ss[i*4] + wv4.y * ss[i*4+1]
               + wv4.z * ss[i*4+2] + wv4.w * ss[i*4+3];
        }
        if (r >= 512) d += (float)L * qkvb[r];
        uv[b * 1024 + r] = d;
    }
}

// ---------------------------------------------------------------------------
extern "C" void kernel_launch(void* const* d_in, const int* in_sizes, int n_in,
                              void* d_out, int out_size)
{
    const float* x      = (const float*)d_in[0];
    const float* gn_w   = (const float*)d_in[1];
    const float* gn_b   = (const float*)d_in[2];
    const float* qkv_w  = (const float*)d_in[3];
    const float* qkv_b  = (const float*)d_in[4];
    const float* proj_w = (const float*)d_in[5];
    const float* proj_b = (const float*)d_in[6];
    float* out = (float*)d_out;

    __half *xnh, *v, *gram, *t1, *logits, *attn, *pm, *wh;
    float *srow, *uv;
    cudaGetSymbolAddress((void**)&xnh,    g_xnh);
    cudaGetSymbolAddress((void**)&v,      g_v);
    cudaGetSymbolAddress((void**)&gram,   g_gram);
    cudaGetSymbolAddress((void**)&t1,     g_t1);
    cudaGetSymbolAddress((void**)&logits, g_logits);
    cudaGetSymbolAddress((void**)&attn,   g_attn);
    cudaGetSymbolAddress((void**)&pm,     g_pm);
    cudaGetSymbolAddress((void**)&wh,     g_wh);
    cudaGetSymbolAddress((void**)&srow,   g_s);
    cudaGetSymbolAddress((void**)&uv,     g_uv);

    cudaFuncSetAttribute(hgemm_kernel<__half, 0, false, false>, cudaFuncAttributeMaxDynamicSharedMemorySize, GEMM_SMEM);
    cudaFuncSetAttribute(hgemm_kernel<__half, 3, false, false>, cudaFuncAttributeMaxDynamicSharedMemorySize, GEMM_SMEM);
    cudaFuncSetAttribute(hgemm_kernel<__half, 0, false, true>,  cudaFuncAttributeMaxDynamicSharedMemorySize, GEMM_SMEM);
    cudaFuncSetAttribute(hgemm_kernel<float,  1, true,  true>,  cudaFuncAttributeMaxDynamicSharedMemorySize, GEMM_SMEM);
    cudaFuncSetAttribute(fused_gv_kernel, cudaFuncAttributeMaxDynamicSharedMemorySize, GEMM_SMEM);

    const long long sXN  = (long long)C * L;
    const long long sATT = (long long)C * C;

    // 1) GroupNorm -> xnh fp16 (+ row sums s, + weight convert)
    gn_cvt_kernel<<<BATCH * GROUPS + 1024, 256>>>(
        x, gn_w, gn_b, xnh, qkv_w, proj_w, wh, srow);

    // 2) fused: G = xn·xn^T  +  V projection  +  u/v matvecs
    fused_gv_kernel<<<512 + 4096 + 256, 128, GEMM_SMEM>>>(
        xnh, gram,
        wh + (size_t)1024 * C, qkv_b + 1024, v,
        qkv_w, qkv_b, srow, uv);

    // 3) T1 = Wq·G  (NT, G symmetric; M=512,N=512,K=512)
    {
        dim3 grid(C / 128, C / 128, BATCH);
        hgemm_kernel<__half, 0, false, false><<<grid, 128, GEMM_SMEM>>>(
            wh, 0LL, C, gram, sATT, C, t1, sATT, C, C,
            nullptr, nullptr, 0LL, 0, nullptr, 1.0f);
    }
    // 4) logits = (T1·Wk^T + v⊗bk + bq⊗u) / 64  (NT, rank-1 epilogue)
    {
        dim3 grid(C / 128, C / 128, BATCH);
        hgemm_kernel<__half, 3, false, false><<<grid, 128, GEMM_SMEM>>>(
            t1, sATT, C, wh + (size_t)512 * C, 0LL, C, logits, sATT, C, C,
            qkv_b, nullptr, 0LL, 0, uv, 0.015625f);
    }
    // 5) softmax -> attn fp16
    softmax512_kernel<<<BATCH * C, 128>>>(logits, attn);

    // 6) M[o,k] = Σ_q P[o,q]·attn[q,k]  (trans-B, M=512,N=512,K=512)
    {
        dim3 grid(C / 128, C / 128, BATCH);
        hgemm_kernel<__half, 0, false, true><<<grid, 128, GEMM_SMEM>>>(
            wh + (size_t)3 * C * C, 0LL, C, attn, sATT, C, pm, sATT, C, C,
            nullptr, nullptr, 0LL, 0, nullptr, 1.0f);
    }
    // 7) out[o,l] = M[o,:]·V[:,l] + proj_b[o] + xnh[o,l]  (trans-B)
    {
        dim3 grid(L / 128, C / 128, BATCH);
        hgemm_kernel<float, 1, true, true><<<grid, 128, GEMM_SMEM>>>(
            pm, sATT, C, v, sXN, L, out, sXN, L, C,
            proj_b, xnh, sXN, L, nullptr, 1.0f);
    }
}

// round 12
// speedup vs baseline: 15.0700x; 1.1695x over previous
#include <cuda_runtime.h>
#include <cuda_fp16.h>
#include <cstdint>
#include <math.h>

#define BATCH 32
#define C 512
#define L 4096
#define GROUPS 32
#define CPG 16
#define EPS 1e-5f

// ---------------- scratch (device globals; allocation-free rule) -----------
__device__ __align__(256) __half g_xnh   [(size_t)BATCH * C * L];   // [C,L] normed
__device__ __align__(256) __half g_gram  [(size_t)BATCH * C * C];   // G = xn·xn^T
__device__ __align__(256) __half g_t1    [(size_t)BATCH * C * C];   // Wq·G
__device__ __align__(256) __half g_logits[(size_t)BATCH * C * C];
__device__ __align__(256) __half g_attn  [(size_t)BATCH * C * C];
__device__ __align__(256) __half g_pm    [(size_t)BATCH * C * C];   // M = P·attn
__device__ __align__(256) __half g_mwv   [(size_t)BATCH * C * C];   // M·Wv
__device__ __align__(256) __half g_wh    [(size_t)4 * C * C];       // qkv_w + proj_w (fp16)
__device__ __align__(256) float  g_s     [(size_t)BATCH * C];       // row sums of xn
__device__ __align__(256) float  g_uv    [(size_t)BATCH * 1024];    // [v=Wq·s | u=Wk·s+L·bk]
__device__ __align__(256) float  g_e     [(size_t)BATCH * C];       // e = M·bv + proj_b

// ---------------- PTX helpers ----------------------------------------------
__device__ __forceinline__ uint32_t smem_u32(const void* p) {
    uint32_t a;
    asm("{ .reg .u64 t; cvta.to.shared.u64 t, %1; cvt.u32.u64 %0, t; }" : "=r"(a) : "l"(p));
    return a;
}
#define CP_ASYNC16(dst, src) \
    asm volatile("cp.async.cg.shared.global [%0], [%1], 16;" :: "r"(dst), "l"(src) : "memory")
#define CP_COMMIT() asm volatile("cp.async.commit_group;" ::: "memory")
#define CP_WAIT1()  asm volatile("cp.async.wait_group 1;" ::: "memory")
#define CP_WAIT0()  asm volatile("cp.async.wait_group 0;" ::: "memory")

__device__ __forceinline__ void ldsm_x4(uint32_t (&r)[4], uint32_t addr) {
    asm volatile("ldmatrix.sync.aligned.m8n8.x4.shared.b16 {%0,%1,%2,%3}, [%4];"
        : "=r"(r[0]), "=r"(r[1]), "=r"(r[2]), "=r"(r[3]) : "r"(addr));
}
__device__ __forceinline__ void ldsm_x4_t(uint32_t (&r)[4], uint32_t addr) {
    asm volatile("ldmatrix.sync.aligned.m8n8.x4.trans.shared.b16 {%0,%1,%2,%3}, [%4];"
        : "=r"(r[0]), "=r"(r[1]), "=r"(r[2]), "=r"(r[3]) : "r"(addr));
}
__device__ __forceinline__ void mma16816(float (&d)[4], const uint32_t (&a)[4],
                                         uint32_t b0, uint32_t b1) {
    asm volatile(
        "mma.sync.aligned.m16n8k16.row.col.f32.f16.f16.f32 "
        "{%0,%1,%2,%3}, {%4,%5,%6,%7}, {%8,%9}, {%0,%1,%2,%3};"
        : "+f"(d[0]), "+f"(d[1]), "+f"(d[2]), "+f"(d[3])
        : "r"(a[0]), "r"(a[1]), "r"(a[2]), "r"(a[3]), "r"(b0), "r"(b1));
}

// ---------------- GroupNorm (+weight convert, +row sums) fused launch -------
__global__ __launch_bounds__(256) void gn_cvt_kernel(
    const float* __restrict__ x, const float* __restrict__ gw,
    const float* __restrict__ gb, __half* __restrict__ xnh,
    const float* __restrict__ qkvw, const float* __restrict__ projw,
    __half* __restrict__ wh, float* __restrict__ srow)
{
    const int bid = blockIdx.x;
    const int tid = threadIdx.x;

    if (bid >= BATCH * GROUPS) {
        const int i4 = (bid - BATCH * GROUPS) * 256 + tid;
        const int n_qkv4 = 3 * C * C / 4;
        float4 v;
        if (i4 < n_qkv4) v = ((const float4*)qkvw)[i4];
        else             v = ((const float4*)projw)[i4 - n_qkv4];
        __half2* o = (__half2*)(wh + (size_t)i4 * 4);
        o[0] = __floats2half2_rn(v.x, v.y);
        o[1] = __floats2half2_rn(v.z, v.w);
        return;
    }

    const int b = bid / GROUPS;
    const int g = bid % GROUPS;
    const size_t base = ((size_t)b * C + (size_t)g * CPG) * L;
    const float4* px4 = (const float4*)(x + base);
    __half2* outh = (__half2*)(xnh + base);
    const int n4 = CPG * L / 4;

    float s = 0.f, ss = 0.f;
    for (int i = tid; i < n4; i += 256) {
        float4 v = px4[i];
        s  += v.x + v.y + v.z + v.w;
        ss += v.x*v.x + v.y*v.y + v.z*v.z + v.w*v.w;
    }
    __shared__ float sh_s[32], sh_ss[32];
    for (int o = 16; o > 0; o >>= 1) {
        s  += __shfl_down_sync(0xffffffff, s, o);
        ss += __shfl_down_sync(0xffffffff, ss, o);
    }
    if ((tid & 31) == 0) { sh_s[tid >> 5] = s; sh_ss[tid >> 5] = ss; }
    __syncthreads();
    if (tid < 32) {
        s  = (tid < 8) ? sh_s[tid]  : 0.f;
        ss = (tid < 8) ? sh_ss[tid] : 0.f;
        for (int o = 4; o > 0; o >>= 1) {
            s  += __shfl_down_sync(0xffffffff, s, o);
            ss += __shfl_down_sync(0xffffffff, ss, o);
        }
        if (tid == 0) { sh_s[0] = s; sh_ss[0] = ss; }
    }
    __syncthreads();
    const float inv_n = 1.f / (float)(CPG * L);
    const float mean  = sh_s[0] * inv_n;
    const float var   = sh_ss[0] * inv_n - mean * mean;
    const float rstd  = rsqrtf(var + EPS);

    float csum[16];
    #pragma unroll
    for (int c = 0; c < 16; c++) csum[c] = 0.f;

    for (int j = 0; j < 64; j++) {
        const int i = tid + 256 * j;
        const int ch = j >> 2;
        const float w = gw[g * CPG + ch] * rstd;
        const float bb = gb[g * CPG + ch] - mean * w;
        float4 v = px4[i];
        const float e0 = fmaf(v.x, w, bb), e1 = fmaf(v.y, w, bb);
        const float e2 = fmaf(v.z, w, bb), e3 = fmaf(v.w, w, bb);
        outh[i * 2 + 0] = __floats2half2_rn(e0, e1);
        outh[i * 2 + 1] = __floats2half2_rn(e2, e3);
        csum[ch] += (e0 + e1) + (e2 + e3);
    }
    __shared__ float s_part[16][8];
    #pragma unroll
    for (int c = 0; c < 16; c++) {
        float t = csum[c];
        for (int o = 16; o > 0; o >>= 1) t += __shfl_down_sync(0xffffffff, t, o);
        if ((tid & 31) == 0) s_part[c][tid >> 5] = t;
    }
    __syncthreads();
    if (tid < 16) {
        float t = 0.f;
        #pragma unroll
        for (int w8 = 0; w8 < 8; w8++) t += s_part[tid][w8];
        srow[b * C + g * CPG + tid] = t;
    }
}

// ---------------- Row softmax (fp16 in, fp16 out) ---------------------------
__global__ __launch_bounds__(128) void softmax512_kernel(
    const __half* __restrict__ logits, __half* __restrict__ attn)
{
    const size_t row = blockIdx.x;
    const __half2* p = (const __half2*)(logits + row * C);
    const int tid = threadIdx.x;

    float2 a = __half22float2(p[tid * 2 + 0]);
    float2 b = __half22float2(p[tid * 2 + 1]);
    float m = fmaxf(fmaxf(a.x, a.y), fmaxf(b.x, b.y));
    __shared__ float sh[4];
    for (int o = 16; o > 0; o >>= 1) m = fmaxf(m, __shfl_xor_sync(0xffffffff, m, o));
    if ((tid & 31) == 0) sh[tid >> 5] = m;
    __syncthreads();
    m = fmaxf(fmaxf(sh[0], sh[1]), fmaxf(sh[2], sh[3]));

    a.x = expf(a.x - m); a.y = expf(a.y - m);
    b.x = expf(b.x - m); b.y = expf(b.y - m);
    float s = a.x + a.y + b.x + b.y;
    for (int o = 16; o > 0; o >>= 1) s += __shfl_xor_sync(0xffffffff, s, o);
    __shared__ float shs[4];
    if ((tid & 31) == 0) shs[tid >> 5] = s;
    __syncthreads();
    s = shs[0] + shs[1] + shs[2] + shs[3];
    const float inv = 1.f / s;

    __half2* o2 = (__half2*)(attn + row * C);
    o2[tid * 2 + 0] = __floats2half2_rn(a.x * inv, a.y * inv);
    o2[tid * 2 + 1] = __floats2half2_rn(b.x * inv, b.y * inv);
}

// ---------------- fp16 tensor-core GEMM core --------------------------------
// BIAS_MODE: 0 none, 1 row bias (per-batch via sBias), 3 rank-1 logits epilogue
#define STAGE_BYTES 32768          // A 16KB + B 16KB
#define GEMM_SMEM  (3 * STAGE_BYTES)

__device__ __forceinline__ void load_A(const __half* __restrict__ gA, int lda,
                                       uint32_t st, int tid)
{
    #pragma unroll
    for (int j = 0; j < 8; j++) {
        const int slot = tid + 128 * j;
        const int row  = slot >> 3;
        const int c    = slot & 7;
        const uint32_t off = (uint32_t)row * 128u + (uint32_t)((c ^ (row & 7)) << 4);
        CP_ASYNC16(st + off, gA + (size_t)row * lda + c * 8);
    }
}
__device__ __forceinline__ void load_B_nt(const __half* __restrict__ gB, int ldb,
                                          uint32_t st, int tid)
{
    #pragma unroll
    for (int j = 0; j < 8; j++) {
        const int slot = tid + 128 * j;
        const int row  = slot >> 3;
        const int c    = slot & 7;
        const uint32_t off = (uint32_t)row * 128u + (uint32_t)((c ^ (row & 7)) << 4);
        CP_ASYNC16(st + off, gB + (size_t)row * ldb + c * 8);
    }
}
__device__ __forceinline__ void load_B_t(const __half* __restrict__ gB, int ldb,
                                         uint32_t st, int tid)
{
    #pragma unroll
    for (int j = 0; j < 8; j++) {
        const int slot = tid + 128 * j;
        const int row  = slot >> 4;           // 0..63 (k)
        const int c    = slot & 15;           // 16B chunk (n/8)
        const uint32_t off = (uint32_t)((row * 2 + (c >> 3)) * 128)
                           + (uint32_t)(((c & 7) ^ (row & 7)) << 4);
        CP_ASYNC16(st + off, gB + (size_t)row * ldb + c * 8);
    }
}

template<typename OutT, int BIAS_MODE, bool ADD_RES, bool B_TRANS>
__device__ __forceinline__ void gemm_core(
    int bx, int by, int bz, uint32_t sbase,
    const __half* __restrict__ A, long long sA, int lda,
    const __half* __restrict__ B, long long sB, int ldb,
    OutT* __restrict__ D, long long sD, int ldd,
    int K,
    const float* __restrict__ bias, long long sBias,
    const __half* __restrict__ res, long long sRes, int ldres,
    const float* __restrict__ uv,
    float alpha)
{
    A += (size_t)bz * sA;
    B += (size_t)bz * sB;
    D += (size_t)bz * sD;
    if (ADD_RES) res += (size_t)bz * sRes;
    if (BIAS_MODE == 1) bias += (size_t)bz * sBias;
    if (BIAS_MODE == 3) uv += (size_t)bz * 1024;

    const int bm = by * 128;
    const int bn = bx * 128;
    const int tid = threadIdx.x;
    const int lane = tid & 31;
    const int wid = tid >> 5;
    const int wm = wid & 1;
    const int wn = wid >> 1;

    const __half* gA = A + (size_t)bm * lda;
    const __half* gB = B_TRANS ? (B + bn) : (B + (size_t)bn * ldb);
    const int T = K >> 6;

    const int a_row_lo = lane & 15;
    const int a_sel    = lane >> 4;
    const int b_row_lo = (lane & 7) + ((lane >> 4) << 3);
    const int b_sel    = (lane >> 3) & 1;
    const int bt_k_lo  = lane & 15;
    const int bt_n8    = (lane >> 4) << 3;

    float acc[4][8][4];
    #pragma unroll
    for (int i = 0; i < 4; i++)
        #pragma unroll
        for (int j = 0; j < 8; j++)
            #pragma unroll
            for (int q = 0; q < 4; q++) acc[i][j][q] = 0.f;

    #pragma unroll
    for (int s = 0; s < 2; s++) {
        const uint32_t st = sbase + s * STAGE_BYTES;
        load_A(gA + s * 64, lda, st, tid);
        if (B_TRANS) load_B_t(gB + (size_t)(s * 64) * ldb, ldb, st + 16384, tid);
        else         load_B_nt(gB + s * 64, ldb, st + 16384, tid);
        CP_COMMIT();
    }

    for (int t = 0; t < T; t++) {
        if (t < T - 1) CP_WAIT1(); else CP_WAIT0();
        __syncthreads();

        if (t + 2 < T) {
            const int s = t + 2;
            const uint32_t st = sbase + (s % 3) * STAGE_BYTES;
            load_A(gA + s * 64, lda, st, tid);
            if (B_TRANS) load_B_t(gB + (size_t)(s * 64) * ldb, ldb, st + 16384, tid);
            else         load_B_nt(gB + s * 64, ldb, st + 16384, tid);
            CP_COMMIT();
        }

        const uint32_t stA = sbase + (t % 3) * STAGE_BYTES;
        const uint32_t stB = stA + 16384;

        #pragma unroll
        for (int ks = 0; ks < 4; ks++) {
            uint32_t aF[4][4];
            uint32_t bF[4][4];
            #pragma unroll
            for (int mi = 0; mi < 4; mi++) {
                const int row = wm * 64 + mi * 16 + a_row_lo;
                const int ch  = ks * 2 + a_sel;
                ldsm_x4(aF[mi], stA + (uint32_t)row * 128u + (uint32_t)((ch ^ (row & 7)) << 4));
            }
            if (B_TRANS) {
                const int krow = ks * 16 + bt_k_lo;
                #pragma unroll
                for (int nb = 0; nb < 4; nb++) {
                    const int n = wn * 64 + nb * 16 + bt_n8;
                    const uint32_t addr = stB
                        + (uint32_t)((krow * 2 + (n >> 6)) * 128)
                        + (uint32_t)((((n >> 3) & 7) ^ (krow & 7)) << 4);
                    ldsm_x4_t(bF[nb], addr);
                }
            } else {
                #pragma unroll
                for (int nb = 0; nb < 4; nb++) {
                    const int row = wn * 64 + nb * 16 + b_row_lo;
                    const int ch  = ks * 2 + b_sel;
                    ldsm_x4(bF[nb], stB + (uint32_t)row * 128u + (uint32_t)((ch ^ (row & 7)) << 4));
                }
            }
            #pragma unroll
            for (int mi = 0; mi < 4; mi++)
                #pragma unroll
                for (int nj = 0; nj < 8; nj++)
                    mma16816(acc[mi][nj], aF[mi],
                             bF[nj >> 1][(nj & 1) * 2], bF[nj >> 1][(nj & 1) * 2 + 1]);
        }
    }

    const int m0 = bm + wm * 64;
    const int n0 = bn + wn * 64;
    #pragma unroll
    for (int mi = 0; mi < 4; mi++) {
        const int r0 = m0 + mi * 16 + (lane >> 2);
        const int r1 = r0 + 8;
        float br0 = 0.f, br1 = 0.f;
        if (BIAS_MODE == 1) { br0 = bias[r0]; br1 = bias[r1]; }
        float bq0 = 0.f, bq1 = 0.f, vv0 = 0.f, vv1 = 0.f;
        if (BIAS_MODE == 3) {
            bq0 = bias[r0]; bq1 = bias[r1];
            vv0 = uv[r0];   vv1 = uv[r1];
        }
        #pragma unroll
        for (int nj = 0; nj < 8; nj++) {
            const int c0 = n0 + nj * 8 + (lane & 3) * 2;
            float v0 = acc[mi][nj][0];
            float v1 = acc[mi][nj][1];
            float v2 = acc[mi][nj][2];
            float v3 = acc[mi][nj][3];
            if (BIAS_MODE == 3) {
                const float bkc0 = bias[512 + c0], bkc1 = bias[512 + c0 + 1];
                const float uc0  = uv[512 + c0],   uc1  = uv[512 + c0 + 1];
                v0 += vv0 * bkc0 + bq0 * uc0;
                v1 += vv0 * bkc1 + bq0 * uc1;
                v2 += vv1 * bkc0 + bq1 * uc0;
                v3 += vv1 * bkc1 + bq1 * uc1;
            }
            v0 *= alpha; v1 *= alpha; v2 *= alpha; v3 *= alpha;
            if (BIAS_MODE == 1) { v0 += br0; v1 += br0; v2 += br1; v3 += br1; }
            if (ADD_RES) {
                const float2 q0 = __half22float2(*(const __half2*)&res[(size_t)r0 * ldres + c0]);
                const float2 q1 = __half22float2(*(const __half2*)&res[(size_t)r1 * ldres + c0]);
                v0 += q0.x; v1 += q0.y; v2 += q1.x; v3 += q1.y;
            }
            if constexpr (sizeof(OutT) == 2) {
                *reinterpret_cast<__half2*>(&D[(size_t)r0 * ldd + c0]) = __floats2half2_rn(v0, v1);
                *reinterpret_cast<__half2*>(&D[(size_t)r1 * ldd + c0]) = __floats2half2_rn(v2, v3);
            } else {
                *reinterpret_cast<float2*>(&D[(size_t)r0 * ldd + c0]) = make_float2(v0, v1);
                *reinterpret_cast<float2*>(&D[(size_t)r1 * ldd + c0]) = make_float2(v2, v3);
            }
        }
    }
}

// ---------------- plain GEMM wrapper ----------------------------------------
template<typename OutT, int BIAS_MODE, bool ADD_RES, bool B_TRANS>
__global__ __launch_bounds__(128, 2) void hgemm_kernel(
    const __half* __restrict__ A, long long sA, int lda,
    const __half* __restrict__ B, long long sB, int ldb,
    OutT* __restrict__ D, long long sD, int ldd,
    int K,
    const float* __restrict__ bias, long long sBias,
    const __half* __restrict__ res, long long sRes, int ldres,
    const float* __restrict__ uv,
    float alpha)
{
    extern __shared__ __align__(128) char smem[];
    gemm_core<OutT, BIAS_MODE, ADD_RES, B_TRANS>(
        blockIdx.x, blockIdx.y, blockIdx.z, smem_u32(smem),
        A, sA, lda, B, sB, ldb, D, sD, ldd, K, bias, sBias,
        res, sRes, ldres, uv, alpha);
}

// ---------------- fused Gram + u/v matvec launch -----------------------------
// ids [0,512): G = xn·xn^T    ids [512,768): u/v matvec
__global__ __launch_bounds__(128, 2) void fused_g_uv_kernel(
    const __half* __restrict__ xnh, __half* __restrict__ gram,
    const float* __restrict__ qkvw, const float* __restrict__ qkvb,
    const float* __restrict__ srow, float* __restrict__ uv)
{
    extern __shared__ __align__(128) char smem[];
    const uint32_t sbase = smem_u32(smem);
    const long long sXN  = (long long)C * L;
    const long long sATT = (long long)C * C;
    const int tid = threadIdx.x;

    int id = blockIdx.x;
    if (id < 512) {
        gemm_core<__half, 0, false, false>(
            id & 3, (id >> 2) & 3, id >> 4, sbase,
            xnh, sXN, L, xnh, sXN, L,
            gram, sATT, C, L, nullptr, 0LL, nullptr, 0LL, 0, nullptr, 1.0f);
    } else {
        id -= 512;                         // 0..255
        const int b = id >> 3;
        const int r = (id & 7) * 128 + tid;
        float* ss = (float*)smem;
        for (int i = tid; i < C; i += 128) ss[i] = srow[b * C + i];
        __syncthreads();
        const float4* w4 = (const float4*)(qkvw + (size_t)r * C);
        float d = 0.f;
        #pragma unroll 4
        for (int i = 0; i < C / 4; i++) {
            const float4 wv4 = w4[i];
            d += wv4.x * ss[i*4] + wv4.y * ss[i*4+1]
               + wv4.z * ss[i*4+2] + wv4.w * ss[i*4+3];
        }
        if (r >= 512) d += (float)L * qkvb[r];
        uv[b * 1024 + r] = d;
    }
}

// ---------------- fused MWv GEMM + e matvec launch ---------------------------
// ids [0,512): MWv = M·Wv (trans-B)   ids [512,640): e = M·bv + proj_b
__global__ __launch_bounds__(128, 2) void fused_mwv_kernel(
    const __half* __restrict__ pm, const __half* __restrict__ wv,
    __half* __restrict__ mwv,
    const float* __restrict__ bv, const float* __restrict__ projb,
    float* __restrict__ e)
{
    extern __shared__ __align__(128) char smem[];
    const uint32_t sbase = smem_u32(smem);
    const long long sATT = (long long)C * C;
    const int tid = threadIdx.x;

    int id = blockIdx.x;
    if (id < 512) {
        // MWv[o,c] = Σ_k M[o,k]·Wv[k,c]  (trans-B, M=N=K=512)
        gemm_core<__half, 0, false, true>(
            id & 3, (id >> 2) & 3, id >> 4, sbase,
            pm, sATT, C, wv, 0LL, C,
            mwv, sATT, C, C, nullptr, 0LL, nullptr, 0LL, 0, nullptr, 1.0f);
    } else {
        id -= 512;                         // 0..127
        const int b = id >> 2;
        const int o = (id & 3) * 128 + tid;
        float* sbv = (float*)smem;
        for (int i = tid; i < C; i += 128) sbv[i] = bv[i];
        __syncthreads();
        const __half2* m2 = (const __half2*)(pm + (size_t)b * C * C + (size_t)o * C);
        float d = 0.f;
        #pragma unroll 4
        for (int i = 0; i < C / 2; i++) {
            const float2 mv = __half22float2(m2[i]);
            d += mv.x * sbv[i*2] + mv.y * sbv[i*2+1];
        }
        e[b * C + o] = d + projb[o];
    }
}

// ---------------------------------------------------------------------------
extern "C" void kernel_launch(void* const* d_in, const int* in_sizes, int n_in,
                              void* d_out, int out_size)
{
    const float* x      = (const float*)d_in[0];
    const float* gn_w   = (const float*)d_in[1];
    const float* gn_b   = (const float*)d_in[2];
    const float* qkv_w  = (const float*)d_in[3];
    const float* qkv_b  = (const float*)d_in[4];
    const float* proj_w = (const float*)d_in[5];
    const float* proj_b = (const float*)d_in[6];
    float* out = (float*)d_out;

    __half *xnh, *gram, *t1, *logits, *attn, *pm, *mwv, *wh;
    float *srow, *uv, *e;
    cudaGetSymbolAddress((void**)&xnh,    g_xnh);
    cudaGetSymbolAddress((void**)&gram,   g_gram);
    cudaGetSymbolAddress((void**)&t1,     g_t1);
    cudaGetSymbolAddress((void**)&logits, g_logits);
    cudaGetSymbolAddress((void**)&attn,   g_attn);
    cudaGetSymbolAddress((void**)&pm,     g_pm);
    cudaGetSymbolAddress((void**)&mwv,    g_mwv);
    cudaGetSymbolAddress((void**)&wh,     g_wh);
    cudaGetSymbolAddress((void**)&srow,   g_s);
    cudaGetSymbolAddress((void**)&uv,     g_uv);
    cudaGetSymbolAddress((void**)&e,      g_e);

    cudaFuncSetAttribute(hgemm_kernel<__half, 0, false, false>, cudaFuncAttributeMaxDynamicSharedMemorySize, GEMM_SMEM);
    cudaFuncSetAttribute(hgemm_kernel<__half, 3, false, false>, cudaFuncAttributeMaxDynamicSharedMemorySize, GEMM_SMEM);
    cudaFuncSetAttribute(hgemm_kernel<__half, 0, false, true>,  cudaFuncAttributeMaxDynamicSharedMemorySize, GEMM_SMEM);
    cudaFuncSetAttribute(hgemm_kernel<float,  1, true,  true>,  cudaFuncAttributeMaxDynamicSharedMemorySize, GEMM_SMEM);
    cudaFuncSetAttribute(fused_g_uv_kernel, cudaFuncAttributeMaxDynamicSharedMemorySize, GEMM_SMEM);
    cudaFuncSetAttribute(fused_mwv_kernel,  cudaFuncAttributeMaxDynamicSharedMemorySize, GEMM_SMEM);

    const long long sXN  = (long long)C * L;
    const long long sATT = (long long)C * C;

    // 1) GroupNorm -> xnh fp16 (+ row sums s, + weight convert)
    gn_cvt_kernel<<<BATCH * GROUPS + 1024, 256>>>(
        x, gn_w, gn_b, xnh, qkv_w, proj_w, wh, srow);

    // 2) fused: G = xn·xn^T + u/v matvecs
    fused_g_uv_kernel<<<512 + 256, 128, GEMM_SMEM>>>(
        xnh, gram, qkv_w, qkv_b, srow, uv);

    // 3) T1 = Wq·G  (NT, M=N=K=512)
    {
        dim3 grid(C / 128, C / 128, BATCH);
        hgemm_kernel<__half, 0, false, false><<<grid, 128, GEMM_SMEM>>>(
            wh, 0LL, C, gram, sATT, C, t1, sATT, C, C,
            nullptr, 0LL, nullptr, 0LL, 0, nullptr, 1.0f);
    }
    // 4) logits = (T1·Wk^T + v⊗bk + bq⊗u) / 64  (NT, rank-1 epilogue)
    {
        dim3 grid(C / 128, C / 128, BATCH);
        hgemm_kernel<__half, 3, false, false><<<grid, 128, GEMM_SMEM>>>(
            t1, sATT, C, wh + (size_t)512 * C, 0LL, C, logits, sATT, C, C,
            qkv_b, 0LL, nullptr, 0LL, 0, uv, 0.015625f);
    }
    // 5) softmax -> attn fp16
    softmax512_kernel<<<BATCH * C, 128>>>(logits, attn);

    // 6) M[o,k] = Σ_q P[o,q]·attn[q,k]  (trans-B, M=N=K=512)
    {
        dim3 grid(C / 128, C / 128, BATCH);
        hgemm_kernel<__half, 0, false, true><<<grid, 128, GEMM_SMEM>>>(
            wh + (size_t)3 * C * C, 0LL, C, attn, sATT, C, pm, sATT, C, C,
            nullptr, 0LL, nullptr, 0LL, 0, nullptr, 1.0f);
    }
    // 7) fused: MWv = M·Wv (trans-B) + e = M·bv + proj_b
    fused_mwv_kernel<<<512 + 128, 128, GEMM_SMEM>>>(
        pm, wh + (size_t)1024 * C, mwv,
        qkv_b + 1024, proj_b, e);

    // 8) out[o,l] = MWv[o,:]·xn[:,l] + e[b][o] + xnh[o,l]  (trans-B)
    {
        dim3 grid(L / 128, C / 128, BATCH);
        hgemm_kernel<float, 1, true, true><<<grid, 128, GEMM_SMEM>>>(
            mwv, sATT, C, xnh, sXN, L, out, sXN, L, C,
            e, (long long)C, xnh, sXN, L, nullptr, 1.0f);
    }
}

// round 13
// speedup vs baseline: 15.2041x; 1.0089x over previous
#include <cuda_runtime.h>
#include <cuda_fp16.h>
#include <cstdint>
#include <math.h>

#define BATCH 32
#define C 512
#define L 4096
#define GROUPS 32
#define CPG 16
#define EPS 1e-5f

// ---------------- scratch (device globals; allocation-free rule) -----------
__device__ __align__(256) __half g_xnh   [(size_t)BATCH * C * L];   // [C,L] normed
__device__ __align__(256) __half g_gram  [(size_t)BATCH * C * C];   // G = xn·xn^T
__device__ __align__(256) __half g_t1    [(size_t)BATCH * C * C];   // Wq·G
__device__ __align__(256) __half g_logits[(size_t)BATCH * C * C];
__device__ __align__(256) __half g_attn  [(size_t)BATCH * C * C];
__device__ __align__(256) __half g_pm    [(size_t)BATCH * C * C];   // M = P·attn
__device__ __align__(256) __half g_mwv   [(size_t)BATCH * C * C];   // M·Wv + I
__device__ __align__(256) __half g_wh    [(size_t)4 * C * C];       // qkv_w + proj_w (fp16)
__device__ __align__(256) float  g_s     [(size_t)BATCH * C];       // row sums of xn
__device__ __align__(256) float  g_uv    [(size_t)BATCH * 1024];    // [v=Wq·s | u=Wk·s+L·bk]
__device__ __align__(256) float  g_e     [(size_t)BATCH * C];       // e = M·bv + proj_b

// ---------------- PTX helpers ----------------------------------------------
__device__ __forceinline__ uint32_t smem_u32(const void* p) {
    uint32_t a;
    asm("{ .reg .u64 t; cvta.to.shared.u64 t, %1; cvt.u32.u64 %0, t; }" : "=r"(a) : "l"(p));
    return a;
}
#define CP_ASYNC16(dst, src) \
    asm volatile("cp.async.cg.shared.global [%0], [%1], 16;" :: "r"(dst), "l"(src) : "memory")
#define CP_COMMIT() asm volatile("cp.async.commit_group;" ::: "memory")
#define CP_WAIT1()  asm volatile("cp.async.wait_group 1;" ::: "memory")
#define CP_WAIT0()  asm volatile("cp.async.wait_group 0;" ::: "memory")

__device__ __forceinline__ void ldsm_x4(uint32_t (&r)[4], uint32_t addr) {
    asm volatile("ldmatrix.sync.aligned.m8n8.x4.shared.b16 {%0,%1,%2,%3}, [%4];"
        : "=r"(r[0]), "=r"(r[1]), "=r"(r[2]), "=r"(r[3]) : "r"(addr));
}
__device__ __forceinline__ void ldsm_x4_t(uint32_t (&r)[4], uint32_t addr) {
    asm volatile("ldmatrix.sync.aligned.m8n8.x4.trans.shared.b16 {%0,%1,%2,%3}, [%4];"
        : "=r"(r[0]), "=r"(r[1]), "=r"(r[2]), "=r"(r[3]) : "r"(addr));
}
__device__ __forceinline__ void mma16816(float (&d)[4], const uint32_t (&a)[4],
                                         uint32_t b0, uint32_t b1) {
    asm volatile(
        "mma.sync.aligned.m16n8k16.row.col.f32.f16.f16.f32 "
        "{%0,%1,%2,%3}, {%4,%5,%6,%7}, {%8,%9}, {%0,%1,%2,%3};"
        : "+f"(d[0]), "+f"(d[1]), "+f"(d[2]), "+f"(d[3])
        : "r"(a[0]), "r"(a[1]), "r"(a[2]), "r"(a[3]), "r"(b0), "r"(b1));
}

// ---------------- GroupNorm (+weight convert, +row sums) fused launch -------
// blocks [0,1024): GN via 128KB smem staging (single DRAM read of x).
// blocks [1024,2048): weight fp32->fp16.
#define GN_SMEM 131072
__global__ __launch_bounds__(256) void gn_cvt_kernel(
    const float* __restrict__ x, const float* __restrict__ gw,
    const float* __restrict__ gb, __half* __restrict__ xnh,
    const float* __restrict__ qkvw, const float* __restrict__ projw,
    __half* __restrict__ wh, float* __restrict__ srow)
{
    extern __shared__ __align__(16) char dsm[];
    const int bid = blockIdx.x;
    const int tid = threadIdx.x;

    if (bid >= BATCH * GROUPS) {
        const int i4 = (bid - BATCH * GROUPS) * 256 + tid;
        const int n_qkv4 = 3 * C * C / 4;
        float4 v;
        if (i4 < n_qkv4) v = ((const float4*)qkvw)[i4];
        else             v = ((const float4*)projw)[i4 - n_qkv4];
        __half2* o = (__half2*)(wh + (size_t)i4 * 4);
        o[0] = __floats2half2_rn(v.x, v.y);
        o[1] = __floats2half2_rn(v.z, v.w);
        return;
    }

    const int b = bid / GROUPS;
    const int g = bid % GROUPS;
    const size_t base = ((size_t)b * C + (size_t)g * CPG) * L;
    const float4* px4 = (const float4*)(x + base);
    __half2* outh = (__half2*)(xnh + base);
    __half2* xs = (__half2*)dsm;          // 32768 half2 = 128KB

    // pass 1: read fp32 once, stage fp16 copy in smem, accumulate stats
    float s = 0.f, ss = 0.f;
    #pragma unroll 4
    for (int j = 0; j < 64; j++) {
        const int i = tid + 256 * j;
        float4 v = px4[i];
        s  += v.x + v.y + v.z + v.w;
        ss += v.x*v.x + v.y*v.y + v.z*v.z + v.w*v.w;
        xs[i * 2 + 0] = __floats2half2_rn(v.x, v.y);
        xs[i * 2 + 1] = __floats2half2_rn(v.z, v.w);
    }
    __shared__ float sh_s[32], sh_ss[32];
    for (int o = 16; o > 0; o >>= 1) {
        s  += __shfl_down_sync(0xffffffff, s, o);
        ss += __shfl_down_sync(0xffffffff, ss, o);
    }
    if ((tid & 31) == 0) { sh_s[tid >> 5] = s; sh_ss[tid >> 5] = ss; }
    __syncthreads();
    if (tid < 32) {
        s  = (tid < 8) ? sh_s[tid]  : 0.f;
        ss = (tid < 8) ? sh_ss[tid] : 0.f;
        for (int o = 4; o > 0; o >>= 1) {
            s  += __shfl_down_sync(0xffffffff, s, o);
            ss += __shfl_down_sync(0xffffffff, ss, o);
        }
        if (tid == 0) { sh_s[0] = s; sh_ss[0] = ss; }
    }
    __syncthreads();
    const float inv_n = 1.f / (float)(CPG * L);
    const float mean  = sh_s[0] * inv_n;
    const float var   = sh_ss[0] * inv_n - mean * mean;
    const float rstd  = rsqrtf(var + EPS);

    // pass 2: normalize from smem, write fp16, accumulate per-channel sums
    float csum[16];
    #pragma unroll
    for (int c = 0; c < 16; c++) csum[c] = 0.f;

    for (int j = 0; j < 64; j++) {
        const int i = tid + 256 * j;
        const int ch = j >> 2;
        const float w = gw[g * CPG + ch] * rstd;
        const float bb = gb[g * CPG + ch] - mean * w;
        const float2 fa = __half22float2(xs[i * 2 + 0]);
        const float2 fb = __half22float2(xs[i * 2 + 1]);
        const float e0 = fmaf(fa.x, w, bb), e1 = fmaf(fa.y, w, bb);
        const float e2 = fmaf(fb.x, w, bb), e3 = fmaf(fb.y, w, bb);
        outh[i * 2 + 0] = __floats2half2_rn(e0, e1);
        outh[i * 2 + 1] = __floats2half2_rn(e2, e3);
        csum[ch] += (e0 + e1) + (e2 + e3);
    }
    __shared__ float s_part[16][8];
    #pragma unroll
    for (int c = 0; c < 16; c++) {
        float t = csum[c];
        for (int o = 16; o > 0; o >>= 1) t += __shfl_down_sync(0xffffffff, t, o);
        if ((tid & 31) == 0) s_part[c][tid >> 5] = t;
    }
    __syncthreads();
    if (tid < 16) {
        float t = 0.f;
        #pragma unroll
        for (int w8 = 0; w8 < 8; w8++) t += s_part[tid][w8];
        srow[b * C + g * CPG + tid] = t;
    }
}

// ---------------- Row softmax (fp16 in, fp16 out) ---------------------------
__global__ __launch_bounds__(128) void softmax512_kernel(
    const __half* __restrict__ logits, __half* __restrict__ attn)
{
    const size_t row = blockIdx.x;
    const __half2* p = (const __half2*)(logits + row * C);
    const int tid = threadIdx.x;

    float2 a = __half22float2(p[tid * 2 + 0]);
    float2 b = __half22float2(p[tid * 2 + 1]);
    float m = fmaxf(fmaxf(a.x, a.y), fmaxf(b.x, b.y));
    __shared__ float sh[4];
    for (int o = 16; o > 0; o >>= 1) m = fmaxf(m, __shfl_xor_sync(0xffffffff, m, o));
    if ((tid & 31) == 0) sh[tid >> 5] = m;
    __syncthreads();
    m = fmaxf(fmaxf(sh[0], sh[1]), fmaxf(sh[2], sh[3]));

    a.x = expf(a.x - m); a.y = expf(a.y - m);
    b.x = expf(b.x - m); b.y = expf(b.y - m);
    float s = a.x + a.y + b.x + b.y;
    for (int o = 16; o > 0; o >>= 1) s += __shfl_xor_sync(0xffffffff, s, o);
    __shared__ float shs[4];
    if ((tid & 31) == 0) shs[tid >> 5] = s;
    __syncthreads();
    s = shs[0] + shs[1] + shs[2] + shs[3];
    const float inv = 1.f / s;

    __half2* o2 = (__half2*)(attn + row * C);
    o2[tid * 2 + 0] = __floats2half2_rn(a.x * inv, a.y * inv);
    o2[tid * 2 + 1] = __floats2half2_rn(b.x * inv, b.y * inv);
}

// ---------------- fp16 tensor-core GEMM core --------------------------------
// BIAS_MODE: 0 none, 1 row bias (per-batch via sBias), 3 rank-1 logits epilogue
// ADD_IDENT: add identity matrix to output (out = alpha*acc + I [+bias...])
#define STAGE_BYTES 32768          // A 16KB + B 16KB
#define GEMM_SMEM  (3 * STAGE_BYTES)

__device__ __forceinline__ void load_A(const __half* __restrict__ gA, int lda,
                                       uint32_t st, int tid)
{
    #pragma unroll
    for (int j = 0; j < 8; j++) {
        const int slot = tid + 128 * j;
        const int row  = slot >> 3;
        const int c    = slot & 7;
        const uint32_t off = (uint32_t)row * 128u + (uint32_t)((c ^ (row & 7)) << 4);
        CP_ASYNC16(st + off, gA + (size_t)row * lda + c * 8);
    }
}
__device__ __forceinline__ void load_B_nt(const __half* __restrict__ gB, int ldb,
                                          uint32_t st, int tid)
{
    #pragma unroll
    for (int j = 0; j < 8; j++) {
        const int slot = tid + 128 * j;
        const int row  = slot >> 3;
        const int c    = slot & 7;
        const uint32_t off = (uint32_t)row * 128u + (uint32_t)((c ^ (row & 7)) << 4);
        CP_ASYNC16(st + off, gB + (size_t)row * ldb + c * 8);
    }
}
__device__ __forceinline__ void load_B_t(const __half* __restrict__ gB, int ldb,
                                         uint32_t st, int tid)
{
    #pragma unroll
    for (int j = 0; j < 8; j++) {
        const int slot = tid + 128 * j;
        const int row  = slot >> 4;           // 0..63 (k)
        const int c    = slot & 15;           // 16B chunk (n/8)
        const uint32_t off = (uint32_t)((row * 2 + (c >> 3)) * 128)
                           + (uint32_t)(((c & 7) ^ (row & 7)) << 4);
        CP_ASYNC16(st + off, gB + (size_t)row * ldb + c * 8);
    }
}

template<typename OutT, int BIAS_MODE, bool ADD_RES, bool B_TRANS, bool ADD_IDENT>
__device__ __forceinline__ void gemm_core(
    int bx, int by, int bz, uint32_t sbase,
    const __half* __restrict__ A, long long sA, int lda,
    const __half* __restrict__ B, long long sB, int ldb,
    OutT* __restrict__ D, long long sD, int ldd,
    int K,
    const float* __restrict__ bias, long long sBias,
    const __half* __restrict__ res, long long sRes, int ldres,
    const float* __restrict__ uv,
    float alpha)
{
    A += (size_t)bz * sA;
    B += (size_t)bz * sB;
    D += (size_t)bz * sD;
    if (ADD_RES) res += (size_t)bz * sRes;
    if (BIAS_MODE == 1) bias += (size_t)bz * sBias;
    if (BIAS_MODE == 3) uv += (size_t)bz * 1024;

    const int bm = by * 128;
    const int bn = bx * 128;
    const int tid = threadIdx.x;
    const int lane = tid & 31;
    const int wid = tid >> 5;
    const int wm = wid & 1;
    const int wn = wid >> 1;

    const __half* gA = A + (size_t)bm * lda;
    const __half* gB = B_TRANS ? (B + bn) : (B + (size_t)bn * ldb);
    const int T = K >> 6;

    const int a_row_lo = lane & 15;
    const int a_sel    = lane >> 4;
    const int b_row_lo = (lane & 7) + ((lane >> 4) << 3);
    const int b_sel    = (lane >> 3) & 1;
    const int bt_k_lo  = lane & 15;
    const int bt_n8    = (lane >> 4) << 3;

    float acc[4][8][4];
    #pragma unroll
    for (int i = 0; i < 4; i++)
        #pragma unroll
        for (int j = 0; j < 8; j++)
            #pragma unroll
            for (int q = 0; q < 4; q++) acc[i][j][q] = 0.f;

    #pragma unroll
    for (int s = 0; s < 2; s++) {
        const uint32_t st = sbase + s * STAGE_BYTES;
        load_A(gA + s * 64, lda, st, tid);
        if (B_TRANS) load_B_t(gB + (size_t)(s * 64) * ldb, ldb, st + 16384, tid);
        else         load_B_nt(gB + s * 64, ldb, st + 16384, tid);
        CP_COMMIT();
    }

    for (int t = 0; t < T; t++) {
        if (t < T - 1) CP_WAIT1(); else CP_WAIT0();
        __syncthreads();

        if (t + 2 < T) {
            const int s = t + 2;
            const uint32_t st = sbase + (s % 3) * STAGE_BYTES;
            load_A(gA + s * 64, lda, st, tid);
            if (B_TRANS) load_B_t(gB + (size_t)(s * 64) * ldb, ldb, st + 16384, tid);
            else         load_B_nt(gB + s * 64, ldb, st + 16384, tid);
            CP_COMMIT();
        }

        const uint32_t stA = sbase + (t % 3) * STAGE_BYTES;
        const uint32_t stB = stA + 16384;

        #pragma unroll
        for (int ks = 0; ks < 4; ks++) {
            uint32_t aF[4][4];
            uint32_t bF[4][4];
            #pragma unroll
            for (int mi = 0; mi < 4; mi++) {
                const int row = wm * 64 + mi * 16 + a_row_lo;
                const int ch  = ks * 2 + a_sel;
                ldsm_x4(aF[mi], stA + (uint32_t)row * 128u + (uint32_t)((ch ^ (row & 7)) << 4));
            }
            if (B_TRANS) {
                const int krow = ks * 16 + bt_k_lo;
                #pragma unroll
                for (int nb = 0; nb < 4; nb++) {
                    const int n = wn * 64 + nb * 16 + bt_n8;
                    const uint32_t addr = stB
                        + (uint32_t)((krow * 2 + (n >> 6)) * 128)
                        + (uint32_t)((((n >> 3) & 7) ^ (krow & 7)) << 4);
                    ldsm_x4_t(bF[nb], addr);
                }
            } else {
                #pragma unroll
                for (int nb = 0; nb < 4; nb++) {
                    const int row = wn * 64 + nb * 16 + b_row_lo;
                    const int ch  = ks * 2 + b_sel;
                    ldsm_x4(bF[nb], stB + (uint32_t)row * 128u + (uint32_t)((ch ^ (row & 7)) << 4));
                }
            }
            #pragma unroll
            for (int mi = 0; mi < 4; mi++)
                #pragma unroll
                for (int nj = 0; nj < 8; nj++)
                    mma16816(acc[mi][nj], aF[mi],
                             bF[nj >> 1][(nj & 1) * 2], bF[nj >> 1][(nj & 1) * 2 + 1]);
        }
    }

    const int m0 = bm + wm * 64;
    const int n0 = bn + wn * 64;
    #pragma unroll
    for (int mi = 0; mi < 4; mi++) {
        const int r0 = m0 + mi * 16 + (lane >> 2);
        const int r1 = r0 + 8;
        float br0 = 0.f, br1 = 0.f;
        if (BIAS_MODE == 1) { br0 = bias[r0]; br1 = bias[r1]; }
        float bq0 = 0.f, bq1 = 0.f, vv0 = 0.f, vv1 = 0.f;
        if (BIAS_MODE == 3) {
            bq0 = bias[r0]; bq1 = bias[r1];
            vv0 = uv[r0];   vv1 = uv[r1];
        }
        #pragma unroll
        for (int nj = 0; nj < 8; nj++) {
            const int c0 = n0 + nj * 8 + (lane & 3) * 2;
            float v0 = acc[mi][nj][0];
            float v1 = acc[mi][nj][1];
            float v2 = acc[mi][nj][2];
            float v3 = acc[mi][nj][3];
            if (BIAS_MODE == 3) {
                const float bkc0 = bias[512 + c0], bkc1 = bias[512 + c0 + 1];
                const float uc0  = uv[512 + c0],   uc1  = uv[512 + c0 + 1];
                v0 += vv0 * bkc0 + bq0 * uc0;
                v1 += vv0 * bkc1 + bq0 * uc1;
                v2 += vv1 * bkc0 + bq1 * uc0;
                v3 += vv1 * bkc1 + bq1 * uc1;
            }
            v0 *= alpha; v1 *= alpha; v2 *= alpha; v3 *= alpha;
            if (ADD_IDENT) {
                if (r0 == c0)     v0 += 1.f;
                if (r0 == c0 + 1) v1 += 1.f;
                if (r1 == c0)     v2 += 1.f;
                if (r1 == c0 + 1) v3 += 1.f;
            }
            if (BIAS_MODE == 1) { v0 += br0; v1 += br0; v2 += br1; v3 += br1; }
            if (ADD_RES) {
                const float2 q0 = __half22float2(*(const __half2*)&res[(size_t)r0 * ldres + c0]);
                const float2 q1 = __half22float2(*(const __half2*)&res[(size_t)r1 * ldres + c0]);
                v0 += q0.x; v1 += q0.y; v2 += q1.x; v3 += q1.y;
            }
            if constexpr (sizeof(OutT) == 2) {
                *reinterpret_cast<__half2*>(&D[(size_t)r0 * ldd + c0]) = __floats2half2_rn(v0, v1);
                *reinterpret_cast<__half2*>(&D[(size_t)r1 * ldd + c0]) = __floats2half2_rn(v2, v3);
            } else {
                *reinterpret_cast<float2*>(&D[(size_t)r0 * ldd + c0]) = make_float2(v0, v1);
                *reinterpret_cast<float2*>(&D[(size_t)r1 * ldd + c0]) = make_float2(v2, v3);
            }
        }
    }
}

// ---------------- plain GEMM wrapper ----------------------------------------
template<typename OutT, int BIAS_MODE, bool ADD_RES, bool B_TRANS, bool ADD_IDENT>
__global__ __launch_bounds__(128, 2) void hgemm_kernel(
    const __half* __restrict__ A, long long sA, int lda,
    const __half* __restrict__ B, long long sB, int ldb,
    OutT* __restrict__ D, long long sD, int ldd,
    int K,
    const float* __restrict__ bias, long long sBias,
    const __half* __restrict__ res, long long sRes, int ldres,
    const float* __restrict__ uv,
    float alpha)
{
    extern __shared__ __align__(128) char smem[];
    gemm_core<OutT, BIAS_MODE, ADD_RES, B_TRANS, ADD_IDENT>(
        blockIdx.x, blockIdx.y, blockIdx.z, smem_u32(smem),
        A, sA, lda, B, sB, ldb, D, sD, ldd, K, bias, sBias,
        res, sRes, ldres, uv, alpha);
}

// ---------------- fused Gram + u/v matvec launch -----------------------------
__global__ __launch_bounds__(128, 2) void fused_g_uv_kernel(
    const __half* __restrict__ xnh, __half* __restrict__ gram,
    const float* __restrict__ qkvw, const float* __restrict__ qkvb,
    const float* __restrict__ srow, float* __restrict__ uv)
{
    extern __shared__ __align__(128) char smem[];
    const uint32_t sbase = smem_u32(smem);
    const long long sXN  = (long long)C * L;
    const long long sATT = (long long)C * C;
    const int tid = threadIdx.x;

    int id = blockIdx.x;
    if (id < 512) {
        gemm_core<__half, 0, false, false, false>(
            id & 3, (id >> 2) & 3, id >> 4, sbase,
            xnh, sXN, L, xnh, sXN, L,
            gram, sATT, C, L, nullptr, 0LL, nullptr, 0LL, 0, nullptr, 1.0f);
    } else {
        id -= 512;
        const int b = id >> 3;
        const int r = (id & 7) * 128 + tid;
        float* ss = (float*)smem;
        for (int i = tid; i < C; i += 128) ss[i] = srow[b * C + i];
        __syncthreads();
        const float4* w4 = (const float4*)(qkvw + (size_t)r * C);
        float d = 0.f;
        #pragma unroll 4
        for (int i = 0; i < C / 4; i++) {
            const float4 wv4 = w4[i];
            d += wv4.x * ss[i*4] + wv4.y * ss[i*4+1]
               + wv4.z * ss[i*4+2] + wv4.w * ss[i*4+3];
        }
        if (r >= 512) d += (float)L * qkvb[r];
        uv[b * 1024 + r] = d;
    }
}

// ---------------- fused MWv GEMM (+I) + e matvec launch ----------------------
__global__ __launch_bounds__(128, 2) void fused_mwv_kernel(
    const __half* __restrict__ pm, const __half* __restrict__ wv,
    __half* __restrict__ mwv,
    const float* __restrict__ bv, const float* __restrict__ projb,
    float* __restrict__ e)
{
    extern __shared__ __align__(128) char smem[];
    const uint32_t sbase = smem_u32(smem);
    const long long sATT = (long long)C * C;
    const int tid = threadIdx.x;

    int id = blockIdx.x;
    if (id < 512) {
        // MWv[o,c] = Σ_k M[o,k]·Wv[k,c] + I  (trans-B, M=N=K=512)
        gemm_core<__half, 0, false, true, true>(
            id & 3, (id >> 2) & 3, id >> 4, sbase,
            pm, sATT, C, wv, 0LL, C,
            mwv, sATT, C, C, nullptr, 0LL, nullptr, 0LL, 0, nullptr, 1.0f);
    } else {
        id -= 512;
        const int b = id >> 2;
        const int o = (id & 3) * 128 + tid;
        float* sbv = (float*)smem;
        for (int i = tid; i < C; i += 128) sbv[i] = bv[i];
        __syncthreads();
        const __half2* m2 = (const __half2*)(pm + (size_t)b * C * C + (size_t)o * C);
        float d = 0.f;
        #pragma unroll 4
        for (int i = 0; i < C / 2; i++) {
            const float2 mv = __half22float2(m2[i]);
            d += mv.x * sbv[i*2] + mv.y * sbv[i*2+1];
        }
        e[b * C + o] = d + projb[o];
    }
}

// ---------------------------------------------------------------------------
extern "C" void kernel_launch(void* const* d_in, const int* in_sizes, int n_in,
                              void* d_out, int out_size)
{
    const float* x      = (const float*)d_in[0];
    const float* gn_w   = (const float*)d_in[1];
    const float* gn_b   = (const float*)d_in[2];
    const float* qkv_w  = (const float*)d_in[3];
    const float* qkv_b  = (const float*)d_in[4];
    const float* proj_w = (const float*)d_in[5];
    const float* proj_b = (const float*)d_in[6];
    float* out = (float*)d_out;

    __half *xnh, *gram, *t1, *logits, *attn, *pm, *mwv, *wh;
    float *srow, *uv, *e;
    cudaGetSymbolAddress((void**)&xnh,    g_xnh);
    cudaGetSymbolAddress((void**)&gram,   g_gram);
    cudaGetSymbolAddress((void**)&t1,     g_t1);
    cudaGetSymbolAddress((void**)&logits, g_logits);
    cudaGetSymbolAddress((void**)&attn,   g_attn);
    cudaGetSymbolAddress((void**)&pm,     g_pm);
    cudaGetSymbolAddress((void**)&mwv,    g_mwv);
    cudaGetSymbolAddress((void**)&wh,     g_wh);
    cudaGetSymbolAddress((void**)&srow,   g_s);
    cudaGetSymbolAddress((void**)&uv,     g_uv);
    cudaGetSymbolAddress((void**)&e,      g_e);

    cudaFuncSetAttribute(gn_cvt_kernel, cudaFuncAttributeMaxDynamicSharedMemorySize, GN_SMEM);
    cudaFuncSetAttribute(hgemm_kernel<__half, 0, false, false, false>, cudaFuncAttributeMaxDynamicSharedMemorySize, GEMM_SMEM);
    cudaFuncSetAttribute(hgemm_kernel<__half, 3, false, false, false>, cudaFuncAttributeMaxDynamicSharedMemorySize, GEMM_SMEM);
    cudaFuncSetAttribute(hgemm_kernel<__half, 0, false, true, false>,  cudaFuncAttributeMaxDynamicSharedMemorySize, GEMM_SMEM);
    cudaFuncSetAttribute(hgemm_kernel<float,  1, false, true, false>,  cudaFuncAttributeMaxDynamicSharedMemorySize, GEMM_SMEM);
    cudaFuncSetAttribute(fused_g_uv_kernel, cudaFuncAttributeMaxDynamicSharedMemorySize, GEMM_SMEM);
    cudaFuncSetAttribute(fused_mwv_kernel,  cudaFuncAttributeMaxDynamicSharedMemorySize, GEMM_SMEM);

    const long long sXN  = (long long)C * L;
    const long long sATT = (long long)C * C;

    // 1) GroupNorm -> xnh fp16 (+ row sums s, + weight convert)
    gn_cvt_kernel<<<BATCH * GROUPS + 1024, 256, GN_SMEM>>>(
        x, gn_w, gn_b, xnh, qkv_w, proj_w, wh, srow);

    // 2) fused: G = xn·xn^T + u/v matvecs
    fused_g_uv_kernel<<<512 + 256, 128, GEMM_SMEM>>>(
        xnh, gram, qkv_w, qkv_b, srow, uv);

    // 3) T1 = Wq·G  (NT, M=N=K=512)
    {
        dim3 grid(C / 128, C / 128, BATCH);
        hgemm_kernel<__half, 0, false, false, false><<<grid, 128, GEMM_SMEM>>>(
            wh, 0LL, C, gram, sATT, C, t1, sATT, C, C,
            nullptr, 0LL, nullptr, 0LL, 0, nullptr, 1.0f);
    }
    // 4) logits = (T1·Wk^T + v⊗bk + bq⊗u) / 64  (NT, rank-1 epilogue)
    {
        dim3 grid(C / 128, C / 128, BATCH);
        hgemm_kernel<__half, 3, false, false, false><<<grid, 128, GEMM_SMEM>>>(
            t1, sATT, C, wh + (size_t)512 * C, 0LL, C, logits, sATT, C, C,
            qkv_b, 0LL, nullptr, 0LL, 0, uv, 0.015625f);
    }
    // 5) softmax -> attn fp16
    softmax512_kernel<<<BATCH * C, 128>>>(logits, attn);

    // 6) M[o,k] = Σ_q P[o,q]·attn[q,k]  (trans-B, M=N=K=512)
    {
        dim3 grid(C / 128, C / 128, BATCH);
        hgemm_kernel<__half, 0, false, true, false><<<grid, 128, GEMM_SMEM>>>(
            wh + (size_t)3 * C * C, 0LL, C, attn, sATT, C, pm, sATT, C, C,
            nullptr, 0LL, nullptr, 0LL, 0, nullptr, 1.0f);
    }
    // 7) fused: MWv = M·Wv + I (trans-B) + e = M·bv + proj_b
    fused_mwv_kernel<<<512 + 128, 128, GEMM_SMEM>>>(
        pm, wh + (size_t)1024 * C, mwv,
        qkv_b + 1024, proj_b, e);

    // 8) out[o,l] = (MWv+I)[o,:]·xn[:,l] + e[b][o]  (trans-B; residual folded)
    {
        dim3 grid(L / 128, C / 128, BATCH);
        hgemm_kernel<float, 1, false, true, false><<<grid, 128, GEMM_SMEM>>>(
            mwv, sATT, C, xnh, sXN, L, out, sXN, L, C,
            e, (long long)C, nullptr, 0LL, 0, nullptr, 1.0f);
    }
}

// round 14
// speedup vs baseline: 16.3151x; 1.0731x over previous
#include <cuda_runtime.h>
#include <cuda_fp16.h>
#include <cstdint>
#include <math.h>

#define BATCH 32
#define C 512
#define L 4096
#define GROUPS 32
#define CPG 16
#define EPS 1e-5f

// ---------------- scratch (device globals; allocation-free rule) -----------
__device__ __align__(256) __half g_xnh   [(size_t)BATCH * C * L];   // [C,L] normed
__device__ __align__(256) __half g_gram  [(size_t)BATCH * C * C];   // G = xn·xn^T
__device__ __align__(256) __half g_t1    [(size_t)BATCH * C * C];   // Wq·G
__device__ __align__(256) __half g_logits[(size_t)BATCH * C * C];
__device__ __align__(256) __half g_attn  [(size_t)BATCH * C * C];
__device__ __align__(256) __half g_pm    [(size_t)BATCH * C * C];   // M = P·attn
__device__ __align__(256) __half g_mwv   [(size_t)BATCH * C * C];   // M·Wv + I
__device__ __align__(256) __half g_wh    [(size_t)4 * C * C];       // qkv_w + proj_w (fp16)
__device__ __align__(256) float  g_s     [(size_t)BATCH * C];       // row sums of xn
__device__ __align__(256) float  g_uv    [(size_t)BATCH * 1024];    // [v=Wq·s | u=Wk·s+L·bk]
__device__ __align__(256) float  g_e     [(size_t)BATCH * C];       // e = M·bv + proj_b

// ---------------- PTX helpers ----------------------------------------------
__device__ __forceinline__ uint32_t smem_u32(const void* p) {
    uint32_t a;
    asm("{ .reg .u64 t; cvta.to.shared.u64 t, %1; cvt.u32.u64 %0, t; }" : "=r"(a) : "l"(p));
    return a;
}
#define CP_ASYNC16(dst, src) \
    asm volatile("cp.async.cg.shared.global [%0], [%1], 16;" :: "r"(dst), "l"(src) : "memory")
#define CP_COMMIT() asm volatile("cp.async.commit_group;" ::: "memory")
#define CP_WAIT1()  asm volatile("cp.async.wait_group 1;" ::: "memory")
#define CP_WAIT0()  asm volatile("cp.async.wait_group 0;" ::: "memory")

__device__ __forceinline__ void ldsm_x4(uint32_t (&r)[4], uint32_t addr) {
    asm volatile("ldmatrix.sync.aligned.m8n8.x4.shared.b16 {%0,%1,%2,%3}, [%4];"
        : "=r"(r[0]), "=r"(r[1]), "=r"(r[2]), "=r"(r[3]) : "r"(addr));
}
__device__ __forceinline__ void ldsm_x4_t(uint32_t (&r)[4], uint32_t addr) {
    asm volatile("ldmatrix.sync.aligned.m8n8.x4.trans.shared.b16 {%0,%1,%2,%3}, [%4];"
        : "=r"(r[0]), "=r"(r[1]), "=r"(r[2]), "=r"(r[3]) : "r"(addr));
}
__device__ __forceinline__ void mma16816(float (&d)[4], const uint32_t (&a)[4],
                                         uint32_t b0, uint32_t b1) {
    asm volatile(
        "mma.sync.aligned.m16n8k16.row.col.f32.f16.f16.f32 "
        "{%0,%1,%2,%3}, {%4,%5,%6,%7}, {%8,%9}, {%0,%1,%2,%3};"
        : "+f"(d[0]), "+f"(d[1]), "+f"(d[2]), "+f"(d[3])
        : "r"(a[0]), "r"(a[1]), "r"(a[2]), "r"(a[3]), "r"(b0), "r"(b1));
}

// ---------------- GroupNorm (+weight convert, +row sums) fused launch -------
__global__ __launch_bounds__(256) void gn_cvt_kernel(
    const float* __restrict__ x, const float* __restrict__ gw,
    const float* __restrict__ gb, __half* __restrict__ xnh,
    const float* __restrict__ qkvw, const float* __restrict__ projw,
    __half* __restrict__ wh, float* __restrict__ srow)
{
    const int bid = blockIdx.x;
    const int tid = threadIdx.x;

    if (bid >= BATCH * GROUPS) {
        const int i4 = (bid - BATCH * GROUPS) * 256 + tid;
        const int n_qkv4 = 3 * C * C / 4;
        float4 v;
        if (i4 < n_qkv4) v = ((const float4*)qkvw)[i4];
        else             v = ((const float4*)projw)[i4 - n_qkv4];
        __half2* o = (__half2*)(wh + (size_t)i4 * 4);
        o[0] = __floats2half2_rn(v.x, v.y);
        o[1] = __floats2half2_rn(v.z, v.w);
        return;
    }

    const int b = bid / GROUPS;
    const int g = bid % GROUPS;
    const size_t base = ((size_t)b * C + (size_t)g * CPG) * L;
    const float4* px4 = (const float4*)(x + base);
    __half2* outh = (__half2*)(xnh + base);
    const int n4 = CPG * L / 4;

    float s = 0.f, ss = 0.f;
    for (int i = tid; i < n4; i += 256) {
        float4 v = px4[i];
        s  += v.x + v.y + v.z + v.w;
        ss += v.x*v.x + v.y*v.y + v.z*v.z + v.w*v.w;
    }
    __shared__ float sh_s[32], sh_ss[32];
    for (int o = 16; o > 0; o >>= 1) {
        s  += __shfl_down_sync(0xffffffff, s, o);
        ss += __shfl_down_sync(0xffffffff, ss, o);
    }
    if ((tid & 31) == 0) { sh_s[tid >> 5] = s; sh_ss[tid >> 5] = ss; }
    __syncthreads();
    if (tid < 32) {
        s  = (tid < 8) ? sh_s[tid]  : 0.f;
        ss = (tid < 8) ? sh_ss[tid] : 0.f;
        for (int o = 4; o > 0; o >>= 1) {
            s  += __shfl_down_sync(0xffffffff, s, o);
            ss += __shfl_down_sync(0xffffffff, ss, o);
        }
        if (tid == 0) { sh_s[0] = s; sh_ss[0] = ss; }
    }
    __syncthreads();
    const float inv_n = 1.f / (float)(CPG * L);
    const float mean  = sh_s[0] * inv_n;
    const float var   = sh_ss[0] * inv_n - mean * mean;
    const float rstd  = rsqrtf(var + EPS);

    float csum[16];
    #pragma unroll
    for (int c = 0; c < 16; c++) csum[c] = 0.f;

    for (int j = 0; j < 64; j++) {
        const int i = tid + 256 * j;
        const int ch = j >> 2;
        const float w = gw[g * CPG + ch] * rstd;
        const float bb = gb[g * CPG + ch] - mean * w;
        float4 v = px4[i];
        const float e0 = fmaf(v.x, w, bb), e1 = fmaf(v.y, w, bb);
        const float e2 = fmaf(v.z, w, bb), e3 = fmaf(v.w, w, bb);
        outh[i * 2 + 0] = __floats2half2_rn(e0, e1);
        outh[i * 2 + 1] = __floats2half2_rn(e2, e3);
        csum[ch] += (e0 + e1) + (e2 + e3);
    }
    __shared__ float s_part[16][8];
    #pragma unroll
    for (int c = 0; c < 16; c++) {
        float t = csum[c];
        for (int o = 16; o > 0; o >>= 1) t += __shfl_down_sync(0xffffffff, t, o);
        if ((tid & 31) == 0) s_part[c][tid >> 5] = t;
    }
    __syncthreads();
    if (tid < 16) {
        float t = 0.f;
        #pragma unroll
        for (int w8 = 0; w8 < 8; w8++) t += s_part[tid][w8];
        srow[b * C + g * CPG + tid] = t;
    }
}

// ---------------- Row softmax (fp16 in, fp16 out) ---------------------------
__global__ __launch_bounds__(128) void softmax512_kernel(
    const __half* __restrict__ logits, __half* __restrict__ attn)
{
    const size_t row = blockIdx.x;
    const __half2* p = (const __half2*)(logits + row * C);
    const int tid = threadIdx.x;

    float2 a = __half22float2(p[tid * 2 + 0]);
    float2 b = __half22float2(p[tid * 2 + 1]);
    float m = fmaxf(fmaxf(a.x, a.y), fmaxf(b.x, b.y));
    __shared__ float sh[4];
    for (int o = 16; o > 0; o >>= 1) m = fmaxf(m, __shfl_xor_sync(0xffffffff, m, o));
    if ((tid & 31) == 0) sh[tid >> 5] = m;
    __syncthreads();
    m = fmaxf(fmaxf(sh[0], sh[1]), fmaxf(sh[2], sh[3]));

    a.x = expf(a.x - m); a.y = expf(a.y - m);
    b.x = expf(b.x - m); b.y = expf(b.y - m);
    float s = a.x + a.y + b.x + b.y;
    for (int o = 16; o > 0; o >>= 1) s += __shfl_xor_sync(0xffffffff, s, o);
    __shared__ float shs[4];
    if ((tid & 31) == 0) shs[tid >> 5] = s;
    __syncthreads();
    s = shs[0] + shs[1] + shs[2] + shs[3];
    const float inv = 1.f / s;

    __half2* o2 = (__half2*)(attn + row * C);
    o2[tid * 2 + 0] = __floats2half2_rn(a.x * inv, a.y * inv);
    o2[tid * 2 + 1] = __floats2half2_rn(b.x * inv, b.y * inv);
}

// ---------------- fp16 tensor-core GEMM core --------------------------------
// BIAS_MODE: 0 none, 1 row bias (per-batch via sBias), 3 rank-1 logits epilogue
// ADD_IDENT: add identity. DO_MIRROR: also write transposed tile (G symmetry).
#define STAGE_BYTES 32768          // A 16KB + B 16KB
#define GEMM_SMEM  (3 * STAGE_BYTES)

__device__ __forceinline__ void load_A(const __half* __restrict__ gA, int lda,
                                       uint32_t st, int tid)
{
    #pragma unroll
    for (int j = 0; j < 8; j++) {
        const int slot = tid + 128 * j;
        const int row  = slot >> 3;
        const int c    = slot & 7;
        const uint32_t off = (uint32_t)row * 128u + (uint32_t)((c ^ (row & 7)) << 4);
        CP_ASYNC16(st + off, gA + (size_t)row * lda + c * 8);
    }
}
__device__ __forceinline__ void load_B_nt(const __half* __restrict__ gB, int ldb,
                                          uint32_t st, int tid)
{
    #pragma unroll
    for (int j = 0; j < 8; j++) {
        const int slot = tid + 128 * j;
        const int row  = slot >> 3;
        const int c    = slot & 7;
        const uint32_t off = (uint32_t)row * 128u + (uint32_t)((c ^ (row & 7)) << 4);
        CP_ASYNC16(st + off, gB + (size_t)row * ldb + c * 8);
    }
}
__device__ __forceinline__ void load_B_t(const __half* __restrict__ gB, int ldb,
                                         uint32_t st, int tid)
{
    #pragma unroll
    for (int j = 0; j < 8; j++) {
        const int slot = tid + 128 * j;
        const int row  = slot >> 4;           // 0..63 (k)
        const int c    = slot & 15;           // 16B chunk (n/8)
        const uint32_t off = (uint32_t)((row * 2 + (c >> 3)) * 128)
                           + (uint32_t)(((c & 7) ^ (row & 7)) << 4);
        CP_ASYNC16(st + off, gB + (size_t)row * ldb + c * 8);
    }
}

template<typename OutT, int BIAS_MODE, bool ADD_RES, bool B_TRANS,
         bool ADD_IDENT, bool DO_MIRROR>
__device__ __forceinline__ void gemm_core(
    int bx, int by, int bz, uint32_t sbase,
    const __half* __restrict__ A, long long sA, int lda,
    const __half* __restrict__ B, long long sB, int ldb,
    OutT* __restrict__ D, long long sD, int ldd,
    int K,
    const float* __restrict__ bias, long long sBias,
    const __half* __restrict__ res, long long sRes, int ldres,
    const float* __restrict__ uv,
    float alpha)
{
    A += (size_t)bz * sA;
    B += (size_t)bz * sB;
    D += (size_t)bz * sD;
    if (ADD_RES) res += (size_t)bz * sRes;
    if (BIAS_MODE == 1) bias += (size_t)bz * sBias;
    if (BIAS_MODE == 3) uv += (size_t)bz * 1024;

    const int bm = by * 128;
    const int bn = bx * 128;
    const int tid = threadIdx.x;
    const int lane = tid & 31;
    const int wid = tid >> 5;
    const int wm = wid & 1;
    const int wn = wid >> 1;

    const __half* gA = A + (size_t)bm * lda;
    const __half* gB = B_TRANS ? (B + bn) : (B + (size_t)bn * ldb);
    const int T = K >> 6;

    const int a_row_lo = lane & 15;
    const int a_sel    = lane >> 4;
    const int b_row_lo = (lane & 7) + ((lane >> 4) << 3);
    const int b_sel    = (lane >> 3) & 1;
    const int bt_k_lo  = lane & 15;
    const int bt_n8    = (lane >> 4) << 3;

    float acc[4][8][4];
    #pragma unroll
    for (int i = 0; i < 4; i++)
        #pragma unroll
        for (int j = 0; j < 8; j++)
            #pragma unroll
            for (int q = 0; q < 4; q++) acc[i][j][q] = 0.f;

    #pragma unroll
    for (int s = 0; s < 2; s++) {
        const uint32_t st = sbase + s * STAGE_BYTES;
        load_A(gA + s * 64, lda, st, tid);
        if (B_TRANS) load_B_t(gB + (size_t)(s * 64) * ldb, ldb, st + 16384, tid);
        else         load_B_nt(gB + s * 64, ldb, st + 16384, tid);
        CP_COMMIT();
    }

    for (int t = 0; t < T; t++) {
        if (t < T - 1) CP_WAIT1(); else CP_WAIT0();
        __syncthreads();

        if (t + 2 < T) {
            const int s = t + 2;
            const uint32_t st = sbase + (s % 3) * STAGE_BYTES;
            load_A(gA + s * 64, lda, st, tid);
            if (B_TRANS) load_B_t(gB + (size_t)(s * 64) * ldb, ldb, st + 16384, tid);
            else         load_B_nt(gB + s * 64, ldb, st + 16384, tid);
            CP_COMMIT();
        }

        const uint32_t stA = sbase + (t % 3) * STAGE_BYTES;
        const uint32_t stB = stA + 16384;

        #pragma unroll
        for (int ks = 0; ks < 4; ks++) {
            uint32_t aF[4][4];
            uint32_t bF[4][4];
            #pragma unroll
            for (int mi = 0; mi < 4; mi++) {
                const int row = wm * 64 + mi * 16 + a_row_lo;
                const int ch  = ks * 2 + a_sel;
                ldsm_x4(aF[mi], stA + (uint32_t)row * 128u + (uint32_t)((ch ^ (row & 7)) << 4));
            }
            if (B_TRANS) {
                const int krow = ks * 16 + bt_k_lo;
                #pragma unroll
                for (int nb = 0; nb < 4; nb++) {
                    const int n = wn * 64 + nb * 16 + bt_n8;
                    const uint32_t addr = stB
                        + (uint32_t)((krow * 2 + (n >> 6)) * 128)
                        + (uint32_t)((((n >> 3) & 7) ^ (krow & 7)) << 4);
                    ldsm_x4_t(bF[nb], addr);
                }
            } else {
                #pragma unroll
                for (int nb = 0; nb < 4; nb++) {
                    const int row = wn * 64 + nb * 16 + b_row_lo;
                    const int ch  = ks * 2 + b_sel;
                    ldsm_x4(bF[nb], stB + (uint32_t)row * 128u + (uint32_t)((ch ^ (row & 7)) << 4));
                }
            }
            #pragma unroll
            for (int mi = 0; mi < 4; mi++)
                #pragma unroll
                for (int nj = 0; nj < 8; nj++)
                    mma16816(acc[mi][nj], aF[mi],
                             bF[nj >> 1][(nj & 1) * 2], bF[nj >> 1][(nj & 1) * 2 + 1]);
        }
    }

    const bool do_mirror = DO_MIRROR && (bx != by);
    const int m0 = bm + wm * 64;
    const int n0 = bn + wn * 64;
    #pragma unroll
    for (int mi = 0; mi < 4; mi++) {
        const int r0 = m0 + mi * 16 + (lane >> 2);
        const int r1 = r0 + 8;
        float br0 = 0.f, br1 = 0.f;
        if (BIAS_MODE == 1) { br0 = bias[r0]; br1 = bias[r1]; }
        float bq0 = 0.f, bq1 = 0.f, vv0 = 0.f, vv1 = 0.f;
        if (BIAS_MODE == 3) {
            bq0 = bias[r0]; bq1 = bias[r1];
            vv0 = uv[r0];   vv1 = uv[r1];
        }
        #pragma unroll
        for (int nj = 0; nj < 8; nj++) {
            const int c0 = n0 + nj * 8 + (lane & 3) * 2;
            float v0 = acc[mi][nj][0];
            float v1 = acc[mi][nj][1];
            float v2 = acc[mi][nj][2];
            float v3 = acc[mi][nj][3];
            if (BIAS_MODE == 3) {
                const float bkc0 = bias[512 + c0], bkc1 = bias[512 + c0 + 1];
                const float uc0  = uv[512 + c0],   uc1  = uv[512 + c0 + 1];
                v0 += vv0 * bkc0 + bq0 * uc0;
                v1 += vv0 * bkc1 + bq0 * uc1;
                v2 += vv1 * bkc0 + bq1 * uc0;
                v3 += vv1 * bkc1 + bq1 * uc1;
            }
            v0 *= alpha; v1 *= alpha; v2 *= alpha; v3 *= alpha;
            if (ADD_IDENT) {
                if (r0 == c0)     v0 += 1.f;
                if (r0 == c0 + 1) v1 += 1.f;
                if (r1 == c0)     v2 += 1.f;
                if (r1 == c0 + 1) v3 += 1.f;
            }
            if (BIAS_MODE == 1) { v0 += br0; v1 += br0; v2 += br1; v3 += br1; }
            if (ADD_RES) {
                const float2 q0 = __half22float2(*(const __half2*)&res[(size_t)r0 * ldres + c0]);
                const float2 q1 = __half22float2(*(const __half2*)&res[(size_t)r1 * ldres + c0]);
                v0 += q0.x; v1 += q0.y; v2 += q1.x; v3 += q1.y;
            }
            if constexpr (sizeof(OutT) == 2) {
                const __half2 h01 = __floats2half2_rn(v0, v1);
                const __half2 h23 = __floats2half2_rn(v2, v3);
                *reinterpret_cast<__half2*>(&D[(size_t)r0 * ldd + c0]) = h01;
                *reinterpret_cast<__half2*>(&D[(size_t)r1 * ldd + c0]) = h23;
                if (DO_MIRROR && do_mirror) {
                    D[(size_t)(c0    ) * ldd + r0] = __low2half(h01);
                    D[(size_t)(c0 + 1) * ldd + r0] = __high2half(h01);
                    D[(size_t)(c0    ) * ldd + r1] = __low2half(h23);
                    D[(size_t)(c0 + 1) * ldd + r1] = __high2half(h23);
                }
            } else {
                *reinterpret_cast<float2*>(&D[(size_t)r0 * ldd + c0]) = make_float2(v0, v1);
                *reinterpret_cast<float2*>(&D[(size_t)r1 * ldd + c0]) = make_float2(v2, v3);
            }
        }
    }
}

// ---------------- plain GEMM wrapper ----------------------------------------
template<typename OutT, int BIAS_MODE, bool ADD_RES, bool B_TRANS, bool ADD_IDENT>
__global__ __launch_bounds__(128, 2) void hgemm_kernel(
    const __half* __restrict__ A, long long sA, int lda,
    const __half* __restrict__ B, long long sB, int ldb,
    OutT* __restrict__ D, long long sD, int ldd,
    int K,
    const float* __restrict__ bias, long long sBias,
    const __half* __restrict__ res, long long sRes, int ldres,
    const float* __restrict__ uv,
    float alpha)
{
    extern __shared__ __align__(128) char smem[];
    gemm_core<OutT, BIAS_MODE, ADD_RES, B_TRANS, ADD_IDENT, false>(
        blockIdx.x, blockIdx.y, blockIdx.z, smem_u32(smem),
        A, sA, lda, B, sB, ldb, D, sD, ldd, K, bias, sBias,
        res, sRes, ldres, uv, alpha);
}

// ---------------- fused symmetric-Gram + u/v matvec launch -------------------
// ids [0,320): upper-tri G tiles (10 per batch, mirrored). ids [320,576): matvec
__constant__ int TBX[10] = {0, 1, 2, 3, 1, 2, 3, 2, 3, 3};
__constant__ int TBY[10] = {0, 0, 0, 0, 1, 1, 1, 2, 2, 3};

__global__ __launch_bounds__(128, 2) void fused_g_uv_kernel(
    const __half* __restrict__ xnh, __half* __restrict__ gram,
    const float* __restrict__ qkvw, const float* __restrict__ qkvb,
    const float* __restrict__ srow, float* __restrict__ uv)
{
    extern __shared__ __align__(128) char smem[];
    const uint32_t sbase = smem_u32(smem);
    const long long sXN  = (long long)C * L;
    const long long sATT = (long long)C * C;
    const int tid = threadIdx.x;

    int id = blockIdx.x;
    if (id < 320) {
        const int b = id / 10;
        const int t = id - b * 10;
        gemm_core<__half, 0, false, false, false, true>(
            TBX[t], TBY[t], b, sbase,
            xnh, sXN, L, xnh, sXN, L,
            gram, sATT, C, L, nullptr, 0LL, nullptr, 0LL, 0, nullptr, 1.0f);
    } else {
        id -= 320;
        const int b = id >> 3;
        const int r = (id & 7) * 128 + tid;
        float* ss = (float*)smem;
        for (int i = tid; i < C; i += 128) ss[i] = srow[b * C + i];
        __syncthreads();
        const float4* w4 = (const float4*)(qkvw + (size_t)r * C);
        float d = 0.f;
        #pragma unroll 4
        for (int i = 0; i < C / 4; i++) {
            const float4 wv4 = w4[i];
            d += wv4.x * ss[i*4] + wv4.y * ss[i*4+1]
               + wv4.z * ss[i*4+2] + wv4.w * ss[i*4+3];
        }
        if (r >= 512) d += (float)L * qkvb[r];
        uv[b * 1024 + r] = d;
    }
}

// ---------------- fused MWv GEMM (+I) + e matvec launch ----------------------
__global__ __launch_bounds__(128, 2) void fused_mwv_kernel(
    const __half* __restrict__ pm, const __half* __restrict__ wv,
    __half* __restrict__ mwv,
    const float* __restrict__ bv, const float* __restrict__ projb,
    float* __restrict__ e)
{
    extern __shared__ __align__(128) char smem[];
    const uint32_t sbase = smem_u32(smem);
    const long long sATT = (long long)C * C;
    const int tid = threadIdx.x;

    int id = blockIdx.x;
    if (id < 512) {
        gemm_core<__half, 0, false, true, true, false>(
            id & 3, (id >> 2) & 3, id >> 4, sbase,
            pm, sATT, C, wv, 0LL, C,
            mwv, sATT, C, C, nullptr, 0LL, nullptr, 0LL, 0, nullptr, 1.0f);
    } else {
        id -= 512;
        const int b = id >> 2;
        const int o = (id & 3) * 128 + tid;
        float* sbv = (float*)smem;
        for (int i = tid; i < C; i += 128) sbv[i] = bv[i];
        __syncthreads();
        const __half2* m2 = (const __half2*)(pm + (size_t)b * C * C + (size_t)o * C);
        float d = 0.f;
        #pragma unroll 4
        for (int i = 0; i < C / 2; i++) {
            const float2 mv = __half22float2(m2[i]);
            d += mv.x * sbv[i*2] + mv.y * sbv[i*2+1];
        }
        e[b * C + o] = d + projb[o];
    }
}

// ---------------------------------------------------------------------------
extern "C" void kernel_launch(void* const* d_in, const int* in_sizes, int n_in,
                              void* d_out, int out_size)
{
    const float* x      = (const float*)d_in[0];
    const float* gn_w   = (const float*)d_in[1];
    const float* gn_b   = (const float*)d_in[2];
    const float* qkv_w  = (const float*)d_in[3];
    const float* qkv_b  = (const float*)d_in[4];
    const float* proj_w = (const float*)d_in[5];
    const float* proj_b = (const float*)d_in[6];
    float* out = (float*)d_out;

    __half *xnh, *gram, *t1, *logits, *attn, *pm, *mwv, *wh;
    float *srow, *uv, *e;
    cudaGetSymbolAddress((void**)&xnh,    g_xnh);
    cudaGetSymbolAddress((void**)&gram,   g_gram);
    cudaGetSymbolAddress((void**)&t1,     g_t1);
    cudaGetSymbolAddress((void**)&logits, g_logits);
    cudaGetSymbolAddress((void**)&attn,   g_attn);
    cudaGetSymbolAddress((void**)&pm,     g_pm);
    cudaGetSymbolAddress((void**)&mwv,    g_mwv);
    cudaGetSymbolAddress((void**)&wh,     g_wh);
    cudaGetSymbolAddress((void**)&srow,   g_s);
    cudaGetSymbolAddress((void**)&uv,     g_uv);
    cudaGetSymbolAddress((void**)&e,      g_e);

    cudaFuncSetAttribute(hgemm_kernel<__half, 0, false, false, false>, cudaFuncAttributeMaxDynamicSharedMemorySize, GEMM_SMEM);
    cudaFuncSetAttribute(hgemm_kernel<__half, 3, false, false, false>, cudaFuncAttributeMaxDynamicSharedMemorySize, GEMM_SMEM);
    cudaFuncSetAttribute(hgemm_kernel<__half, 0, false, true, false>,  cudaFuncAttributeMaxDynamicSharedMemorySize, GEMM_SMEM);
    cudaFuncSetAttribute(hgemm_kernel<float,  1, false, true, false>,  cudaFuncAttributeMaxDynamicSharedMemorySize, GEMM_SMEM);
    cudaFuncSetAttribute(fused_g_uv_kernel, cudaFuncAttributeMaxDynamicSharedMemorySize, GEMM_SMEM);
    cudaFuncSetAttribute(fused_mwv_kernel,  cudaFuncAttributeMaxDynamicSharedMemorySize, GEMM_SMEM);

    const long long sXN  = (long long)C * L;
    const long long sATT = (long long)C * C;

    // 1) GroupNorm -> xnh fp16 (+ row sums s, + weight convert)
    gn_cvt_kernel<<<BATCH * GROUPS + 1024, 256>>>(
        x, gn_w, gn_b, xnh, qkv_w, proj_w, wh, srow);

    // 2) fused: G = xn·xn^T (symmetric, 10 tiles/batch + mirror) + u/v matvecs
    fused_g_uv_kernel<<<320 + 256, 128, GEMM_SMEM>>>(
        xnh, gram, qkv_w, qkv_b, srow, uv);

    // 3) T1 = Wq·G  (NT, M=N=K=512)
    {
        dim3 grid(C / 128, C / 128, BATCH);
        hgemm_kernel<__half, 0, false, false, false><<<grid, 128, GEMM_SMEM>>>(
            wh, 0LL, C, gram, sATT, C, t1, sATT, C, C,
            nullptr, 0LL, nullptr, 0LL, 0, nullptr, 1.0f);
    }
    // 4) logits = (T1·Wk^T + v⊗bk + bq⊗u) / 64  (NT, rank-1 epilogue)
    {
        dim3 grid(C / 128, C / 128, BATCH);
        hgemm_kernel<__half, 3, false, false, false><<<grid, 128, GEMM_SMEM>>>(
            t1, sATT, C, wh + (size_t)512 * C, 0LL, C, logits, sATT, C, C,
            qkv_b, 0LL, nullptr, 0LL, 0, uv, 0.015625f);
    }
    // 5) softmax -> attn fp16
    softmax512_kernel<<<BATCH * C, 128>>>(logits, attn);

    // 6) M[o,k] = Σ_q P[o,q]·attn[q,k]  (trans-B, M=N=K=512)
    {
        dim3 grid(C / 128, C / 128, BATCH);
        hgemm_kernel<__half, 0, false, true, false><<<grid, 128, GEMM_SMEM>>>(
            wh + (size_t)3 * C * C, 0LL, C, attn, sATT, C, pm, sATT, C, C,
            nullptr, 0LL, nullptr, 0LL, 0, nullptr, 1.0f);
    }
    // 7) fused: MWv = M·Wv + I (trans-B) + e = M·bv + proj_b
    fused_mwv_kernel<<<512 + 128, 128, GEMM_SMEM>>>(
        pm, wh + (size_t)1024 * C, mwv,
        qkv_b + 1024, proj_b, e);

    // 8) out[o,l] = (MWv+I)[o,:]·xn[:,l] + e[b][o]  (trans-B; residual folded)
    {
        dim3 grid(L / 128, C / 128, BATCH);
        hgemm_kernel<float, 1, false, true, false><<<grid, 128, GEMM_SMEM>>>(
            mwv, sATT, C, xnh, sXN, L, out, sXN, L, C,
            e, (long long)C, nullptr, 0LL, 0, nullptr, 1.0f);
    }
}

// round 15
// speedup vs baseline: 16.9991x; 1.0419x over previous
#include <cuda_runtime.h>
#include <cuda_fp16.h>
#include <cstdint>
#include <math.h>

#define BATCH 32
#define C 512
#define L 4096
#define GROUPS 32
#define CPG 16
#define EPS 1e-5f

// ---------------- scratch (device globals; allocation-free rule) -----------
__device__ __align__(256) __half g_xnh   [(size_t)BATCH * C * L];   // [C,L] normed
__device__ __align__(256) __half g_gram  [(size_t)BATCH * C * C];   // G = xn·xn^T
__device__ __align__(256) __half g_t1    [(size_t)BATCH * C * C];   // Wq·G
__device__ __align__(256) __half g_logits[(size_t)BATCH * C * C];
__device__ __align__(256) __half g_attn  [(size_t)BATCH * C * C];
__device__ __align__(256) __half g_pm    [(size_t)BATCH * C * C];   // M = P·attn
__device__ __align__(256) __half g_mwv   [(size_t)BATCH * C * C];   // M·Wv + I
__device__ __align__(256) __half g_wh    [(size_t)4 * C * C];       // qkv_w + proj_w (fp16)
__device__ __align__(256) float  g_s     [(size_t)BATCH * C];       // row sums of xn
__device__ __align__(256) float  g_uv    [(size_t)BATCH * 1024];    // [v=Wq·s | u=Wk·s+L·bk]
__device__ __align__(256) float  g_e     [(size_t)BATCH * C];       // e = M·bv + proj_b

// ---------------- PTX helpers ----------------------------------------------
__device__ __forceinline__ uint32_t smem_u32(const void* p) {
    uint32_t a;
    asm("{ .reg .u64 t; cvta.to.shared.u64 t, %1; cvt.u32.u64 %0, t; }" : "=r"(a) : "l"(p));
    return a;
}
#define CP_ASYNC16(dst, src) \
    asm volatile("cp.async.cg.shared.global [%0], [%1], 16;" :: "r"(dst), "l"(src) : "memory")
#define CP_COMMIT() asm volatile("cp.async.commit_group;" ::: "memory")
#define CP_WAIT1()  asm volatile("cp.async.wait_group 1;" ::: "memory")
#define CP_WAIT0()  asm volatile("cp.async.wait_group 0;" ::: "memory")

__device__ __forceinline__ void ldsm_x4(uint32_t (&r)[4], uint32_t addr) {
    asm volatile("ldmatrix.sync.aligned.m8n8.x4.shared.b16 {%0,%1,%2,%3}, [%4];"
        : "=r"(r[0]), "=r"(r[1]), "=r"(r[2]), "=r"(r[3]) : "r"(addr));
}
__device__ __forceinline__ void ldsm_x4_t(uint32_t (&r)[4], uint32_t addr) {
    asm volatile("ldmatrix.sync.aligned.m8n8.x4.trans.shared.b16 {%0,%1,%2,%3}, [%4];"
        : "=r"(r[0]), "=r"(r[1]), "=r"(r[2]), "=r"(r[3]) : "r"(addr));
}
__device__ __forceinline__ void mma16816(float (&d)[4], const uint32_t (&a)[4],
                                         uint32_t b0, uint32_t b1) {
    asm volatile(
        "mma.sync.aligned.m16n8k16.row.col.f32.f16.f16.f32 "
        "{%0,%1,%2,%3}, {%4,%5,%6,%7}, {%8,%9}, {%0,%1,%2,%3};"
        : "+f"(d[0]), "+f"(d[1]), "+f"(d[2]), "+f"(d[3])
        : "r"(a[0]), "r"(a[1]), "r"(a[2]), "r"(a[3]), "r"(b0), "r"(b1));
}

// ---------------- GroupNorm (+weight convert, +row sums) fused launch -------
__global__ __launch_bounds__(256) void gn_cvt_kernel(
    const float* __restrict__ x, const float* __restrict__ gw,
    const float* __restrict__ gb, __half* __restrict__ xnh,
    const float* __restrict__ qkvw, const float* __restrict__ projw,
    __half* __restrict__ wh, float* __restrict__ srow)
{
    const int bid = blockIdx.x;
    const int tid = threadIdx.x;

    if (bid >= BATCH * GROUPS) {
        const int i4 = (bid - BATCH * GROUPS) * 256 + tid;
        const int n_qkv4 = 3 * C * C / 4;
        float4 v;
        if (i4 < n_qkv4) v = ((const float4*)qkvw)[i4];
        else             v = ((const float4*)projw)[i4 - n_qkv4];
        __half2* o = (__half2*)(wh + (size_t)i4 * 4);
        o[0] = __floats2half2_rn(v.x, v.y);
        o[1] = __floats2half2_rn(v.z, v.w);
        return;
    }

    const int b = bid / GROUPS;
    const int g = bid % GROUPS;
    const size_t base = ((size_t)b * C + (size_t)g * CPG) * L;
    const float4* px4 = (const float4*)(x + base);
    __half2* outh = (__half2*)(xnh + base);
    const int n4 = CPG * L / 4;

    float s = 0.f, ss = 0.f;
    for (int i = tid; i < n4; i += 256) {
        float4 v = px4[i];
        s  += v.x + v.y + v.z + v.w;
        ss += v.x*v.x + v.y*v.y + v.z*v.z + v.w*v.w;
    }
    __shared__ float sh_s[32], sh_ss[32];
    for (int o = 16; o > 0; o >>= 1) {
        s  += __shfl_down_sync(0xffffffff, s, o);
        ss += __shfl_down_sync(0xffffffff, ss, o);
    }
    if ((tid & 31) == 0) { sh_s[tid >> 5] = s; sh_ss[tid >> 5] = ss; }
    __syncthreads();
    if (tid < 32) {
        s  = (tid < 8) ? sh_s[tid]  : 0.f;
        ss = (tid < 8) ? sh_ss[tid] : 0.f;
        for (int o = 4; o > 0; o >>= 1) {
            s  += __shfl_down_sync(0xffffffff, s, o);
            ss += __shfl_down_sync(0xffffffff, ss, o);
        }
        if (tid == 0) { sh_s[0] = s; sh_ss[0] = ss; }
    }
    __syncthreads();
    const float inv_n = 1.f / (float)(CPG * L);
    const float mean  = sh_s[0] * inv_n;
    const float var   = sh_ss[0] * inv_n - mean * mean;
    const float rstd  = rsqrtf(var + EPS);

    float csum[16];
    #pragma unroll
    for (int c = 0; c < 16; c++) csum[c] = 0.f;

    for (int j = 0; j < 64; j++) {
        const int i = tid + 256 * j;
        const int ch = j >> 2;
        const float w = gw[g * CPG + ch] * rstd;
        const float bb = gb[g * CPG + ch] - mean * w;
        float4 v = px4[i];
        const float e0 = fmaf(v.x, w, bb), e1 = fmaf(v.y, w, bb);
        const float e2 = fmaf(v.z, w, bb), e3 = fmaf(v.w, w, bb);
        outh[i * 2 + 0] = __floats2half2_rn(e0, e1);
        outh[i * 2 + 1] = __floats2half2_rn(e2, e3);
        csum[ch] += (e0 + e1) + (e2 + e3);
    }
    __shared__ float s_part[16][8];
    #pragma unroll
    for (int c = 0; c < 16; c++) {
        float t = csum[c];
        for (int o = 16; o > 0; o >>= 1) t += __shfl_down_sync(0xffffffff, t, o);
        if ((tid & 31) == 0) s_part[c][tid >> 5] = t;
    }
    __syncthreads();
    if (tid < 16) {
        float t = 0.f;
        #pragma unroll
        for (int w8 = 0; w8 < 8; w8++) t += s_part[tid][w8];
        srow[b * C + g * CPG + tid] = t;
    }
}

// ---------------- Row softmax (fp16 in, fp16 out) ---------------------------
__global__ __launch_bounds__(128) void softmax512_kernel(
    const __half* __restrict__ logits, __half* __restrict__ attn)
{
    const size_t row = blockIdx.x;
    const __half2* p = (const __half2*)(logits + row * C);
    const int tid = threadIdx.x;

    float2 a = __half22float2(p[tid * 2 + 0]);
    float2 b = __half22float2(p[tid * 2 + 1]);
    float m = fmaxf(fmaxf(a.x, a.y), fmaxf(b.x, b.y));
    __shared__ float sh[4];
    for (int o = 16; o > 0; o >>= 1) m = fmaxf(m, __shfl_xor_sync(0xffffffff, m, o));
    if ((tid & 31) == 0) sh[tid >> 5] = m;
    __syncthreads();
    m = fmaxf(fmaxf(sh[0], sh[1]), fmaxf(sh[2], sh[3]));

    a.x = expf(a.x - m); a.y = expf(a.y - m);
    b.x = expf(b.x - m); b.y = expf(b.y - m);
    float s = a.x + a.y + b.x + b.y;
    for (int o = 16; o > 0; o >>= 1) s += __shfl_xor_sync(0xffffffff, s, o);
    __shared__ float shs[4];
    if ((tid & 31) == 0) shs[tid >> 5] = s;
    __syncthreads();
    s = shs[0] + shs[1] + shs[2] + shs[3];
    const float inv = 1.f / s;

    __half2* o2 = (__half2*)(attn + row * C);
    o2[tid * 2 + 0] = __floats2half2_rn(a.x * inv, a.y * inv);
    o2[tid * 2 + 1] = __floats2half2_rn(b.x * inv, b.y * inv);
}

// ---------------- fp16 tensor-core GEMM core (128x128 tile) -----------------
// BIAS_MODE: 0 none, 1 row bias (per-batch via sBias), 3 rank-1 logits epilogue
// ADD_IDENT: add identity.
#define STAGE_BYTES 32768          // A 16KB + B 16KB
#define GEMM_SMEM  (3 * STAGE_BYTES)

__device__ __forceinline__ void load_A(const __half* __restrict__ gA, int lda,
                                       uint32_t st, int tid)
{
    #pragma unroll
    for (int j = 0; j < 8; j++) {
        const int slot = tid + 128 * j;
        const int row  = slot >> 3;
        const int c    = slot & 7;
        const uint32_t off = (uint32_t)row * 128u + (uint32_t)((c ^ (row & 7)) << 4);
        CP_ASYNC16(st + off, gA + (size_t)row * lda + c * 8);
    }
}
__device__ __forceinline__ void load_B_nt(const __half* __restrict__ gB, int ldb,
                                          uint32_t st, int tid)
{
    #pragma unroll
    for (int j = 0; j < 8; j++) {
        const int slot = tid + 128 * j;
        const int row  = slot >> 3;
        const int c    = slot & 7;
        const uint32_t off = (uint32_t)row * 128u + (uint32_t)((c ^ (row & 7)) << 4);
        CP_ASYNC16(st + off, gB + (size_t)row * ldb + c * 8);
    }
}
__device__ __forceinline__ void load_B_t(const __half* __restrict__ gB, int ldb,
                                         uint32_t st, int tid)
{
    #pragma unroll
    for (int j = 0; j < 8; j++) {
        const int slot = tid + 128 * j;
        const int row  = slot >> 4;           // 0..63 (k)
        const int c    = slot & 15;           // 16B chunk (n/8)
        const uint32_t off = (uint32_t)((row * 2 + (c >> 3)) * 128)
                           + (uint32_t)(((c & 7) ^ (row & 7)) << 4);
        CP_ASYNC16(st + off, gB + (size_t)row * ldb + c * 8);
    }
}

template<typename OutT, int BIAS_MODE, bool ADD_RES, bool B_TRANS, bool ADD_IDENT>
__device__ __forceinline__ void gemm_core(
    int bx, int by, int bz, uint32_t sbase,
    const __half* __restrict__ A, long long sA, int lda,
    const __half* __restrict__ B, long long sB, int ldb,
    OutT* __restrict__ D, long long sD, int ldd,
    int K,
    const float* __restrict__ bias, long long sBias,
    const __half* __restrict__ res, long long sRes, int ldres,
    const float* __restrict__ uv,
    float alpha)
{
    A += (size_t)bz * sA;
    B += (size_t)bz * sB;
    D += (size_t)bz * sD;
    if (ADD_RES) res += (size_t)bz * sRes;
    if (BIAS_MODE == 1) bias += (size_t)bz * sBias;
    if (BIAS_MODE == 3) uv += (size_t)bz * 1024;

    const int bm = by * 128;
    const int bn = bx * 128;
    const int tid = threadIdx.x;
    const int lane = tid & 31;
    const int wid = tid >> 5;
    const int wm = wid & 1;
    const int wn = wid >> 1;

    const __half* gA = A + (size_t)bm * lda;
    const __half* gB = B_TRANS ? (B + bn) : (B + (size_t)bn * ldb);
    const int T = K >> 6;

    const int a_row_lo = lane & 15;
    const int a_sel    = lane >> 4;
    const int b_row_lo = (lane & 7) + ((lane >> 4) << 3);
    const int b_sel    = (lane >> 3) & 1;
    const int bt_k_lo  = lane & 15;
    const int bt_n8    = (lane >> 4) << 3;

    float acc[4][8][4];
    #pragma unroll
    for (int i = 0; i < 4; i++)
        #pragma unroll
        for (int j = 0; j < 8; j++)
            #pragma unroll
            for (int q = 0; q < 4; q++) acc[i][j][q] = 0.f;

    #pragma unroll
    for (int s = 0; s < 2; s++) {
        const uint32_t st = sbase + s * STAGE_BYTES;
        load_A(gA + s * 64, lda, st, tid);
        if (B_TRANS) load_B_t(gB + (size_t)(s * 64) * ldb, ldb, st + 16384, tid);
        else         load_B_nt(gB + s * 64, ldb, st + 16384, tid);
        CP_COMMIT();
    }

    for (int t = 0; t < T; t++) {
        if (t < T - 1) CP_WAIT1(); else CP_WAIT0();
        __syncthreads();

        if (t + 2 < T) {
            const int s = t + 2;
            const uint32_t st = sbase + (s % 3) * STAGE_BYTES;
            load_A(gA + s * 64, lda, st, tid);
            if (B_TRANS) load_B_t(gB + (size_t)(s * 64) * ldb, ldb, st + 16384, tid);
            else         load_B_nt(gB + s * 64, ldb, st + 16384, tid);
            CP_COMMIT();
        }

        const uint32_t stA = sbase + (t % 3) * STAGE_BYTES;
        const uint32_t stB = stA + 16384;

        #pragma unroll
        for (int ks = 0; ks < 4; ks++) {
            uint32_t aF[4][4];
            uint32_t bF[4][4];
            #pragma unroll
            for (int mi = 0; mi < 4; mi++) {
                const int row = wm * 64 + mi * 16 + a_row_lo;
                const int ch  = ks * 2 + a_sel;
                ldsm_x4(aF[mi], stA + (uint32_t)row * 128u + (uint32_t)((ch ^ (row & 7)) << 4));
            }
            if (B_TRANS) {
                const int krow = ks * 16 + bt_k_lo;
                #pragma unroll
                for (int nb = 0; nb < 4; nb++) {
                    const int n = wn * 64 + nb * 16 + bt_n8;
                    const uint32_t addr = stB
                        + (uint32_t)((krow * 2 + (n >> 6)) * 128)
                        + (uint32_t)((((n >> 3) & 7) ^ (krow & 7)) << 4);
                    ldsm_x4_t(bF[nb], addr);
                }
            } else {
                #pragma unroll
                for (int nb = 0; nb < 4; nb++) {
                    const int row = wn * 64 + nb * 16 + b_row_lo;
                    const int ch  = ks * 2 + b_sel;
                    ldsm_x4(bF[nb], stB + (uint32_t)row * 128u + (uint32_t)((ch ^ (row & 7)) << 4));
                }
            }
            #pragma unroll
            for (int mi = 0; mi < 4; mi++)
                #pragma unroll
                for (int nj = 0; nj < 8; nj++)
                    mma16816(acc[mi][nj], aF[mi],
                             bF[nj >> 1][(nj & 1) * 2], bF[nj >> 1][(nj & 1) * 2 + 1]);
        }
    }

    const int m0 = bm + wm * 64;
    const int n0 = bn + wn * 64;
    #pragma unroll
    for (int mi = 0; mi < 4; mi++) {
        const int r0 = m0 + mi * 16 + (lane >> 2);
        const int r1 = r0 + 8;
        float br0 = 0.f, br1 = 0.f;
        if (BIAS_MODE == 1) { br0 = bias[r0]; br1 = bias[r1]; }
        float bq0 = 0.f, bq1 = 0.f, vv0 = 0.f, vv1 = 0.f;
        if (BIAS_MODE == 3) {
            bq0 = bias[r0]; bq1 = bias[r1];
            vv0 = uv[r0];   vv1 = uv[r1];
        }
        #pragma unroll
        for (int nj = 0; nj < 8; nj++) {
            const int c0 = n0 + nj * 8 + (lane & 3) * 2;
            float v0 = acc[mi][nj][0];
            float v1 = acc[mi][nj][1];
            float v2 = acc[mi][nj][2];
            float v3 = acc[mi][nj][3];
            if (BIAS_MODE == 3) {
                const float bkc0 = bias[512 + c0], bkc1 = bias[512 + c0 + 1];
                const float uc0  = uv[512 + c0],   uc1  = uv[512 + c0 + 1];
                v0 += vv0 * bkc0 + bq0 * uc0;
                v1 += vv0 * bkc1 + bq0 * uc1;
                v2 += vv1 * bkc0 + bq1 * uc0;
                v3 += vv1 * bkc1 + bq1 * uc1;
            }
            v0 *= alpha; v1 *= alpha; v2 *= alpha; v3 *= alpha;
            if (ADD_IDENT) {
                if (r0 == c0)     v0 += 1.f;
                if (r0 == c0 + 1) v1 += 1.f;
                if (r1 == c0)     v2 += 1.f;
                if (r1 == c0 + 1) v3 += 1.f;
            }
            if (BIAS_MODE == 1) { v0 += br0; v1 += br0; v2 += br1; v3 += br1; }
            if (ADD_RES) {
                const float2 q0 = __half22float2(*(const __half2*)&res[(size_t)r0 * ldres + c0]);
                const float2 q1 = __half22float2(*(const __half2*)&res[(size_t)r1 * ldres + c0]);
                v0 += q0.x; v1 += q0.y; v2 += q1.x; v3 += q1.y;
            }
            if constexpr (sizeof(OutT) == 2) {
                *reinterpret_cast<__half2*>(&D[(size_t)r0 * ldd + c0]) = __floats2half2_rn(v0, v1);
                *reinterpret_cast<__half2*>(&D[(size_t)r1 * ldd + c0]) = __floats2half2_rn(v2, v3);
            } else {
                *reinterpret_cast<float2*>(&D[(size_t)r0 * ldd + c0]) = make_float2(v0, v1);
                *reinterpret_cast<float2*>(&D[(size_t)r1 * ldd + c0]) = make_float2(v2, v3);
            }
        }
    }
}

// ---------------- plain GEMM wrapper ----------------------------------------
template<typename OutT, int BIAS_MODE, bool ADD_RES, bool B_TRANS, bool ADD_IDENT>
__global__ __launch_bounds__(128, 2) void hgemm_kernel(
    const __half* __restrict__ A, long long sA, int lda,
    const __half* __restrict__ B, long long sB, int ldb,
    OutT* __restrict__ D, long long sD, int ldd,
    int K,
    const float* __restrict__ bias, long long sBias,
    const __half* __restrict__ res, long long sRes, int ldres,
    const float* __restrict__ uv,
    float alpha)
{
    extern __shared__ __align__(128) char smem[];
    gemm_core<OutT, BIAS_MODE, ADD_RES, B_TRANS, ADD_IDENT>(
        blockIdx.x, blockIdx.y, blockIdx.z, smem_u32(smem),
        A, sA, lda, B, sB, ldb, D, sD, ldd, K, bias, sBias,
        res, sRes, ldres, uv, alpha);
}

// ---------------- 64x64 symmetric-Gram kernel (NT, K=4096) -------------------
// 128 thr = 4 warps (2m x 2n), warp tile 32x32. 3-stage, stage = A8K+B8K=16KB.
#define G64_STAGE 16384
#define G64_SMEM  (3 * G64_STAGE)

__device__ __forceinline__ void load_64(const __half* __restrict__ g, int ld,
                                        uint32_t st, int tid)
{
    #pragma unroll
    for (int j = 0; j < 4; j++) {
        const int slot = tid + 128 * j;       // 0..511
        const int row  = slot >> 3;           // 0..63
        const int c    = slot & 7;
        const uint32_t off = (uint32_t)row * 128u + (uint32_t)((c ^ (row & 7)) << 4);
        CP_ASYNC16(st + off, g + (size_t)row * ld + c * 8);
    }
}

__device__ __forceinline__ void gram64_core(
    int ix, int iy, int bz, uint32_t sbase,
    const __half* __restrict__ X, __half* __restrict__ G)
{
    X += (size_t)bz * C * L;
    G += (size_t)bz * C * C;

    const int bm = iy * 64;
    const int bn = ix * 64;
    const int tid = threadIdx.x;
    const int lane = tid & 31;
    const int wid = tid >> 5;
    const int wm = wid & 1;
    const int wn = wid >> 1;

    const __half* gA = X + (size_t)bm * L;
    const __half* gB = X + (size_t)bn * L;
    const int T = L >> 6;          // 64

    const int a_row_lo = lane & 15;
    const int a_sel    = lane >> 4;
    const int b_row_lo = (lane & 7) + ((lane >> 4) << 3);
    const int b_sel    = (lane >> 3) & 1;

    float acc[2][4][4];
    #pragma unroll
    for (int i = 0; i < 2; i++)
        #pragma unroll
        for (int j = 0; j < 4; j++)
            #pragma unroll
            for (int q = 0; q < 4; q++) acc[i][j][q] = 0.f;

    #pragma unroll
    for (int s = 0; s < 2; s++) {
        const uint32_t st = sbase + s * G64_STAGE;
        load_64(gA + s * 64, L, st, tid);
        load_64(gB + s * 64, L, st + 8192, tid);
        CP_COMMIT();
    }

    for (int t = 0; t < T; t++) {
        if (t < T - 1) CP_WAIT1(); else CP_WAIT0();
        __syncthreads();

        if (t + 2 < T) {
            const int s = t + 2;
            const uint32_t st = sbase + (s % 3) * G64_STAGE;
            load_64(gA + s * 64, L, st, tid);
            load_64(gB + s * 64, L, st + 8192, tid);
            CP_COMMIT();
        }

        const uint32_t stA = sbase + (t % 3) * G64_STAGE;
        const uint32_t stB = stA + 8192;

        #pragma unroll
        for (int ks = 0; ks < 4; ks++) {
            uint32_t aF[2][4];
            uint32_t bF[2][4];
            #pragma unroll
            for (int mi = 0; mi < 2; mi++) {
                const int row = wm * 32 + mi * 16 + a_row_lo;
                const int ch  = ks * 2 + a_sel;
                ldsm_x4(aF[mi], stA + (uint32_t)row * 128u + (uint32_t)((ch ^ (row & 7)) << 4));
            }
            #pragma unroll
            for (int nb = 0; nb < 2; nb++) {
                const int row = wn * 32 + nb * 16 + b_row_lo;
                const int ch  = ks * 2 + b_sel;
                ldsm_x4(bF[nb], stB + (uint32_t)row * 128u + (uint32_t)((ch ^ (row & 7)) << 4));
            }
            #pragma unroll
            for (int mi = 0; mi < 2; mi++)
                #pragma unroll
                for (int nj = 0; nj < 4; nj++)
                    mma16816(acc[mi][nj], aF[mi],
                             bF[nj >> 1][(nj & 1) * 2], bF[nj >> 1][(nj & 1) * 2 + 1]);
        }
    }

    const bool mirror = (ix != iy);
    const int m0 = bm + wm * 32;
    const int n0 = bn + wn * 32;
    #pragma unroll
    for (int mi = 0; mi < 2; mi++) {
        const int r0 = m0 + mi * 16 + (lane >> 2);
        const int r1 = r0 + 8;
        #pragma unroll
        for (int nj = 0; nj < 4; nj++) {
            const int c0 = n0 + nj * 8 + (lane & 3) * 2;
            const __half2 h01 = __floats2half2_rn(acc[mi][nj][0], acc[mi][nj][1]);
            const __half2 h23 = __floats2half2_rn(acc[mi][nj][2], acc[mi][nj][3]);
            *reinterpret_cast<__half2*>(&G[(size_t)r0 * C + c0]) = h01;
            *reinterpret_cast<__half2*>(&G[(size_t)r1 * C + c0]) = h23;
            if (mirror) {
                G[(size_t)(c0    ) * C + r0] = __low2half(h01);
                G[(size_t)(c0 + 1) * C + r0] = __high2half(h01);
                G[(size_t)(c0    ) * C + r1] = __low2half(h23);
                G[(size_t)(c0 + 1) * C + r1] = __high2half(h23);
            }
        }
    }
}

// upper-tri 64x64 tile tables: 36 tiles (iy <= ix), iy row-block, ix col-block
__constant__ int G64X[36] = {0,1,2,3,4,5,6,7, 1,2,3,4,5,6,7, 2,3,4,5,6,7,
                             3,4,5,6,7, 4,5,6,7, 5,6,7, 6,7, 7};
__constant__ int G64Y[36] = {0,0,0,0,0,0,0,0, 1,1,1,1,1,1,1, 2,2,2,2,2,2,
                             3,3,3,3,3, 4,4,4,4, 5,5,5, 6,6, 7};

// ids [0,1152): symmetric G tiles. ids [1152,1408): u/v matvec.
__global__ __launch_bounds__(128, 4) void fused_g_uv_kernel(
    const __half* __restrict__ xnh, __half* __restrict__ gram,
    const float* __restrict__ qkvw, const float* __restrict__ qkvb,
    const float* __restrict__ srow, float* __restrict__ uv)
{
    extern __shared__ __align__(128) char smem[];
    const int tid = threadIdx.x;

    int id = blockIdx.x;
    if (id < 1152) {
        const int b = id / 36;
        const int t = id - b * 36;
        gram64_core(G64X[t], G64Y[t], b, smem_u32(smem), xnh, gram);
    } else {
        id -= 1152;
        const int b = id >> 3;
        const int r = (id & 7) * 128 + tid;
        float* ss = (float*)smem;
        for (int i = tid; i < C; i += 128) ss[i] = srow[b * C + i];
        __syncthreads();
        const float4* w4 = (const float4*)(qkvw + (size_t)r * C);
        float d = 0.f;
        #pragma unroll 4
        for (int i = 0; i < C / 4; i++) {
            const float4 wv4 = w4[i];
            d += wv4.x * ss[i*4] + wv4.y * ss[i*4+1]
               + wv4.z * ss[i*4+2] + wv4.w * ss[i*4+3];
        }
        if (r >= 512) d += (float)L * qkvb[r];
        uv[b * 1024 + r] = d;
    }
}

// ---------------- fused MWv GEMM (+I) + e matvec launch ----------------------
__global__ __launch_bounds__(128, 2) void fused_mwv_kernel(
    const __half* __restrict__ pm, const __half* __restrict__ wv,
    __half* __restrict__ mwv,
    const float* __restrict__ bv, const float* __restrict__ projb,
    float* __restrict__ e)
{
    extern __shared__ __align__(128) char smem[];
    const uint32_t sbase = smem_u32(smem);
    const long long sATT = (long long)C * C;
    const int tid = threadIdx.x;

    int id = blockIdx.x;
    if (id < 512) {
        gemm_core<__half, 0, false, true, true>(
            id & 3, (id >> 2) & 3, id >> 4, sbase,
            pm, sATT, C, wv, 0LL, C,
            mwv, sATT, C, C, nullptr, 0LL, nullptr, 0LL, 0, nullptr, 1.0f);
    } else {
        id -= 512;
        const int b = id >> 2;
        const int o = (id & 3) * 128 + tid;
        float* sbv = (float*)smem;
        for (int i = tid; i < C; i += 128) sbv[i] = bv[i];
        __syncthreads();
        const __half2* m2 = (const __half2*)(pm + (size_t)b * C * C + (size_t)o * C);
        float d = 0.f;
        #pragma unroll 4
        for (int i = 0; i < C / 2; i++) {
            const float2 mv = __half22float2(m2[i]);
            d += mv.x * sbv[i*2] + mv.y * sbv[i*2+1];
        }
        e[b * C + o] = d + projb[o];
    }
}

// ---------------------------------------------------------------------------
extern "C" void kernel_launch(void* const* d_in, const int* in_sizes, int n_in,
                              void* d_out, int out_size)
{
    const float* x      = (const float*)d_in[0];
    const float* gn_w   = (const float*)d_in[1];
    const float* gn_b   = (const float*)d_in[2];
    const float* qkv_w  = (const float*)d_in[3];
    const float* qkv_b  = (const float*)d_in[4];
    const float* proj_w = (const float*)d_in[5];
    const float* proj_b = (const float*)d_in[6];
    float* out = (float*)d_out;

    __half *xnh, *gram, *t1, *logits, *attn, *pm, *mwv, *wh;
    float *srow, *uv, *e;
    cudaGetSymbolAddress((void**)&xnh,    g_xnh);
    cudaGetSymbolAddress((void**)&gram,   g_gram);
    cudaGetSymbolAddress((void**)&t1,     g_t1);
    cudaGetSymbolAddress((void**)&logits, g_logits);
    cudaGetSymbolAddress((void**)&attn,   g_attn);
    cudaGetSymbolAddress((void**)&pm,     g_pm);
    cudaGetSymbolAddress((void**)&mwv,    g_mwv);
    cudaGetSymbolAddress((void**)&wh,     g_wh);
    cudaGetSymbolAddress((void**)&srow,   g_s);
    cudaGetSymbolAddress((void**)&uv,     g_uv);
    cudaGetSymbolAddress((void**)&e,      g_e);

    cudaFuncSetAttribute(hgemm_kernel<__half, 0, false, false, false>, cudaFuncAttributeMaxDynamicSharedMemorySize, GEMM_SMEM);
    cudaFuncSetAttribute(hgemm_kernel<__half, 3, false, false, false>, cudaFuncAttributeMaxDynamicSharedMemorySize, GEMM_SMEM);
    cudaFuncSetAttribute(hgemm_kernel<__half, 0, false, true, false>,  cudaFuncAttributeMaxDynamicSharedMemorySize, GEMM_SMEM);
    cudaFuncSetAttribute(hgemm_kernel<float,  1, false, true, false>,  cudaFuncAttributeMaxDynamicSharedMemorySize, GEMM_SMEM);
    cudaFuncSetAttribute(fused_g_uv_kernel, cudaFuncAttributeMaxDynamicSharedMemorySize, G64_SMEM);
    cudaFuncSetAttribute(fused_mwv_kernel,  cudaFuncAttributeMaxDynamicSharedMemorySize, GEMM_SMEM);

    const long long sXN  = (long long)C * L;
    const long long sATT = (long long)C * C;

    // 1) GroupNorm -> xnh fp16 (+ row sums s, + weight convert)
    gn_cvt_kernel<<<BATCH * GROUPS + 1024, 256>>>(
        x, gn_w, gn_b, xnh, qkv_w, proj_w, wh, srow);

    // 2) fused: G = xn·xn^T (symmetric 64x64 tiles + mirror) + u/v matvecs
    fused_g_uv_kernel<<<1152 + 256, 128, G64_SMEM>>>(
        xnh, gram, qkv_w, qkv_b, srow, uv);

    // 3) T1 = Wq·G  (NT, M=N=K=512)
    {
        dim3 grid(C / 128, C / 128, BATCH);
        hgemm_kernel<__half, 0, false, false, false><<<grid, 128, GEMM_SMEM>>>(
            wh, 0LL, C, gram, sATT, C, t1, sATT, C, C,
            nullptr, 0LL, nullptr, 0LL, 0, nullptr, 1.0f);
    }
    // 4) logits = (T1·Wk^T + v⊗bk + bq⊗u) / 64  (NT, rank-1 epilogue)
    {
        dim3 grid(C / 128, C / 128, BATCH);
        hgemm_kernel<__half, 3, false, false, false><<<grid, 128, GEMM_SMEM>>>(
            t1, sATT, C, wh + (size_t)512 * C, 0LL, C, logits, sATT, C, C,
            qkv_b, 0LL, nullptr, 0LL, 0, uv, 0.015625f);
    }
    // 5) softmax -> attn fp16
    softmax512_kernel<<<BATCH * C, 128>>>(logits, attn);

    // 6) M[o,k] = Σ_q P[o,q]·attn[q,k]  (trans-B, M=N=K=512)
    {
        dim3 grid(C / 128, C / 128, BATCH);
        hgemm_kernel<__half, 0, false, true, false><<<grid, 128, GEMM_SMEM>>>(
            wh + (size_t)3 * C * C, 0LL, C, attn, sATT, C, pm, sATT, C, C,
            nullptr, 0LL, nullptr, 0LL, 0, nullptr, 1.0f);
    }
    // 7) fused: MWv = M·Wv + I (trans-B) + e = M·bv + proj_b
    fused_mwv_kernel<<<512 + 128, 128, GEMM_SMEM>>>(
        pm, wh + (size_t)1024 * C, mwv,
        qkv_b + 1024, proj_b, e);

    // 8) out[o,l] = (MWv+I)[o,:]·xn[:,l] + e[b][o]  (trans-B; residual folded)
    {
        dim3 grid(L / 128, C / 128, BATCH);
        hgemm_kernel<float, 1, false, true, false><<<grid, 128, GEMM_SMEM>>>(
            mwv, sATT, C, xnh, sXN, L, out, sXN, L, C,
            e, (long long)C, nullptr, 0LL, 0, nullptr, 1.0f);
    }
}